// round 6
// baseline (speedup 1.0000x reference)
#include <cuda_runtime.h>
#include <cuda_bf16.h>
#include <math.h>

// ---------------------------------------------------------------------------
// STTM: 4-layer transformer, w=192, C=128, NHEAD=4, hd=32
// feat layout: (w, n, C) row-major. Self: n in [0,256). fl: n<128, fr: n>=128.
// Rel-pos: project pos_enc (383 rows) once per layer.
// Attention: bf16 mma, skew-stored Z1/Z2, 512 threads / 16 warps per block.
// Projections: bf16 mma hgemm.
// ---------------------------------------------------------------------------

#define W_ 192
#define CC 128

// ------------------------- device scratch ---------------------------------
__device__ float g_ln [W_*256*CC];
__device__ float g_ln2[W_*128*CC];
__device__ float g_qkv[W_*256*3*CC];
__device__ float g_vo [W_*256*CC];
__device__ float g_proj[2*383*256];

// ------------------------- helpers -----------------------------------------
__device__ __forceinline__ unsigned pack_bf2(float x, float y) {
    __nv_bfloat162 h = __float22bfloat162_rn(make_float2(x, y));
    return *(unsigned*)&h;
}
__device__ __forceinline__ uint2 pack4(float4 v) {
    uint2 u; u.x = pack_bf2(v.x, v.y); u.y = pack_bf2(v.z, v.w); return u;
}
__device__ __forceinline__ uint2 pack4s(float4 v, float s) {
    uint2 u; u.x = pack_bf2(v.x * s, v.y * s); u.y = pack_bf2(v.z * s, v.w * s); return u;
}

__device__ __forceinline__ void ldm4(unsigned& r0, unsigned& r1, unsigned& r2, unsigned& r3,
                                     unsigned addr) {
    asm volatile("ldmatrix.sync.aligned.m8n8.x4.shared.b16 {%0,%1,%2,%3},[%4];"
                 : "=r"(r0), "=r"(r1), "=r"(r2), "=r"(r3) : "r"(addr));
}

__device__ __forceinline__ void mma_bf16(float* d, const unsigned* a, unsigned b0, unsigned b1) {
    asm volatile(
        "mma.sync.aligned.m16n8k16.row.col.f32.bf16.bf16.f32 "
        "{%0,%1,%2,%3},{%4,%5,%6,%7},{%8,%9},{%0,%1,%2,%3};"
        : "+f"(d[0]), "+f"(d[1]), "+f"(d[2]), "+f"(d[3])
        : "r"(a[0]), "r"(a[1]), "r"(a[2]), "r"(a[3]), "r"(b0), "r"(b1));
}

// ------------------------- build feat from inputs -------------------------
__global__ void build_feat(const float* __restrict__ L, const float* __restrict__ R,
                           float* __restrict__ feat)
{
    __shared__ float tile[32][33];
    int n = blockIdx.z;
    const float* src = (n < 128) ? L : R;
    int nn = n & 127;
    int h = nn >> 1, b = nn & 1;
    int i = blockIdx.x * 32 + threadIdx.x;
    int c = blockIdx.y * 32 + threadIdx.y;
    tile[threadIdx.y][threadIdx.x] = src[(((size_t)b * 128 + c) * 64 + h) * 192 + i];
    __syncthreads();
    int i2 = blockIdx.x * 32 + threadIdx.y;
    int c2 = blockIdx.y * 32 + threadIdx.x;
    feat[((size_t)i2 * 256 + n) * 128 + c2] = tile[threadIdx.x][threadIdx.y];
}

// ------------------------- LayerNorm: 1 warp per row, 4 rows/block ---------
__global__ void ln4_kernel(const float* __restrict__ x, int n0, int nW, int nF,
                           const float* __restrict__ g, const float* __restrict__ b,
                           float* __restrict__ y)
{
    int t = blockIdx.x * 4 + (threadIdx.x >> 5);
    int lane = threadIdx.x & 31;
    int row = (t / nW) * nF + n0 + (t % nW);
    float4 v = *(const float4*)(x + (size_t)row * 128 + lane * 4);
    float s  = v.x + v.y + v.z + v.w;
    float sq = v.x*v.x + v.y*v.y + v.z*v.z + v.w*v.w;
    #pragma unroll
    for (int o = 16; o > 0; o >>= 1) {
        s  += __shfl_xor_sync(0xffffffffu, s,  o);
        sq += __shfl_xor_sync(0xffffffffu, sq, o);
    }
    float mean = s * (1.f / 128.f);
    float var  = sq * (1.f / 128.f) - mean * mean;
    float inv = rsqrtf(var + 1e-5f);
    float4 gv = *(const float4*)(g + lane * 4);
    float4 bv = *(const float4*)(b + lane * 4);
    float4 o4;
    o4.x = (v.x - mean) * inv * gv.x + bv.x;
    o4.y = (v.y - mean) * inv * gv.y + bv.y;
    o4.z = (v.z - mean) * inv * gv.z + bv.z;
    o4.w = (v.w - mean) * inv * gv.w + bv.w;
    *(float4*)(y + (size_t)t * 128 + lane * 4) = o4;
}

// ------------------------- small SGEMM (64x64 tiles, bounds-checked) -------
__global__ void sgemm64(const float* __restrict__ A, int aN0, int aNW, int aNF,
                        const float* __restrict__ B, const float* __restrict__ bias,
                        float* __restrict__ C, int cN0, int cNW, int cNF, int cPitch,
                        int M, int N, int addRes)
{
    __shared__ float As[16][68];
    __shared__ float Bs[16][68];
    int tid = threadIdx.x;
    int tx = tid & 15, ty = tid >> 4;
    int rowBase = blockIdx.y * 64;
    int colBase = blockIdx.x * 64;

    float acc[4][4];
    #pragma unroll
    for (int i = 0; i < 4; i++)
        #pragma unroll
        for (int j = 0; j < 4; j++) acc[i][j] = 0.f;

    int lr = tid >> 2;
    int lc = (tid & 3) * 4;
    int ar = rowBase + lr;
    const float* aRowPtr = nullptr;
    if (ar < M) {
        int arow = (ar / aNW) * aNF + aN0 + (ar % aNW);
        aRowPtr = A + (size_t)arow * 128;
    }
    int bc = colBase + lr;
    const float* bRowPtr = (bc < N) ? (B + (size_t)bc * 128) : nullptr;

    for (int kt = 0; kt < 8; kt++) {
        int k0 = kt * 16 + lc;
        float4 av = aRowPtr ? *(const float4*)(aRowPtr + k0) : make_float4(0, 0, 0, 0);
        float4 bv = bRowPtr ? *(const float4*)(bRowPtr + k0) : make_float4(0, 0, 0, 0);
        As[lc + 0][lr] = av.x; As[lc + 1][lr] = av.y; As[lc + 2][lr] = av.z; As[lc + 3][lr] = av.w;
        Bs[lc + 0][lr] = bv.x; Bs[lc + 1][lr] = bv.y; Bs[lc + 2][lr] = bv.z; Bs[lc + 3][lr] = bv.w;
        __syncthreads();
        #pragma unroll
        for (int k = 0; k < 16; k++) {
            float a0 = As[k][ty * 4 + 0], a1 = As[k][ty * 4 + 1];
            float a2 = As[k][ty * 4 + 2], a3 = As[k][ty * 4 + 3];
            float b0 = Bs[k][tx * 4 + 0], b1 = Bs[k][tx * 4 + 1];
            float b2 = Bs[k][tx * 4 + 2], b3 = Bs[k][tx * 4 + 3];
            acc[0][0] = fmaf(a0, b0, acc[0][0]); acc[0][1] = fmaf(a0, b1, acc[0][1]);
            acc[0][2] = fmaf(a0, b2, acc[0][2]); acc[0][3] = fmaf(a0, b3, acc[0][3]);
            acc[1][0] = fmaf(a1, b0, acc[1][0]); acc[1][1] = fmaf(a1, b1, acc[1][1]);
            acc[1][2] = fmaf(a1, b2, acc[1][2]); acc[1][3] = fmaf(a1, b3, acc[1][3]);
            acc[2][0] = fmaf(a2, b0, acc[2][0]); acc[2][1] = fmaf(a2, b1, acc[2][1]);
            acc[2][2] = fmaf(a2, b2, acc[2][2]); acc[2][3] = fmaf(a2, b3, acc[2][3]);
            acc[3][0] = fmaf(a3, b0, acc[3][0]); acc[3][1] = fmaf(a3, b1, acc[3][1]);
            acc[3][2] = fmaf(a3, b2, acc[3][2]); acc[3][3] = fmaf(a3, b3, acc[3][3]);
        }
        __syncthreads();
    }

    #pragma unroll
    for (int mi = 0; mi < 4; mi++) {
        int r = rowBase + ty * 4 + mi;
        if (r >= M) continue;
        int crow = (r / cNW) * cNF + cN0 + (r % cNW);
        float* cRow = C + (size_t)crow * cPitch;
        #pragma unroll
        for (int ni = 0; ni < 4; ni++) {
            int col = colBase + tx * 4 + ni;
            if (col >= N) continue;
            float v = acc[mi][ni] + bias[col];
            if (addRes) cRow[col] += v; else cRow[col] = v;
        }
    }
}

// ------------------------- bf16 tensor-core GEMM ---------------------------
#define HSMEM (2 * 128 * 128 * 2)

__global__ void __launch_bounds__(256) hgemm(
    const float* __restrict__ A, int aN0, int aNW, int aNF,
    const float* __restrict__ B, const float* __restrict__ bias,
    float* __restrict__ C, int cN0, int cNW, int cNF, int cPitch,
    int addRes)
{
    extern __shared__ __nv_bfloat16 hsm[];
    __nv_bfloat16* As = hsm;
    __nv_bfloat16* Bs = hsm + 128*128;

    int tid = threadIdx.x;
    int rowBase = blockIdx.y * 128;
    int colBase = blockIdx.x * 128;

    int lr = tid >> 1, lkh = tid & 1;
    {
        int ar = rowBase + lr;
        int arow = (ar / aNW) * aNF + aN0 + (ar % aNW);
        const float* ap = A + (size_t)arow * 128 + lkh * 64;
        const float* bp = B + (size_t)(colBase + lr) * 128 + lkh * 64;
        int sw = lr & 7;
        #pragma unroll
        for (int j = 0; j < 8; j++) {
            int c = lkh * 8 + j;
            int cp = c ^ sw;
            float4 v0 = *(const float4*)(ap + j * 8);
            float4 v1 = *(const float4*)(ap + j * 8 + 4);
            uint4 u;
            u.x = pack_bf2(v0.x, v0.y); u.y = pack_bf2(v0.z, v0.w);
            u.z = pack_bf2(v1.x, v1.y); u.w = pack_bf2(v1.z, v1.w);
            *(uint4*)&As[lr * 128 + cp * 8] = u;
            v0 = *(const float4*)(bp + j * 8);
            v1 = *(const float4*)(bp + j * 8 + 4);
            u.x = pack_bf2(v0.x, v0.y); u.y = pack_bf2(v0.z, v0.w);
            u.z = pack_bf2(v1.x, v1.y); u.w = pack_bf2(v1.z, v1.w);
            *(uint4*)&Bs[lr * 128 + cp * 8] = u;
        }
    }
    __syncthreads();

    int wid = tid >> 5, lane = tid & 31;
    int wm = (wid & 3) * 32;
    int wn = (wid >> 2) * 64;
    int g = lane >> 2, tg = lane & 3;

    float acc[2][8][4];
    #pragma unroll
    for (int mt = 0; mt < 2; mt++)
        #pragma unroll
        for (int nt = 0; nt < 8; nt++)
            #pragma unroll
            for (int q = 0; q < 4; q++) acc[mt][nt][q] = 0.f;

    unsigned asBase = (unsigned)__cvta_generic_to_shared(As);
    unsigned bsBase = (unsigned)__cvta_generic_to_shared(Bs);

    #pragma unroll
    for (int ks = 0; ks < 8; ks++) {
        int c0 = ks * 2;
        unsigned afr[2][4];
        #pragma unroll
        for (int mt = 0; mt < 2; mt++) {
            int row = wm + mt * 16 + (lane & 15);
            int ch = c0 + (lane >> 4);
            unsigned addr = asBase + (unsigned)((row * 128 + ((ch ^ (row & 7)) << 3)) * 2);
            ldm4(afr[mt][0], afr[mt][1], afr[mt][2], afr[mt][3], addr);
        }
        unsigned bfr[8][2];
        #pragma unroll
        for (int p = 0; p < 4; p++) {
            int row = wn + p * 16 + (lane & 7) + ((lane >> 4) << 3);
            int ch = c0 + ((lane >> 3) & 1);
            unsigned addr = bsBase + (unsigned)((row * 128 + ((ch ^ (row & 7)) << 3)) * 2);
            unsigned r0, r1, r2, r3;
            ldm4(r0, r1, r2, r3, addr);
            bfr[p * 2][0] = r0;     bfr[p * 2][1] = r1;
            bfr[p * 2 + 1][0] = r2; bfr[p * 2 + 1][1] = r3;
        }
        #pragma unroll
        for (int mt = 0; mt < 2; mt++)
            #pragma unroll
            for (int nt = 0; nt < 8; nt++)
                mma_bf16(acc[mt][nt], afr[mt], bfr[nt][0], bfr[nt][1]);
    }

    #pragma unroll
    for (int mt = 0; mt < 2; mt++) {
        int r0g = rowBase + wm + mt * 16 + g;
        #pragma unroll
        for (int half = 0; half < 2; half++) {
            int r = r0g + half * 8;
            int crow = (r / cNW) * cNF + cN0 + (r % cNW);
            float* cRow = C + (size_t)crow * cPitch;
            #pragma unroll
            for (int nt = 0; nt < 8; nt++) {
                int col = colBase + wn + nt * 8 + 2 * tg;
                float2 b2 = *(const float2*)(bias + col);
                float vx = acc[mt][nt][half * 2 + 0] + b2.x;
                float vy = acc[mt][nt][half * 2 + 1] + b2.y;
                if (addRes) {
                    float2 old = *(const float2*)(cRow + col);
                    vx += old.x; vy += old.y;
                }
                float2 o2; o2.x = vx; o2.y = vy;
                *(float2*)(cRow + col) = o2;
            }
        }
    }
}

// ------------------------- bf16 mma attention (512 threads) -----------------
// Block = (n, e, half: rows i in [i0, i0+96)). 512 threads = 16 warps.
// S[il][j] = QK[il][j] + Z1s[il][j] + Z2s[j][il]
// smem: Qs@0 (96x40 bf16), Ks@7680 (192x40), PKs@23040 (288x40),
//   PQs@46080 (288x40; Vt 32x200 bf16 overlays), Z1s@69120 (96x196 f32 -> P),
//   Z2s@144384 (192x97 f32 -> Opart 96x32 f32), stats@218880 (4x96 f32).
#define ATC_SMEM (218880 + 1536)

template<int DSIGN>
__global__ void __launch_bounds__(512, 1) attn_tc(
    const float* __restrict__ qPtr, int qPitch, int qOff,
    const float* __restrict__ kPtr, int kPitch, int kOff,
    const float* __restrict__ vPtr, int vPitch, int vOff,
    const float* __restrict__ proj, float* __restrict__ vo, int nB)
{
    extern __shared__ char smraw[];
    __nv_bfloat16* Qs  = (__nv_bfloat16*)(smraw);
    __nv_bfloat16* Ks  = (__nv_bfloat16*)(smraw + 7680);
    __nv_bfloat16* PKs = (__nv_bfloat16*)(smraw + 23040);
    __nv_bfloat16* PQs = (__nv_bfloat16*)(smraw + 46080);
    __nv_bfloat16* Vt  = PQs;                       // overlay (after Z2 phase)
    float* Z1s  = (float*)(smraw + 69120);
    float* Z2s  = (float*)(smraw + 144384);
    float* Opart = Z2s;                             // overlay (after P written)
    float* hmax = (float*)(smraw + 218880);         // [2][96]
    float* hsum = hmax + 192;                       // [2][96]

    int n = blockIdx.x, e = blockIdx.y;
    int i0 = blockIdx.z * 96;
    int tid = threadIdx.x;
    const float scale = 0.17677669529663687f;
    const int dlo = (DSIGN > 0) ? (96 - i0) : i0;

    // ---- loads: Q (scaled), K, PK, PQ (scaled) ----
    for (int idx = tid; idx < 96 * 8; idx += 512) {
        int r = idx >> 3, c4 = (idx & 7) * 4;
        float4 v = *(const float4*)(qPtr + (size_t)((i0 + r) * nB + n) * qPitch + qOff + e * 32 + c4);
        *(uint2*)&Qs[r * 40 + c4] = pack4s(v, scale);
    }
    for (int idx = tid; idx < 192 * 8; idx += 512) {
        int r = idx >> 3, c4 = (idx & 7) * 4;
        float4 v = *(const float4*)(kPtr + (size_t)(r * nB + n) * kPitch + kOff + e * 32 + c4);
        *(uint2*)&Ks[r * 40 + c4] = pack4(v);
    }
    for (int idx = tid; idx < 288 * 8; idx += 512) {
        int t = idx >> 3, c4 = (idx & 7) * 4;
        int d = dlo + t;
        float4 vk = make_float4(0, 0, 0, 0), vq = make_float4(0, 0, 0, 0);
        if (d < 383) {
            vk = *(const float4*)(proj + (size_t)d * 256 + 128 + e * 32 + c4);
            vq = *(const float4*)(proj + (size_t)d * 256 + e * 32 + c4);
        }
        *(uint2*)&PKs[t * 40 + c4] = pack4(vk);
        *(uint2*)&PQs[t * 40 + c4] = pack4s(vq, scale);
    }
    __syncthreads();

    int wid = tid >> 5, lane = tid & 31;
    int g = lane >> 2, tg = lane & 3;
    unsigned qBase  = (unsigned)__cvta_generic_to_shared(Qs);
    unsigned kBase  = (unsigned)__cvta_generic_to_shared(Ks);
    unsigned pkBase = (unsigned)__cvta_generic_to_shared(PKs);
    unsigned pqBase = (unsigned)__cvta_generic_to_shared(PQs);
    unsigned vtBase = (unsigned)__cvta_generic_to_shared(Vt);
    unsigned pBase  = (unsigned)__cvta_generic_to_shared(Z1s);

    // ---- Z1 = Q @ PK^T, skew-scattered: 78 tiles over 16 warps ----
    #pragma unroll 1
    for (int u = wid; u < 78; u += 16) {
        int mt = u / 13, nt = u % 13;
        int t0m = (DSIGN > 0) ? (80 - 16 * mt) : (16 * mt);
        int tb = t0m + nt * 16;
        unsigned a[2][4], b[2][4];
        #pragma unroll
        for (int ks = 0; ks < 2; ks++) {
            unsigned addrA = qBase + (unsigned)((mt * 16 + (lane & 15)) * 80 + (ks * 2 + (lane >> 4)) * 16);
            ldm4(a[ks][0], a[ks][1], a[ks][2], a[ks][3], addrA);
            int row = tb + (lane & 7) + ((lane >> 4) << 3);
            unsigned addrB = pkBase + (unsigned)(row * 80 + (ks * 2 + ((lane >> 3) & 1)) * 16);
            ldm4(b[ks][0], b[ks][1], b[ks][2], b[ks][3], addrB);
        }
        float acc[2][4];
        #pragma unroll
        for (int h = 0; h < 2; h++) { acc[h][0] = acc[h][1] = acc[h][2] = acc[h][3] = 0.f; }
        mma_bf16(acc[0], a[0], b[0][0], b[0][1]); mma_bf16(acc[0], a[1], b[1][0], b[1][1]);
        mma_bf16(acc[1], a[0], b[0][2], b[0][3]); mma_bf16(acc[1], a[1], b[1][2], b[1][3]);
        #pragma unroll
        for (int h = 0; h < 2; h++) {
            int t = tb + h * 8 + 2 * tg;
            #pragma unroll
            for (int rr = 0; rr < 2; rr++) {
                int il = mt * 16 + g + 8 * rr;
                int j0 = (DSIGN > 0) ? (t + il - 95) : (191 + il - t);
                int j1 = (DSIGN > 0) ? (j0 + 1) : (j0 - 1);
                if ((unsigned)j0 < 192u) Z1s[il * 196 + j0] = acc[h][rr * 2 + 0];
                if ((unsigned)j1 < 192u) Z1s[il * 196 + j1] = acc[h][rr * 2 + 1];
            }
        }
    }

    // ---- Z2 = K @ PQ^T, skew-scattered: 84 tiles over 16 warps ----
    #pragma unroll 1
    for (int u = wid; u < 84; u += 16) {
        int jt = u / 7, nt = u % 7;
        int t0m = (DSIGN > 0) ? (16 * jt) : (176 - 16 * jt);
        int tb = t0m + nt * 16;
        unsigned a[2][4], b[2][4];
        #pragma unroll
        for (int ks = 0; ks < 2; ks++) {
            unsigned addrA = kBase + (unsigned)((jt * 16 + (lane & 15)) * 80 + (ks * 2 + (lane >> 4)) * 16);
            ldm4(a[ks][0], a[ks][1], a[ks][2], a[ks][3], addrA);
            int row = tb + (lane & 7) + ((lane >> 4) << 3);
            unsigned addrB = pqBase + (unsigned)(row * 80 + (ks * 2 + ((lane >> 3) & 1)) * 16);
            ldm4(b[ks][0], b[ks][1], b[ks][2], b[ks][3], addrB);
        }
        float acc[2][4];
        #pragma unroll
        for (int h = 0; h < 2; h++) { acc[h][0] = acc[h][1] = acc[h][2] = acc[h][3] = 0.f; }
        mma_bf16(acc[0], a[0], b[0][0], b[0][1]); mma_bf16(acc[0], a[1], b[1][0], b[1][1]);
        mma_bf16(acc[1], a[0], b[0][2], b[0][3]); mma_bf16(acc[1], a[1], b[1][2], b[1][3]);
        #pragma unroll
        for (int h = 0; h < 2; h++) {
            int t = tb + h * 8 + 2 * tg;
            #pragma unroll
            for (int rr = 0; rr < 2; rr++) {
                int j = jt * 16 + g + 8 * rr;
                int il0 = (DSIGN > 0) ? (j + 95 - t) : (j + t - 191);
                int il1 = (DSIGN > 0) ? (il0 - 1) : (il0 + 1);
                if ((unsigned)il0 < 96u) Z2s[j * 97 + il0] = acc[h][rr * 2 + 0];
                if ((unsigned)il1 < 96u) Z2s[j * 97 + il1] = acc[h][rr * 2 + 1];
            }
        }
    }
    __syncthreads();

    // ---- warps 0-11: QK^T (m-tile = wid>>1, col-half = wid&1) + gather.
    //      warps 12-15: load Vt.
    float acc[12][4];
    int mt = wid >> 1, chalf = wid & 1;
    int ilA = mt * 16 + g, ilB = ilA + 8;
    if (wid < 12) {
        #pragma unroll
        for (int nt = 0; nt < 12; nt++)
            #pragma unroll
            for (int q = 0; q < 4; q++) acc[nt][q] = 0.f;

        unsigned a[2][4];
        #pragma unroll
        for (int ks = 0; ks < 2; ks++) {
            unsigned addrA = qBase + (unsigned)((mt * 16 + (lane & 15)) * 80 + (ks * 2 + (lane >> 4)) * 16);
            ldm4(a[ks][0], a[ks][1], a[ks][2], a[ks][3], addrA);
        }
        #pragma unroll
        for (int nt16 = 0; nt16 < 6; nt16++) {
            unsigned b[2][4];
            #pragma unroll
            for (int ks = 0; ks < 2; ks++) {
                int row = chalf * 96 + nt16 * 16 + (lane & 7) + ((lane >> 4) << 3);
                unsigned addrB = kBase + (unsigned)(row * 80 + (ks * 2 + ((lane >> 3) & 1)) * 16);
                ldm4(b[ks][0], b[ks][1], b[ks][2], b[ks][3], addrB);
            }
            mma_bf16(acc[nt16 * 2],     a[0], b[0][0], b[0][1]);
            mma_bf16(acc[nt16 * 2],     a[1], b[1][0], b[1][1]);
            mma_bf16(acc[nt16 * 2 + 1], a[0], b[0][2], b[0][3]);
            mma_bf16(acc[nt16 * 2 + 1], a[1], b[1][2], b[1][3]);
        }

        #pragma unroll
        for (int nt = 0; nt < 12; nt++) {
            int j = chalf * 96 + nt * 8 + 2 * tg;
            acc[nt][0] += Z1s[ilA * 196 + j]     + Z2s[j * 97 + ilA];
            acc[nt][1] += Z1s[ilA * 196 + j + 1] + Z2s[(j + 1) * 97 + ilA];
            acc[nt][2] += Z1s[ilB * 196 + j]     + Z2s[j * 97 + ilB];
            acc[nt][3] += Z1s[ilB * 196 + j + 1] + Z2s[(j + 1) * 97 + ilB];
        }

        // partial row max (over this col-half)
        float mA = -1e30f, mB = -1e30f;
        #pragma unroll
        for (int nt = 0; nt < 12; nt++) {
            mA = fmaxf(mA, fmaxf(acc[nt][0], acc[nt][1]));
            mB = fmaxf(mB, fmaxf(acc[nt][2], acc[nt][3]));
        }
        mA = fmaxf(mA, __shfl_xor_sync(0xffffffffu, mA, 1));
        mA = fmaxf(mA, __shfl_xor_sync(0xffffffffu, mA, 2));
        mB = fmaxf(mB, __shfl_xor_sync(0xffffffffu, mB, 1));
        mB = fmaxf(mB, __shfl_xor_sync(0xffffffffu, mB, 2));
        if (tg == 0) {
            hmax[chalf * 96 + ilA] = mA;
            hmax[chalf * 96 + ilB] = mB;
        }
    } else {
        // load Vt[c][j] = V[j][c] into the (dead) PQs region
        for (int idx = tid - 384; idx < 192 * 8; idx += 128) {
            int j = idx >> 3, c4 = (idx & 7) * 4;
            float4 v = *(const float4*)(vPtr + (size_t)(j * nB + n) * vPitch + vOff + e * 32 + c4);
            Vt[(c4 + 0) * 200 + j] = __float2bfloat16(v.x);
            Vt[(c4 + 1) * 200 + j] = __float2bfloat16(v.y);
            Vt[(c4 + 2) * 200 + j] = __float2bfloat16(v.z);
            Vt[(c4 + 3) * 200 + j] = __float2bfloat16(v.w);
        }
    }
    __syncthreads();

    // ---- exp + partial sums ----
    if (wid < 12) {
        float mA = fmaxf(hmax[ilA], hmax[96 + ilA]);
        float mB = fmaxf(hmax[ilB], hmax[96 + ilB]);
        float sA = 0.f, sB = 0.f;
        #pragma unroll
        for (int nt = 0; nt < 12; nt++) {
            acc[nt][0] = __expf(acc[nt][0] - mA); sA += acc[nt][0];
            acc[nt][1] = __expf(acc[nt][1] - mA); sA += acc[nt][1];
            acc[nt][2] = __expf(acc[nt][2] - mB); sB += acc[nt][2];
            acc[nt][3] = __expf(acc[nt][3] - mB); sB += acc[nt][3];
        }
        sA += __shfl_xor_sync(0xffffffffu, sA, 1);
        sA += __shfl_xor_sync(0xffffffffu, sA, 2);
        sB += __shfl_xor_sync(0xffffffffu, sB, 1);
        sB += __shfl_xor_sync(0xffffffffu, sB, 2);
        if (tg == 0) {
            hsum[chalf * 96 + ilA] = sA;
            hsum[chalf * 96 + ilB] = sB;
        }
    }
    __syncthreads();

    // ---- normalize, write P (packed bf16 over Z1s) ----
    if (wid < 12) {
        float invA = 1.f / (hsum[ilA] + hsum[96 + ilA]);
        float invB = 1.f / (hsum[ilB] + hsum[96 + ilB]);
        unsigned* Pw = (unsigned*)Z1s;
        #pragma unroll
        for (int nt = 0; nt < 12; nt++) {
            int cw = chalf * 48 + nt * 4 + tg;
            Pw[ilA * 196 + cw] = pack_bf2(acc[nt][0] * invA, acc[nt][1] * invA);
            Pw[ilB * 196 + cw] = pack_bf2(acc[nt][2] * invB, acc[nt][3] * invB);
        }
    }
    __syncthreads();

    // ---- O = P @ V : 12 warps, k split in halves; combine via Opart ----
    float oacc[4][4];
    if (wid < 12) {
        #pragma unroll
        for (int t = 0; t < 4; t++)
            #pragma unroll
            for (int q = 0; q < 4; q++) oacc[t][q] = 0.f;

        #pragma unroll 1
        for (int s = 0; s < 6; s++) {
            int ks = chalf * 6 + s;
            unsigned a[4];
            unsigned addrA = pBase + (unsigned)((mt * 16 + (lane & 15)) * 784 + (ks * 2 + (lane >> 4)) * 16);
            ldm4(a[0], a[1], a[2], a[3], addrA);
            #pragma unroll
            for (int nb = 0; nb < 2; nb++) {
                int row = nb * 16 + (lane & 7) + ((lane >> 4) << 3);
                unsigned addrB = vtBase + (unsigned)(row * 400 + (ks * 2 + ((lane >> 3) & 1)) * 16);
                unsigned b0, b1, b2, b3;
                ldm4(b0, b1, b2, b3, addrB);
                mma_bf16(oacc[nb * 2],     a, b0, b1);
                mma_bf16(oacc[nb * 2 + 1], a, b2, b3);
            }
        }
        if (chalf == 1) {
            #pragma unroll
            for (int t = 0; t < 4; t++) {
                int c = t * 8 + 2 * tg;
                Opart[ilA * 32 + c]     = oacc[t][0];
                Opart[ilA * 32 + c + 1] = oacc[t][1];
                Opart[ilB * 32 + c]     = oacc[t][2];
                Opart[ilB * 32 + c + 1] = oacc[t][3];
            }
        }
    }
    __syncthreads();

    if (wid < 12 && chalf == 0) {
        int iA = i0 + ilA, iB = i0 + ilB;
        size_t oA = (size_t)(iA * nB + n) * 128 + e * 32;
        size_t oB = (size_t)(iB * nB + n) * 128 + e * 32;
        #pragma unroll
        for (int t = 0; t < 4; t++) {
            int c = t * 8 + 2 * tg;
            float2 vA, vB;
            vA.x = oacc[t][0] + Opart[ilA * 32 + c];
            vA.y = oacc[t][1] + Opart[ilA * 32 + c + 1];
            vB.x = oacc[t][2] + Opart[ilB * 32 + c];
            vB.y = oacc[t][3] + Opart[ilB * 32 + c + 1];
            *(float2*)(vo + oA + c) = vA;
            *(float2*)(vo + oB + c) = vB;
        }
    }
}

// ---------------------------------------------------------------------------
extern "C" void kernel_launch(void* const* d_in, const int* in_sizes, int n_in,
                              void* d_out, int out_size)
{
    (void)in_sizes; (void)n_in; (void)out_size;
    const float* feat_left  = (const float*)d_in[0];
    const float* feat_right = (const float*)d_in[1];
    const float* pos_enc    = (const float*)d_in[2];
    const float* s_iw = (const float*)d_in[3];
    const float* s_ib = (const float*)d_in[4];
    const float* s_ow = (const float*)d_in[5];
    const float* s_ob = (const float*)d_in[6];
    const float* s_g  = (const float*)d_in[7];
    const float* s_b  = (const float*)d_in[8];
    const float* c_iw = (const float*)d_in[9];
    const float* c_ib = (const float*)d_in[10];
    const float* c_ow = (const float*)d_in[11];
    const float* c_ob = (const float*)d_in[12];
    const float* c_g1 = (const float*)d_in[13];
    const float* c_b1 = (const float*)d_in[14];
    const float* c_g2 = (const float*)d_in[15];
    const float* c_b2 = (const float*)d_in[16];

    float* feat = (float*)d_out;

    float *ln_buf, *ln2_buf, *qkv, *vo, *projb;
    cudaGetSymbolAddress((void**)&ln_buf, g_ln);
    cudaGetSymbolAddress((void**)&ln2_buf, g_ln2);
    cudaGetSymbolAddress((void**)&qkv, g_qkv);
    cudaGetSymbolAddress((void**)&vo, g_vo);
    cudaGetSymbolAddress((void**)&projb, g_proj);
    float* projS = projb;
    float* projC = projb + 383 * 256;
    float* qb  = qkv;
    float* kvb = qkv + 192 * 128 * 128;

    cudaFuncSetAttribute(attn_tc<1>,  cudaFuncAttributeMaxDynamicSharedMemorySize, ATC_SMEM);
    cudaFuncSetAttribute(attn_tc<-1>, cudaFuncAttributeMaxDynamicSharedMemorySize, ATC_SMEM);
    cudaFuncSetAttribute(hgemm, cudaFuncAttributeMaxDynamicSharedMemorySize, HSMEM);

    build_feat<<<dim3(6, 4, 256), dim3(32, 32)>>>(feat_left, feat_right, feat);

    for (int L = 0; L < 4; L++) {
        const float* siw = s_iw + (size_t)L * 384 * 128;
        const float* sib = s_ib + (size_t)L * 384;
        const float* sow = s_ow + (size_t)L * 128 * 128;
        const float* sob = s_ob + (size_t)L * 128;
        const float* ciw = c_iw + (size_t)L * 384 * 128;
        const float* cib = c_ib + (size_t)L * 384;
        const float* cow = c_ow + (size_t)L * 128 * 128;
        const float* cob = c_ob + (size_t)L * 128;

        // ---------------- self-attention ----------------
        ln4_kernel<<<12288, 128>>>(feat, 0, 256, 256, s_g + L * 128, s_b + L * 128, ln_buf);
        sgemm64<<<dim3(4, 6), 256>>>(pos_enc, 0, 383, 383, siw, sib,
                                     projS, 0, 383, 383, 256, 383, 256, 0);
        hgemm<<<dim3(3, 384), 256, HSMEM>>>(ln_buf, 0, 256, 256, siw, sib,
                                            qkv, 0, 256, 256, 384, 0);
        attn_tc<1><<<dim3(256, 4, 2), 512, ATC_SMEM>>>(qkv, 384, 0, qkv, 384, 128,
                                                       qkv, 384, 256, projS, vo, 256);
        hgemm<<<dim3(1, 384), 256, HSMEM>>>(vo, 0, 256, 256, sow, sob,
                                            feat, 0, 256, 256, 128, 1);

        // ---------------- cross-attention ----------------
        ln4_kernel<<<12288, 128>>>(feat, 0, 256, 256, c_g1 + L * 128, c_b1 + L * 128, ln_buf);
        sgemm64<<<dim3(4, 6), 256>>>(pos_enc, 0, 383, 383, ciw, cib,
                                     projC, 0, 383, 383, 256, 383, 256, 0);

        // fr update: q from fr2, kv from fl2, flipped table (DSIGN=-1)
        hgemm<<<dim3(1, 192), 256, HSMEM>>>(ln_buf, 128, 128, 256, ciw, cib,
                                            qb, 0, 128, 128, 128, 0);
        hgemm<<<dim3(2, 192), 256, HSMEM>>>(ln_buf, 0, 128, 256, ciw + 128 * 128, cib + 128,
                                            kvb, 0, 128, 128, 256, 0);
        attn_tc<-1><<<dim3(128, 4, 2), 512, ATC_SMEM>>>(qb, 128, 0, kvb, 256, 0,
                                                        kvb, 256, 128, projC, vo, 128);
        hgemm<<<dim3(1, 192), 256, HSMEM>>>(vo, 0, 128, 128, cow, cob,
                                            feat, 128, 128, 256, 128, 1);

        // fr2n = LN(updated fr)
        ln4_kernel<<<6144, 128>>>(feat, 128, 128, 256, c_g2 + L * 128, c_b2 + L * 128, ln2_buf);

        // fl update: q from fl2, kv from fr2n, normal table (DSIGN=+1)
        hgemm<<<dim3(1, 192), 256, HSMEM>>>(ln_buf, 0, 128, 256, ciw, cib,
                                            qb, 0, 128, 128, 128, 0);
        hgemm<<<dim3(2, 192), 256, HSMEM>>>(ln2_buf, 0, 128, 128, ciw + 128 * 128, cib + 128,
                                            kvb, 0, 128, 128, 256, 0);
        attn_tc<1><<<dim3(128, 4, 2), 512, ATC_SMEM>>>(qb, 128, 0, kvb, 256, 0,
                                                       kvb, 256, 128, projC, vo, 128);
        hgemm<<<dim3(1, 192), 256, HSMEM>>>(vo, 0, 128, 128, cow, cob,
                                            feat, 0, 128, 256, 128, 1);
    }
}

// round 7
// speedup vs baseline: 1.0997x; 1.0997x over previous
#include <cuda_runtime.h>
#include <cuda_bf16.h>
#include <math.h>

// ---------------------------------------------------------------------------
// STTM: 4-layer transformer, w=192, C=128, NHEAD=4, hd=32
// feat layout: (w, n, C) row-major. Self: n in [0,256). fl: n<128, fr: n>=128.
// Rel-pos: project pos_enc (383 rows) once per layer.
// Attention: bf16 mma, Z1/Z2 scatter-merged into one fp32 S-prior buffer,
// 48-row blocks (96KB smem -> 2 blocks/SM). Projections: bf16 mma hgemm.
// ---------------------------------------------------------------------------

#define W_ 192
#define CC 128

// ------------------------- device scratch ---------------------------------
__device__ float g_ln [W_*256*CC];
__device__ float g_ln2[W_*128*CC];
__device__ float g_qkv[W_*256*3*CC];
__device__ float g_vo [W_*256*CC];
__device__ float g_proj[2*383*256];

// ------------------------- helpers -----------------------------------------
__device__ __forceinline__ unsigned pack_bf2(float x, float y) {
    __nv_bfloat162 h = __float22bfloat162_rn(make_float2(x, y));
    return *(unsigned*)&h;
}
__device__ __forceinline__ uint2 pack4(float4 v) {
    uint2 u; u.x = pack_bf2(v.x, v.y); u.y = pack_bf2(v.z, v.w); return u;
}
__device__ __forceinline__ uint2 pack4s(float4 v, float s) {
    uint2 u; u.x = pack_bf2(v.x * s, v.y * s); u.y = pack_bf2(v.z * s, v.w * s); return u;
}

__device__ __forceinline__ void ldm4(unsigned& r0, unsigned& r1, unsigned& r2, unsigned& r3,
                                     unsigned addr) {
    asm volatile("ldmatrix.sync.aligned.m8n8.x4.shared.b16 {%0,%1,%2,%3},[%4];"
                 : "=r"(r0), "=r"(r1), "=r"(r2), "=r"(r3) : "r"(addr));
}

__device__ __forceinline__ void mma_bf16(float* d, const unsigned* a, unsigned b0, unsigned b1) {
    asm volatile(
        "mma.sync.aligned.m16n8k16.row.col.f32.bf16.bf16.f32 "
        "{%0,%1,%2,%3},{%4,%5,%6,%7},{%8,%9},{%0,%1,%2,%3};"
        : "+f"(d[0]), "+f"(d[1]), "+f"(d[2]), "+f"(d[3])
        : "r"(a[0]), "r"(a[1]), "r"(a[2]), "r"(a[3]), "r"(b0), "r"(b1));
}

// ------------------------- build feat from inputs -------------------------
__global__ void build_feat(const float* __restrict__ L, const float* __restrict__ R,
                           float* __restrict__ feat)
{
    __shared__ float tile[32][33];
    int n = blockIdx.z;
    const float* src = (n < 128) ? L : R;
    int nn = n & 127;
    int h = nn >> 1, b = nn & 1;
    int i = blockIdx.x * 32 + threadIdx.x;
    int c = blockIdx.y * 32 + threadIdx.y;
    tile[threadIdx.y][threadIdx.x] = src[(((size_t)b * 128 + c) * 64 + h) * 192 + i];
    __syncthreads();
    int i2 = blockIdx.x * 32 + threadIdx.y;
    int c2 = blockIdx.y * 32 + threadIdx.x;
    feat[((size_t)i2 * 256 + n) * 128 + c2] = tile[threadIdx.x][threadIdx.y];
}

// ------------------------- LayerNorm: 1 warp per row, 4 rows/block ---------
__global__ void ln4_kernel(const float* __restrict__ x, int n0, int nW, int nF,
                           const float* __restrict__ g, const float* __restrict__ b,
                           float* __restrict__ y)
{
    int t = blockIdx.x * 4 + (threadIdx.x >> 5);
    int lane = threadIdx.x & 31;
    int row = (t / nW) * nF + n0 + (t % nW);
    float4 v = *(const float4*)(x + (size_t)row * 128 + lane * 4);
    float s  = v.x + v.y + v.z + v.w;
    float sq = v.x*v.x + v.y*v.y + v.z*v.z + v.w*v.w;
    #pragma unroll
    for (int o = 16; o > 0; o >>= 1) {
        s  += __shfl_xor_sync(0xffffffffu, s,  o);
        sq += __shfl_xor_sync(0xffffffffu, sq, o);
    }
    float mean = s * (1.f / 128.f);
    float var  = sq * (1.f / 128.f) - mean * mean;
    float inv = rsqrtf(var + 1e-5f);
    float4 gv = *(const float4*)(g + lane * 4);
    float4 bv = *(const float4*)(b + lane * 4);
    float4 o4;
    o4.x = (v.x - mean) * inv * gv.x + bv.x;
    o4.y = (v.y - mean) * inv * gv.y + bv.y;
    o4.z = (v.z - mean) * inv * gv.z + bv.z;
    o4.w = (v.w - mean) * inv * gv.w + bv.w;
    *(float4*)(y + (size_t)t * 128 + lane * 4) = o4;
}

// ------------------------- small SGEMM (64x64 tiles, bounds-checked) -------
__global__ void sgemm64(const float* __restrict__ A, int aN0, int aNW, int aNF,
                        const float* __restrict__ B, const float* __restrict__ bias,
                        float* __restrict__ C, int cN0, int cNW, int cNF, int cPitch,
                        int M, int N, int addRes)
{
    __shared__ float As[16][68];
    __shared__ float Bs[16][68];
    int tid = threadIdx.x;
    int tx = tid & 15, ty = tid >> 4;
    int rowBase = blockIdx.y * 64;
    int colBase = blockIdx.x * 64;

    float acc[4][4];
    #pragma unroll
    for (int i = 0; i < 4; i++)
        #pragma unroll
        for (int j = 0; j < 4; j++) acc[i][j] = 0.f;

    int lr = tid >> 2;
    int lc = (tid & 3) * 4;
    int ar = rowBase + lr;
    const float* aRowPtr = nullptr;
    if (ar < M) {
        int arow = (ar / aNW) * aNF + aN0 + (ar % aNW);
        aRowPtr = A + (size_t)arow * 128;
    }
    int bc = colBase + lr;
    const float* bRowPtr = (bc < N) ? (B + (size_t)bc * 128) : nullptr;

    for (int kt = 0; kt < 8; kt++) {
        int k0 = kt * 16 + lc;
        float4 av = aRowPtr ? *(const float4*)(aRowPtr + k0) : make_float4(0, 0, 0, 0);
        float4 bv = bRowPtr ? *(const float4*)(bRowPtr + k0) : make_float4(0, 0, 0, 0);
        As[lc + 0][lr] = av.x; As[lc + 1][lr] = av.y; As[lc + 2][lr] = av.z; As[lc + 3][lr] = av.w;
        Bs[lc + 0][lr] = bv.x; Bs[lc + 1][lr] = bv.y; Bs[lc + 2][lr] = bv.z; Bs[lc + 3][lr] = bv.w;
        __syncthreads();
        #pragma unroll
        for (int k = 0; k < 16; k++) {
            float a0 = As[k][ty * 4 + 0], a1 = As[k][ty * 4 + 1];
            float a2 = As[k][ty * 4 + 2], a3 = As[k][ty * 4 + 3];
            float b0 = Bs[k][tx * 4 + 0], b1 = Bs[k][tx * 4 + 1];
            float b2 = Bs[k][tx * 4 + 2], b3 = Bs[k][tx * 4 + 3];
            acc[0][0] = fmaf(a0, b0, acc[0][0]); acc[0][1] = fmaf(a0, b1, acc[0][1]);
            acc[0][2] = fmaf(a0, b2, acc[0][2]); acc[0][3] = fmaf(a0, b3, acc[0][3]);
            acc[1][0] = fmaf(a1, b0, acc[1][0]); acc[1][1] = fmaf(a1, b1, acc[1][1]);
            acc[1][2] = fmaf(a1, b2, acc[1][2]); acc[1][3] = fmaf(a1, b3, acc[1][3]);
            acc[2][0] = fmaf(a2, b0, acc[2][0]); acc[2][1] = fmaf(a2, b1, acc[2][1]);
            acc[2][2] = fmaf(a2, b2, acc[2][2]); acc[2][3] = fmaf(a2, b3, acc[2][3]);
            acc[3][0] = fmaf(a3, b0, acc[3][0]); acc[3][1] = fmaf(a3, b1, acc[3][1]);
            acc[3][2] = fmaf(a3, b2, acc[3][2]); acc[3][3] = fmaf(a3, b3, acc[3][3]);
        }
        __syncthreads();
    }

    #pragma unroll
    for (int mi = 0; mi < 4; mi++) {
        int r = rowBase + ty * 4 + mi;
        if (r >= M) continue;
        int crow = (r / cNW) * cNF + cN0 + (r % cNW);
        float* cRow = C + (size_t)crow * cPitch;
        #pragma unroll
        for (int ni = 0; ni < 4; ni++) {
            int col = colBase + tx * 4 + ni;
            if (col >= N) continue;
            float v = acc[mi][ni] + bias[col];
            if (addRes) cRow[col] += v; else cRow[col] = v;
        }
    }
}

// ------------------------- bf16 tensor-core GEMM ---------------------------
#define HSMEM (2 * 128 * 128 * 2)

__global__ void __launch_bounds__(256) hgemm(
    const float* __restrict__ A, int aN0, int aNW, int aNF,
    const float* __restrict__ B, const float* __restrict__ bias,
    float* __restrict__ C, int cN0, int cNW, int cNF, int cPitch,
    int addRes)
{
    extern __shared__ __nv_bfloat16 hsm[];
    __nv_bfloat16* As = hsm;
    __nv_bfloat16* Bs = hsm + 128*128;

    int tid = threadIdx.x;
    int rowBase = blockIdx.y * 128;
    int colBase = blockIdx.x * 128;

    int lr = tid >> 1, lkh = tid & 1;
    {
        int ar = rowBase + lr;
        int arow = (ar / aNW) * aNF + aN0 + (ar % aNW);
        const float* ap = A + (size_t)arow * 128 + lkh * 64;
        const float* bp = B + (size_t)(colBase + lr) * 128 + lkh * 64;
        int sw = lr & 7;
        #pragma unroll
        for (int j = 0; j < 8; j++) {
            int c = lkh * 8 + j;
            int cp = c ^ sw;
            float4 v0 = *(const float4*)(ap + j * 8);
            float4 v1 = *(const float4*)(ap + j * 8 + 4);
            uint4 u;
            u.x = pack_bf2(v0.x, v0.y); u.y = pack_bf2(v0.z, v0.w);
            u.z = pack_bf2(v1.x, v1.y); u.w = pack_bf2(v1.z, v1.w);
            *(uint4*)&As[lr * 128 + cp * 8] = u;
            v0 = *(const float4*)(bp + j * 8);
            v1 = *(const float4*)(bp + j * 8 + 4);
            u.x = pack_bf2(v0.x, v0.y); u.y = pack_bf2(v0.z, v0.w);
            u.z = pack_bf2(v1.x, v1.y); u.w = pack_bf2(v1.z, v1.w);
            *(uint4*)&Bs[lr * 128 + cp * 8] = u;
        }
    }
    __syncthreads();

    int wid = tid >> 5, lane = tid & 31;
    int wm = (wid & 3) * 32;
    int wn = (wid >> 2) * 64;
    int g = lane >> 2, tg = lane & 3;

    float acc[2][8][4];
    #pragma unroll
    for (int mt = 0; mt < 2; mt++)
        #pragma unroll
        for (int nt = 0; nt < 8; nt++)
            #pragma unroll
            for (int q = 0; q < 4; q++) acc[mt][nt][q] = 0.f;

    unsigned asBase = (unsigned)__cvta_generic_to_shared(As);
    unsigned bsBase = (unsigned)__cvta_generic_to_shared(Bs);

    #pragma unroll
    for (int ks = 0; ks < 8; ks++) {
        int c0 = ks * 2;
        unsigned afr[2][4];
        #pragma unroll
        for (int mt = 0; mt < 2; mt++) {
            int row = wm + mt * 16 + (lane & 15);
            int ch = c0 + (lane >> 4);
            unsigned addr = asBase + (unsigned)((row * 128 + ((ch ^ (row & 7)) << 3)) * 2);
            ldm4(afr[mt][0], afr[mt][1], afr[mt][2], afr[mt][3], addr);
        }
        unsigned bfr[8][2];
        #pragma unroll
        for (int p = 0; p < 4; p++) {
            int row = wn + p * 16 + (lane & 7) + ((lane >> 4) << 3);
            int ch = c0 + ((lane >> 3) & 1);
            unsigned addr = bsBase + (unsigned)((row * 128 + ((ch ^ (row & 7)) << 3)) * 2);
            unsigned r0, r1, r2, r3;
            ldm4(r0, r1, r2, r3, addr);
            bfr[p * 2][0] = r0;     bfr[p * 2][1] = r1;
            bfr[p * 2 + 1][0] = r2; bfr[p * 2 + 1][1] = r3;
        }
        #pragma unroll
        for (int mt = 0; mt < 2; mt++)
            #pragma unroll
            for (int nt = 0; nt < 8; nt++)
                mma_bf16(acc[mt][nt], afr[mt], bfr[nt][0], bfr[nt][1]);
    }

    #pragma unroll
    for (int mt = 0; mt < 2; mt++) {
        int r0g = rowBase + wm + mt * 16 + g;
        #pragma unroll
        for (int half = 0; half < 2; half++) {
            int r = r0g + half * 8;
            int crow = (r / cNW) * cNF + cN0 + (r % cNW);
            float* cRow = C + (size_t)crow * cPitch;
            #pragma unroll
            for (int nt = 0; nt < 8; nt++) {
                int col = colBase + wn + nt * 8 + 2 * tg;
                float2 b2 = *(const float2*)(bias + col);
                float vx = acc[mt][nt][half * 2 + 0] + b2.x;
                float vy = acc[mt][nt][half * 2 + 1] + b2.y;
                if (addRes) {
                    float2 old = *(const float2*)(cRow + col);
                    vx += old.x; vy += old.y;
                }
                float2 o2; o2.x = vx; o2.y = vy;
                *(float2*)(cRow + col) = o2;
            }
        }
    }
}

// ------------------------- bf16 mma attention (48-row blocks) ---------------
// Block = (n, e, q: rows i in [q*48, q*48+48)). 256 threads = 8 warps.
// S[il][j] = QK[il][j] + Ssm[il][j], with Ssm built by two skewed GEMM passes:
//   pass Z1 (init):  Ssm[il][t->j] = (Q@PK^T)[il][dlo+t]
//   pass Z2 (add):   Ssm[t->il][j] += (K@PQ^T)[j][dlo+t]
// DSIGN=+1: dlo=144-i0, j=t+il-47, il=47+j-t.
// DSIGN=-1: dlo=i0,     j=191+il-t, il=t+j-191.
// smem: Qs@0 (48x40 bf16), Ks@3840 (192x40; Opart 48x32 f32 overlays),
//   PKs@19200 (240x40), PQs@38400 (240x40; Vt 32x200 bf16 overlays),
//   Ssm@57600 (48x196 f32 -> packed-bf16 P), stats@95232 (4x48 f32). 96000 B.
#define ATC_SMEM 96000

template<int DSIGN>
__global__ void __launch_bounds__(256, 2) attn_tc(
    const float* __restrict__ qPtr, int qPitch, int qOff,
    const float* __restrict__ kPtr, int kPitch, int kOff,
    const float* __restrict__ vPtr, int vPitch, int vOff,
    const float* __restrict__ proj, float* __restrict__ vo, int nB)
{
    extern __shared__ char smraw[];
    __nv_bfloat16* Qs  = (__nv_bfloat16*)(smraw);
    __nv_bfloat16* Ks  = (__nv_bfloat16*)(smraw + 3840);
    __nv_bfloat16* PKs = (__nv_bfloat16*)(smraw + 19200);
    __nv_bfloat16* PQs = (__nv_bfloat16*)(smraw + 38400);
    __nv_bfloat16* Vt  = PQs;                       // overlay (after Z2 phase)
    float* Opart = (float*)(smraw + 3840);          // overlay Ks (after QK phase)
    float* Ssm  = (float*)(smraw + 57600);
    float* hmax = (float*)(smraw + 95232);          // [2][48]
    float* hsum = hmax + 96;                        // [2][48]

    int n = blockIdx.x, e = blockIdx.y;
    int i0 = blockIdx.z * 48;
    int tid = threadIdx.x;
    const float scale = 0.17677669529663687f;
    const int dlo = (DSIGN > 0) ? (144 - i0) : i0;

    // ---- loads: Q (scaled), K, PK, PQ (scaled) ----
    for (int idx = tid; idx < 48 * 8; idx += 256) {
        int r = idx >> 3, c4 = (idx & 7) * 4;
        float4 v = *(const float4*)(qPtr + (size_t)((i0 + r) * nB + n) * qPitch + qOff + e * 32 + c4);
        *(uint2*)&Qs[r * 40 + c4] = pack4s(v, scale);
    }
    for (int idx = tid; idx < 192 * 8; idx += 256) {
        int r = idx >> 3, c4 = (idx & 7) * 4;
        float4 v = *(const float4*)(kPtr + (size_t)(r * nB + n) * kPitch + kOff + e * 32 + c4);
        *(uint2*)&Ks[r * 40 + c4] = pack4(v);
    }
    for (int idx = tid; idx < 240 * 8; idx += 256) {
        int t = idx >> 3, c4 = (idx & 7) * 4;
        int d = dlo + t;
        float4 vk = make_float4(0, 0, 0, 0), vq = make_float4(0, 0, 0, 0);
        if (d < 383) {
            vk = *(const float4*)(proj + (size_t)d * 256 + 128 + e * 32 + c4);
            vq = *(const float4*)(proj + (size_t)d * 256 + e * 32 + c4);
        }
        *(uint2*)&PKs[t * 40 + c4] = pack4(vk);
        *(uint2*)&PQs[t * 40 + c4] = pack4s(vq, scale);
    }
    __syncthreads();

    int wid = tid >> 5, lane = tid & 31;
    int g = lane >> 2, tg = lane & 3;
    unsigned qBase  = (unsigned)__cvta_generic_to_shared(Qs);
    unsigned kBase  = (unsigned)__cvta_generic_to_shared(Ks);
    unsigned pkBase = (unsigned)__cvta_generic_to_shared(PKs);
    unsigned pqBase = (unsigned)__cvta_generic_to_shared(PQs);
    unsigned vtBase = (unsigned)__cvta_generic_to_shared(Vt);
    unsigned pBase  = (unsigned)__cvta_generic_to_shared(Ssm);

    // ---- Z1 = Q @ PK^T, skew-scattered (init): 3 m-tiles x 13 n16-tiles ----
    #pragma unroll 1
    for (int u = wid; u < 39; u += 8) {
        int mt = u / 13, nt = u % 13;
        int t0m = (DSIGN > 0) ? (32 - 16 * mt) : (16 * mt);
        int tb = t0m + nt * 16;
        unsigned a[2][4], b[2][4];
        #pragma unroll
        for (int ks = 0; ks < 2; ks++) {
            unsigned addrA = qBase + (unsigned)((mt * 16 + (lane & 15)) * 80 + (ks * 2 + (lane >> 4)) * 16);
            ldm4(a[ks][0], a[ks][1], a[ks][2], a[ks][3], addrA);
            int row = tb + (lane & 7) + ((lane >> 4) << 3);
            unsigned addrB = pkBase + (unsigned)(row * 80 + (ks * 2 + ((lane >> 3) & 1)) * 16);
            ldm4(b[ks][0], b[ks][1], b[ks][2], b[ks][3], addrB);
        }
        float acc[2][4];
        #pragma unroll
        for (int h = 0; h < 2; h++) { acc[h][0] = acc[h][1] = acc[h][2] = acc[h][3] = 0.f; }
        mma_bf16(acc[0], a[0], b[0][0], b[0][1]); mma_bf16(acc[0], a[1], b[1][0], b[1][1]);
        mma_bf16(acc[1], a[0], b[0][2], b[0][3]); mma_bf16(acc[1], a[1], b[1][2], b[1][3]);
        #pragma unroll
        for (int h = 0; h < 2; h++) {
            int t = tb + h * 8 + 2 * tg;
            #pragma unroll
            for (int rr = 0; rr < 2; rr++) {
                int il = mt * 16 + g + 8 * rr;
                int j0 = (DSIGN > 0) ? (t + il - 47) : (191 + il - t);
                int j1 = (DSIGN > 0) ? (j0 + 1) : (j0 - 1);
                if ((unsigned)j0 < 192u) Ssm[il * 196 + j0] = acc[h][rr * 2 + 0];
                if ((unsigned)j1 < 192u) Ssm[il * 196 + j1] = acc[h][rr * 2 + 1];
            }
        }
    }
    __syncthreads();

    // ---- Z2 = K @ PQ^T, skew scatter-ADD: 12 j-tiles x 4 n16-tiles ----
    #pragma unroll 1
    for (int u = wid; u < 48; u += 8) {
        int jt = u >> 2, nt = u & 3;
        int t0m = (DSIGN > 0) ? (16 * jt) : (176 - 16 * jt);
        int tb = t0m + nt * 16;
        unsigned a[2][4], b[2][4];
        #pragma unroll
        for (int ks = 0; ks < 2; ks++) {
            unsigned addrA = kBase + (unsigned)((jt * 16 + (lane & 15)) * 80 + (ks * 2 + (lane >> 4)) * 16);
            ldm4(a[ks][0], a[ks][1], a[ks][2], a[ks][3], addrA);
            int row = tb + (lane & 7) + ((lane >> 4) << 3);
            unsigned addrB = pqBase + (unsigned)(row * 80 + (ks * 2 + ((lane >> 3) & 1)) * 16);
            ldm4(b[ks][0], b[ks][1], b[ks][2], b[ks][3], addrB);
        }
        float acc[2][4];
        #pragma unroll
        for (int h = 0; h < 2; h++) { acc[h][0] = acc[h][1] = acc[h][2] = acc[h][3] = 0.f; }
        mma_bf16(acc[0], a[0], b[0][0], b[0][1]); mma_bf16(acc[0], a[1], b[1][0], b[1][1]);
        mma_bf16(acc[1], a[0], b[0][2], b[0][3]); mma_bf16(acc[1], a[1], b[1][2], b[1][3]);
        #pragma unroll
        for (int h = 0; h < 2; h++) {
            int t = tb + h * 8 + 2 * tg;
            #pragma unroll
            for (int rr = 0; rr < 2; rr++) {
                int j = jt * 16 + g + 8 * rr;
                int il0 = (DSIGN > 0) ? (47 + j - t) : (t + j - 191);
                int il1 = (DSIGN > 0) ? (il0 - 1) : (il0 + 1);
                if ((unsigned)il0 < 48u) Ssm[il0 * 196 + j] += acc[h][rr * 2 + 0];
                if ((unsigned)il1 < 48u) Ssm[il1 * 196 + j] += acc[h][rr * 2 + 1];
            }
        }
    }
    __syncthreads();

    // ---- warps 0-5: QK^T (m-tile = wid>>1, col-half = wid&1) + gather.
    //      warps 6-7: load Vt into the dead PQs region.
    float acc[12][4];
    int mt = wid >> 1, chalf = wid & 1;
    int ilA = mt * 16 + g, ilB = ilA + 8;
    if (wid < 6) {
        #pragma unroll
        for (int nt = 0; nt < 12; nt++)
            #pragma unroll
            for (int q = 0; q < 4; q++) acc[nt][q] = 0.f;

        unsigned a[2][4];
        #pragma unroll
        for (int ks = 0; ks < 2; ks++) {
            unsigned addrA = qBase + (unsigned)((mt * 16 + (lane & 15)) * 80 + (ks * 2 + (lane >> 4)) * 16);
            ldm4(a[ks][0], a[ks][1], a[ks][2], a[ks][3], addrA);
        }
        #pragma unroll
        for (int nt16 = 0; nt16 < 6; nt16++) {
            unsigned b[2][4];
            #pragma unroll
            for (int ks = 0; ks < 2; ks++) {
                int row = chalf * 96 + nt16 * 16 + (lane & 7) + ((lane >> 4) << 3);
                unsigned addrB = kBase + (unsigned)(row * 80 + (ks * 2 + ((lane >> 3) & 1)) * 16);
                ldm4(b[ks][0], b[ks][1], b[ks][2], b[ks][3], addrB);
            }
            mma_bf16(acc[nt16 * 2],     a[0], b[0][0], b[0][1]);
            mma_bf16(acc[nt16 * 2],     a[1], b[1][0], b[1][1]);
            mma_bf16(acc[nt16 * 2 + 1], a[0], b[0][2], b[0][3]);
            mma_bf16(acc[nt16 * 2 + 1], a[1], b[1][2], b[1][3]);
        }

        #pragma unroll
        for (int nt = 0; nt < 12; nt++) {
            int j = chalf * 96 + nt * 8 + 2 * tg;
            float2 zA = *(const float2*)&Ssm[ilA * 196 + j];
            float2 zB = *(const float2*)&Ssm[ilB * 196 + j];
            acc[nt][0] += zA.x; acc[nt][1] += zA.y;
            acc[nt][2] += zB.x; acc[nt][3] += zB.y;
        }

        float mA = -1e30f, mB = -1e30f;
        #pragma unroll
        for (int nt = 0; nt < 12; nt++) {
            mA = fmaxf(mA, fmaxf(acc[nt][0], acc[nt][1]));
            mB = fmaxf(mB, fmaxf(acc[nt][2], acc[nt][3]));
        }
        mA = fmaxf(mA, __shfl_xor_sync(0xffffffffu, mA, 1));
        mA = fmaxf(mA, __shfl_xor_sync(0xffffffffu, mA, 2));
        mB = fmaxf(mB, __shfl_xor_sync(0xffffffffu, mB, 1));
        mB = fmaxf(mB, __shfl_xor_sync(0xffffffffu, mB, 2));
        if (tg == 0) {
            hmax[chalf * 48 + ilA] = mA;
            hmax[chalf * 48 + ilB] = mB;
        }
    } else {
        for (int idx = tid - 192; idx < 192 * 8; idx += 64) {
            int j = idx >> 3, c4 = (idx & 7) * 4;
            float4 v = *(const float4*)(vPtr + (size_t)(j * nB + n) * vPitch + vOff + e * 32 + c4);
            Vt[(c4 + 0) * 200 + j] = __float2bfloat16(v.x);
            Vt[(c4 + 1) * 200 + j] = __float2bfloat16(v.y);
            Vt[(c4 + 2) * 200 + j] = __float2bfloat16(v.z);
            Vt[(c4 + 3) * 200 + j] = __float2bfloat16(v.w);
        }
    }
    __syncthreads();

    // ---- exp + partial sums ----
    if (wid < 6) {
        float mA = fmaxf(hmax[ilA], hmax[48 + ilA]);
        float mB = fmaxf(hmax[ilB], hmax[48 + ilB]);
        float sA = 0.f, sB = 0.f;
        #pragma unroll
        for (int nt = 0; nt < 12; nt++) {
            acc[nt][0] = __expf(acc[nt][0] - mA); sA += acc[nt][0];
            acc[nt][1] = __expf(acc[nt][1] - mA); sA += acc[nt][1];
            acc[nt][2] = __expf(acc[nt][2] - mB); sB += acc[nt][2];
            acc[nt][3] = __expf(acc[nt][3] - mB); sB += acc[nt][3];
        }
        sA += __shfl_xor_sync(0xffffffffu, sA, 1);
        sA += __shfl_xor_sync(0xffffffffu, sA, 2);
        sB += __shfl_xor_sync(0xffffffffu, sB, 1);
        sB += __shfl_xor_sync(0xffffffffu, sB, 2);
        if (tg == 0) {
            hsum[chalf * 48 + ilA] = sA;
            hsum[chalf * 48 + ilB] = sB;
        }
    }
    __syncthreads();

    // ---- normalize, write P (packed bf16 over Ssm) ----
    if (wid < 6) {
        float invA = 1.f / (hsum[ilA] + hsum[48 + ilA]);
        float invB = 1.f / (hsum[ilB] + hsum[48 + ilB]);
        unsigned* Pw = (unsigned*)Ssm;
        #pragma unroll
        for (int nt = 0; nt < 12; nt++) {
            int cw = chalf * 48 + nt * 4 + tg;
            Pw[ilA * 196 + cw] = pack_bf2(acc[nt][0] * invA, acc[nt][1] * invA);
            Pw[ilB * 196 + cw] = pack_bf2(acc[nt][2] * invB, acc[nt][3] * invB);
        }
    }
    __syncthreads();

    // ---- O = P @ V : 6 warps (3 m-tiles x 2 k-halves); combine via Opart ----
    float oacc[4][4];
    if (wid < 6) {
        #pragma unroll
        for (int t = 0; t < 4; t++)
            #pragma unroll
            for (int q = 0; q < 4; q++) oacc[t][q] = 0.f;

        #pragma unroll 1
        for (int s = 0; s < 6; s++) {
            int ks = chalf * 6 + s;
            unsigned a[4];
            unsigned addrA = pBase + (unsigned)((mt * 16 + (lane & 15)) * 784 + (ks * 2 + (lane >> 4)) * 16);
            ldm4(a[0], a[1], a[2], a[3], addrA);
            #pragma unroll
            for (int nb = 0; nb < 2; nb++) {
                int row = nb * 16 + (lane & 7) + ((lane >> 4) << 3);
                unsigned addrB = vtBase + (unsigned)(row * 400 + (ks * 2 + ((lane >> 3) & 1)) * 16);
                unsigned b0, b1, b2, b3;
                ldm4(b0, b1, b2, b3, addrB);
                mma_bf16(oacc[nb * 2],     a, b0, b1);
                mma_bf16(oacc[nb * 2 + 1], a, b2, b3);
            }
        }
        if (chalf == 1) {
            #pragma unroll
            for (int t = 0; t < 4; t++) {
                int c = t * 8 + 2 * tg;
                Opart[ilA * 32 + c]     = oacc[t][0];
                Opart[ilA * 32 + c + 1] = oacc[t][1];
                Opart[ilB * 32 + c]     = oacc[t][2];
                Opart[ilB * 32 + c + 1] = oacc[t][3];
            }
        }
    }
    __syncthreads();

    if (wid < 6 && chalf == 0) {
        int iA = i0 + ilA, iB = i0 + ilB;
        size_t oA = (size_t)(iA * nB + n) * 128 + e * 32;
        size_t oB = (size_t)(iB * nB + n) * 128 + e * 32;
        #pragma unroll
        for (int t = 0; t < 4; t++) {
            int c = t * 8 + 2 * tg;
            float2 vA, vB;
            vA.x = oacc[t][0] + Opart[ilA * 32 + c];
            vA.y = oacc[t][1] + Opart[ilA * 32 + c + 1];
            vB.x = oacc[t][2] + Opart[ilB * 32 + c];
            vB.y = oacc[t][3] + Opart[ilB * 32 + c + 1];
            *(float2*)(vo + oA + c) = vA;
            *(float2*)(vo + oB + c) = vB;
        }
    }
}

// ---------------------------------------------------------------------------
extern "C" void kernel_launch(void* const* d_in, const int* in_sizes, int n_in,
                              void* d_out, int out_size)
{
    (void)in_sizes; (void)n_in; (void)out_size;
    const float* feat_left  = (const float*)d_in[0];
    const float* feat_right = (const float*)d_in[1];
    const float* pos_enc    = (const float*)d_in[2];
    const float* s_iw = (const float*)d_in[3];
    const float* s_ib = (const float*)d_in[4];
    const float* s_ow = (const float*)d_in[5];
    const float* s_ob = (const float*)d_in[6];
    const float* s_g  = (const float*)d_in[7];
    const float* s_b  = (const float*)d_in[8];
    const float* c_iw = (const float*)d_in[9];
    const float* c_ib = (const float*)d_in[10];
    const float* c_ow = (const float*)d_in[11];
    const float* c_ob = (const float*)d_in[12];
    const float* c_g1 = (const float*)d_in[13];
    const float* c_b1 = (const float*)d_in[14];
    const float* c_g2 = (const float*)d_in[15];
    const float* c_b2 = (const float*)d_in[16];

    float* feat = (float*)d_out;

    float *ln_buf, *ln2_buf, *qkv, *vo, *projb;
    cudaGetSymbolAddress((void**)&ln_buf, g_ln);
    cudaGetSymbolAddress((void**)&ln2_buf, g_ln2);
    cudaGetSymbolAddress((void**)&qkv, g_qkv);
    cudaGetSymbolAddress((void**)&vo, g_vo);
    cudaGetSymbolAddress((void**)&projb, g_proj);
    float* projS = projb;
    float* projC = projb + 383 * 256;
    float* qb  = qkv;
    float* kvb = qkv + 192 * 128 * 128;

    cudaFuncSetAttribute(attn_tc<1>,  cudaFuncAttributeMaxDynamicSharedMemorySize, ATC_SMEM);
    cudaFuncSetAttribute(attn_tc<-1>, cudaFuncAttributeMaxDynamicSharedMemorySize, ATC_SMEM);
    cudaFuncSetAttribute(hgemm, cudaFuncAttributeMaxDynamicSharedMemorySize, HSMEM);

    build_feat<<<dim3(6, 4, 256), dim3(32, 32)>>>(feat_left, feat_right, feat);

    for (int L = 0; L < 4; L++) {
        const float* siw = s_iw + (size_t)L * 384 * 128;
        const float* sib = s_ib + (size_t)L * 384;
        const float* sow = s_ow + (size_t)L * 128 * 128;
        const float* sob = s_ob + (size_t)L * 128;
        const float* ciw = c_iw + (size_t)L * 384 * 128;
        const float* cib = c_ib + (size_t)L * 384;
        const float* cow = c_ow + (size_t)L * 128 * 128;
        const float* cob = c_ob + (size_t)L * 128;

        // ---------------- self-attention ----------------
        ln4_kernel<<<12288, 128>>>(feat, 0, 256, 256, s_g + L * 128, s_b + L * 128, ln_buf);
        sgemm64<<<dim3(4, 6), 256>>>(pos_enc, 0, 383, 383, siw, sib,
                                     projS, 0, 383, 383, 256, 383, 256, 0);
        hgemm<<<dim3(3, 384), 256, HSMEM>>>(ln_buf, 0, 256, 256, siw, sib,
                                            qkv, 0, 256, 256, 384, 0);
        attn_tc<1><<<dim3(256, 4, 4), 256, ATC_SMEM>>>(qkv, 384, 0, qkv, 384, 128,
                                                       qkv, 384, 256, projS, vo, 256);
        hgemm<<<dim3(1, 384), 256, HSMEM>>>(vo, 0, 256, 256, sow, sob,
                                            feat, 0, 256, 256, 128, 1);

        // ---------------- cross-attention ----------------
        ln4_kernel<<<12288, 128>>>(feat, 0, 256, 256, c_g1 + L * 128, c_b1 + L * 128, ln_buf);
        sgemm64<<<dim3(4, 6), 256>>>(pos_enc, 0, 383, 383, ciw, cib,
                                     projC, 0, 383, 383, 256, 383, 256, 0);

        // fr update: q from fr2, kv from fl2, flipped table (DSIGN=-1)
        hgemm<<<dim3(1, 192), 256, HSMEM>>>(ln_buf, 128, 128, 256, ciw, cib,
                                            qb, 0, 128, 128, 128, 0);
        hgemm<<<dim3(2, 192), 256, HSMEM>>>(ln_buf, 0, 128, 256, ciw + 128 * 128, cib + 128,
                                            kvb, 0, 128, 128, 256, 0);
        attn_tc<-1><<<dim3(128, 4, 4), 256, ATC_SMEM>>>(qb, 128, 0, kvb, 256, 0,
                                                        kvb, 256, 128, projC, vo, 128);
        hgemm<<<dim3(1, 192), 256, HSMEM>>>(vo, 0, 128, 128, cow, cob,
                                            feat, 128, 128, 256, 128, 1);

        // fr2n = LN(updated fr)
        ln4_kernel<<<6144, 128>>>(feat, 128, 128, 256, c_g2 + L * 128, c_b2 + L * 128, ln2_buf);

        // fl update: q from fl2, kv from fr2n, normal table (DSIGN=+1)
        hgemm<<<dim3(1, 192), 256, HSMEM>>>(ln_buf, 0, 128, 256, ciw, cib,
                                            qb, 0, 128, 128, 128, 0);
        hgemm<<<dim3(2, 192), 256, HSMEM>>>(ln2_buf, 0, 128, 128, ciw + 128 * 128, cib + 128,
                                            kvb, 0, 128, 128, 256, 0);
        attn_tc<1><<<dim3(128, 4, 4), 256, ATC_SMEM>>>(qb, 128, 0, kvb, 256, 0,
                                                       kvb, 256, 128, projC, vo, 128);
        hgemm<<<dim3(1, 192), 256, HSMEM>>>(vo, 0, 128, 128, cow, cob,
                                            feat, 0, 128, 256, 128, 1);
    }
}

// round 9
// speedup vs baseline: 1.1894x; 1.0816x over previous
#include <cuda_runtime.h>
#include <cuda_bf16.h>
#include <math.h>

// ---------------------------------------------------------------------------
// STTM: 4-layer transformer, w=192, C=128, NHEAD=4, hd=32
// feat (fp32, d_out): (w, n, C). Self: n in [0,256). fl: n<128, fr: n>=128.
// Activations between GEMMs and attention are bf16. LayerNorm fused into the
// GEMM A-load. pos_enc projections batched into one up-front launch.
// ---------------------------------------------------------------------------

#define W_ 192
#define CC 128

// ------------------------- device scratch ---------------------------------
__device__ __nv_bfloat16 g_qkvh[W_*256*384];   // qkv (self) / qb+kvb (cross)
__device__ __nv_bfloat16 g_voh [W_*256*CC];    // attention output
__device__ float g_proj[8*383*256];            // per (layer, self|cross) proj

// ------------------------- helpers -----------------------------------------
__device__ __forceinline__ unsigned pack_bf2(float x, float y) {
    __nv_bfloat162 h = __float22bfloat162_rn(make_float2(x, y));
    return *(unsigned*)&h;
}
__device__ __forceinline__ uint2 pack4(float4 v) {
    uint2 u; u.x = pack_bf2(v.x, v.y); u.y = pack_bf2(v.z, v.w); return u;
}
__device__ __forceinline__ uint2 pack4s(float4 v, float s) {
    uint2 u; u.x = pack_bf2(v.x * s, v.y * s); u.y = pack_bf2(v.z * s, v.w * s); return u;
}

__device__ __forceinline__ void ldm4(unsigned& r0, unsigned& r1, unsigned& r2, unsigned& r3,
                                     unsigned addr) {
    asm volatile("ldmatrix.sync.aligned.m8n8.x4.shared.b16 {%0,%1,%2,%3},[%4];"
                 : "=r"(r0), "=r"(r1), "=r"(r2), "=r"(r3) : "r"(addr));
}

__device__ __forceinline__ void mma_bf16(float* d, const unsigned* a, unsigned b0, unsigned b1) {
    asm volatile(
        "mma.sync.aligned.m16n8k16.row.col.f32.bf16.bf16.f32 "
        "{%0,%1,%2,%3},{%4,%5,%6,%7},{%8,%9},{%0,%1,%2,%3};"
        : "+f"(d[0]), "+f"(d[1]), "+f"(d[2]), "+f"(d[3])
        : "r"(a[0]), "r"(a[1]), "r"(a[2]), "r"(a[3]), "r"(b0), "r"(b1));
}

// ------------------------- build feat from inputs -------------------------
__global__ void build_feat(const float* __restrict__ L, const float* __restrict__ R,
                           float* __restrict__ feat)
{
    __shared__ float tile[32][33];
    int n = blockIdx.z;
    const float* src = (n < 128) ? L : R;
    int nn = n & 127;
    int h = nn >> 1, b = nn & 1;
    int i = blockIdx.x * 32 + threadIdx.x;
    int c = blockIdx.y * 32 + threadIdx.y;
    tile[threadIdx.y][threadIdx.x] = src[(((size_t)b * 128 + c) * 64 + h) * 192 + i];
    __syncthreads();
    int i2 = blockIdx.x * 32 + threadIdx.y;
    int c2 = blockIdx.y * 32 + threadIdx.x;
    feat[((size_t)i2 * 256 + n) * 128 + c2] = tile[threadIdx.x][threadIdx.y];
}

// ------------------------- batched pos_enc projection ----------------------
// One launch computes all 8 (layer x {self,cross}) projections:
// out[z] = pos_enc @ W[z][:256].T + b[z][:256], z = layer*2 + isCross.
__global__ void proj_batch(const float* __restrict__ pos_enc,
                           const float* __restrict__ s_iw, const float* __restrict__ s_ib,
                           const float* __restrict__ c_iw, const float* __restrict__ c_ib,
                           float* __restrict__ out)
{
    int z = blockIdx.z, layer = z >> 1;
    const float* B    = ((z & 1) ? c_iw : s_iw) + (size_t)layer * 384 * 128;
    const float* bias = ((z & 1) ? c_ib : s_ib) + layer * 384;
    float* C = out + (size_t)z * 383 * 256;
    const int M = 383, N = 256;

    __shared__ float As[16][68];
    __shared__ float Bs[16][68];
    int tid = threadIdx.x;
    int tx = tid & 15, ty = tid >> 4;
    int rowBase = blockIdx.y * 64;
    int colBase = blockIdx.x * 64;

    float acc[4][4];
    #pragma unroll
    for (int i = 0; i < 4; i++)
        #pragma unroll
        for (int j = 0; j < 4; j++) acc[i][j] = 0.f;

    int lr = tid >> 2;
    int lc = (tid & 3) * 4;
    int ar = rowBase + lr;
    const float* aRowPtr = (ar < M) ? (pos_enc + (size_t)ar * 128) : nullptr;
    int bc = colBase + lr;
    const float* bRowPtr = (bc < N) ? (B + (size_t)bc * 128) : nullptr;

    for (int kt = 0; kt < 8; kt++) {
        int k0 = kt * 16 + lc;
        float4 av = aRowPtr ? *(const float4*)(aRowPtr + k0) : make_float4(0, 0, 0, 0);
        float4 bv = bRowPtr ? *(const float4*)(bRowPtr + k0) : make_float4(0, 0, 0, 0);
        As[lc + 0][lr] = av.x; As[lc + 1][lr] = av.y; As[lc + 2][lr] = av.z; As[lc + 3][lr] = av.w;
        Bs[lc + 0][lr] = bv.x; Bs[lc + 1][lr] = bv.y; Bs[lc + 2][lr] = bv.z; Bs[lc + 3][lr] = bv.w;
        __syncthreads();
        #pragma unroll
        for (int k = 0; k < 16; k++) {
            float a0 = As[k][ty * 4 + 0], a1 = As[k][ty * 4 + 1];
            float a2 = As[k][ty * 4 + 2], a3 = As[k][ty * 4 + 3];
            float b0 = Bs[k][tx * 4 + 0], b1 = Bs[k][tx * 4 + 1];
            float b2 = Bs[k][tx * 4 + 2], b3 = Bs[k][tx * 4 + 3];
            acc[0][0] = fmaf(a0, b0, acc[0][0]); acc[0][1] = fmaf(a0, b1, acc[0][1]);
            acc[0][2] = fmaf(a0, b2, acc[0][2]); acc[0][3] = fmaf(a0, b3, acc[0][3]);
            acc[1][0] = fmaf(a1, b0, acc[1][0]); acc[1][1] = fmaf(a1, b1, acc[1][1]);
            acc[1][2] = fmaf(a1, b2, acc[1][2]); acc[1][3] = fmaf(a1, b3, acc[1][3]);
            acc[2][0] = fmaf(a2, b0, acc[2][0]); acc[2][1] = fmaf(a2, b1, acc[2][1]);
            acc[2][2] = fmaf(a2, b2, acc[2][2]); acc[2][3] = fmaf(a2, b3, acc[2][3]);
            acc[3][0] = fmaf(a3, b0, acc[3][0]); acc[3][1] = fmaf(a3, b1, acc[3][1]);
            acc[3][2] = fmaf(a3, b2, acc[3][2]); acc[3][3] = fmaf(a3, b3, acc[3][3]);
        }
        __syncthreads();
    }

    #pragma unroll
    for (int mi = 0; mi < 4; mi++) {
        int r = rowBase + ty * 4 + mi;
        if (r >= M) continue;
        float* cRow = C + (size_t)r * 256;
        #pragma unroll
        for (int ni = 0; ni < 4; ni++) {
            int col = colBase + tx * 4 + ni;
            cRow[col] = acc[mi][ni] + bias[col];
        }
    }
}

// ------------------------- bf16 tensor-core GEMM ---------------------------
// AMODE: 0 = A fp32, 1 = A fp32 + fused LayerNorm(lnG, lnB), 2 = A bf16.
// Output: if Cbf != null -> bf16 store (cols < scaleLim multiplied by hd^-0.5);
// else fp32 store with optional residual add.
#define HSMEM (2 * 128 * 128 * 2)

template<int AMODE>
__global__ void __launch_bounds__(256) hgemm(
    const void* __restrict__ Av, int aN0, int aNW, int aNF,
    const float* __restrict__ lnG, const float* __restrict__ lnB,
    const float* __restrict__ B, const float* __restrict__ bias,
    float* __restrict__ C, __nv_bfloat16* __restrict__ Cbf,
    int cN0, int cNW, int cNF, int cPitch,
    int addRes, int scaleLim)
{
    extern __shared__ __nv_bfloat16 hsm[];
    __nv_bfloat16* As = hsm;
    __nv_bfloat16* Bs = hsm + 128*128;

    int tid = threadIdx.x;
    int rowBase = blockIdx.y * 128;
    int colBase = blockIdx.x * 128;

    int lr = tid >> 1, lkh = tid & 1;
    {
        int ar = rowBase + lr;
        int arow = (ar / aNW) * aNF + aN0 + (ar % aNW);
        const float* bp = B + (size_t)(colBase + lr) * 128 + lkh * 64;
        int sw = lr & 7;

        float mean = 0.f, inv = 1.f;
        if (AMODE == 1) {
            const float* ap = (const float*)Av + (size_t)arow * 128 + lkh * 64;
            float s = 0.f, sq = 0.f;
            #pragma unroll
            for (int j = 0; j < 16; j++) {
                float4 v = *(const float4*)(ap + j * 4);
                s += v.x + v.y + v.z + v.w;
                sq += v.x*v.x + v.y*v.y + v.z*v.z + v.w*v.w;
            }
            s  += __shfl_xor_sync(0xffffffffu, s,  1);
            sq += __shfl_xor_sync(0xffffffffu, sq, 1);
            mean = s * (1.f / 128.f);
            float var = sq * (1.f / 128.f) - mean * mean;
            inv = rsqrtf(var + 1e-5f);
        }

        #pragma unroll
        for (int j = 0; j < 8; j++) {
            int c = lkh * 8 + j;
            int cp = c ^ sw;
            uint4 u;
            if (AMODE == 2) {
                const __nv_bfloat16* ap = (const __nv_bfloat16*)Av + (size_t)arow * 128 + lkh * 64;
                u = *(const uint4*)(ap + j * 8);
            } else {
                const float* ap = (const float*)Av + (size_t)arow * 128 + lkh * 64;
                float4 v0 = *(const float4*)(ap + j * 8);
                float4 v1 = *(const float4*)(ap + j * 8 + 4);
                if (AMODE == 1) {
                    int ch = lkh * 64 + j * 8;
                    float4 g0 = *(const float4*)(lnG + ch), g1 = *(const float4*)(lnG + ch + 4);
                    float4 b0 = *(const float4*)(lnB + ch), b1 = *(const float4*)(lnB + ch + 4);
                    v0.x = (v0.x - mean) * inv * g0.x + b0.x;
                    v0.y = (v0.y - mean) * inv * g0.y + b0.y;
                    v0.z = (v0.z - mean) * inv * g0.z + b0.z;
                    v0.w = (v0.w - mean) * inv * g0.w + b0.w;
                    v1.x = (v1.x - mean) * inv * g1.x + b1.x;
                    v1.y = (v1.y - mean) * inv * g1.y + b1.y;
                    v1.z = (v1.z - mean) * inv * g1.z + b1.z;
                    v1.w = (v1.w - mean) * inv * g1.w + b1.w;
                }
                u.x = pack_bf2(v0.x, v0.y); u.y = pack_bf2(v0.z, v0.w);
                u.z = pack_bf2(v1.x, v1.y); u.w = pack_bf2(v1.z, v1.w);
            }
            *(uint4*)&As[lr * 128 + cp * 8] = u;

            float4 w0 = *(const float4*)(bp + j * 8);
            float4 w1 = *(const float4*)(bp + j * 8 + 4);
            uint4 ub;
            ub.x = pack_bf2(w0.x, w0.y); ub.y = pack_bf2(w0.z, w0.w);
            ub.z = pack_bf2(w1.x, w1.y); ub.w = pack_bf2(w1.z, w1.w);
            *(uint4*)&Bs[lr * 128 + cp * 8] = ub;
        }
    }
    __syncthreads();

    int wid = tid >> 5, lane = tid & 31;
    int wm = (wid & 3) * 32;
    int wn = (wid >> 2) * 64;
    int g = lane >> 2, tg = lane & 3;

    float acc[2][8][4];
    #pragma unroll
    for (int mt = 0; mt < 2; mt++)
        #pragma unroll
        for (int nt = 0; nt < 8; nt++)
            #pragma unroll
            for (int q = 0; q < 4; q++) acc[mt][nt][q] = 0.f;

    unsigned asBase = (unsigned)__cvta_generic_to_shared(As);
    unsigned bsBase = (unsigned)__cvta_generic_to_shared(Bs);

    #pragma unroll
    for (int ks = 0; ks < 8; ks++) {
        int c0 = ks * 2;
        unsigned afr[2][4];
        #pragma unroll
        for (int mt = 0; mt < 2; mt++) {
            int row = wm + mt * 16 + (lane & 15);
            int ch = c0 + (lane >> 4);
            unsigned addr = asBase + (unsigned)((row * 128 + ((ch ^ (row & 7)) << 3)) * 2);
            ldm4(afr[mt][0], afr[mt][1], afr[mt][2], afr[mt][3], addr);
        }
        unsigned bfr[8][2];
        #pragma unroll
        for (int p = 0; p < 4; p++) {
            int row = wn + p * 16 + (lane & 7) + ((lane >> 4) << 3);
            int ch = c0 + ((lane >> 3) & 1);
            unsigned addr = bsBase + (unsigned)((row * 128 + ((ch ^ (row & 7)) << 3)) * 2);
            unsigned r0, r1, r2, r3;
            ldm4(r0, r1, r2, r3, addr);
            bfr[p * 2][0] = r0;     bfr[p * 2][1] = r1;
            bfr[p * 2 + 1][0] = r2; bfr[p * 2 + 1][1] = r3;
        }
        #pragma unroll
        for (int mt = 0; mt < 2; mt++)
            #pragma unroll
            for (int nt = 0; nt < 8; nt++)
                mma_bf16(acc[mt][nt], afr[mt], bfr[nt][0], bfr[nt][1]);
    }

    const float qsc = 0.17677669529663687f;
    #pragma unroll
    for (int mt = 0; mt < 2; mt++) {
        int r0g = rowBase + wm + mt * 16 + g;
        #pragma unroll
        for (int half = 0; half < 2; half++) {
            int r = r0g + half * 8;
            int crow = (r / cNW) * cNF + cN0 + (r % cNW);
            #pragma unroll
            for (int nt = 0; nt < 8; nt++) {
                int col = colBase + wn + nt * 8 + 2 * tg;
                float2 b2 = *(const float2*)(bias + col);
                float vx = acc[mt][nt][half * 2 + 0] + b2.x;
                float vy = acc[mt][nt][half * 2 + 1] + b2.y;
                if (Cbf) {
                    if (col < scaleLim) { vx *= qsc; vy *= qsc; }
                    *(unsigned*)(Cbf + (size_t)crow * cPitch + col) = pack_bf2(vx, vy);
                } else {
                    float* cp = C + (size_t)crow * cPitch + col;
                    if (addRes) {
                        float2 old = *(const float2*)cp;
                        vx += old.x; vy += old.y;
                    }
                    float2 o2; o2.x = vx; o2.y = vy;
                    *(float2*)cp = o2;
                }
            }
        }
    }
}

// ------------------------- bf16 mma attention (48-row blocks) ---------------
// Block = (n, e, q: rows i in [q*48, q*48+48)). 256 threads = 8 warps.
// q/k/v are bf16 (q pre-scaled by hd^-0.5 in the projection epilogue).
// S[il][j] = QK[il][j] + Ssm[il][j]; Ssm = skew(Q@PK^T) + skew(K@PQ^T).
// smem: Qs@0 (48x40 bf16), Ks@3840 (192x40; Opart 48x32 f32 overlays),
//   PKs@19200 (240x40), PQs@38400 (240x40; Vt 32x200 bf16 overlays),
//   Ssm@57600 (48x196 f32 -> packed-bf16 P), stats@95232 (4x48 f32). 96000 B.
#define ATC_SMEM 96000

template<int DSIGN>
__global__ void __launch_bounds__(256, 2) attn_tc(
    const __nv_bfloat16* __restrict__ qPtr, int qPitch, int qOff,
    const __nv_bfloat16* __restrict__ kPtr, int kPitch, int kOff,
    const __nv_bfloat16* __restrict__ vPtr, int vPitch, int vOff,
    const float* __restrict__ proj, __nv_bfloat16* __restrict__ vo, int nB)
{
    extern __shared__ char smraw[];
    __nv_bfloat16* Qs  = (__nv_bfloat16*)(smraw);
    __nv_bfloat16* Ks  = (__nv_bfloat16*)(smraw + 3840);
    __nv_bfloat16* PKs = (__nv_bfloat16*)(smraw + 19200);
    __nv_bfloat16* PQs = (__nv_bfloat16*)(smraw + 38400);
    __nv_bfloat16* Vt  = PQs;                       // overlay (after Z2 phase)
    float* Opart = (float*)(smraw + 3840);          // overlay Ks (after QK phase)
    float* Ssm  = (float*)(smraw + 57600);
    float* hmax = (float*)(smraw + 95232);          // [2][48]
    float* hsum = hmax + 96;                        // [2][48]

    int n = blockIdx.x, e = blockIdx.y;
    int i0 = blockIdx.z * 48;
    int tid = threadIdx.x;
    const float scale = 0.17677669529663687f;
    const int dlo = (DSIGN > 0) ? (144 - i0) : i0;

    // ---- loads: Q, K (raw bf16, 4 x uint4 = 32 elems per row), PK, PQ ----
    for (int idx = tid; idx < 48 * 4; idx += 256) {
        int r = idx >> 2, h = (idx & 3) * 8;
        uint4 u = *(const uint4*)(qPtr + (size_t)((i0 + r) * nB + n) * qPitch + qOff + e * 32 + h);
        *(uint4*)&Qs[r * 40 + h] = u;
    }
    for (int idx = tid; idx < 192 * 4; idx += 256) {
        int r = idx >> 2, h = (idx & 3) * 8;
        uint4 u = *(const uint4*)(kPtr + (size_t)(r * nB + n) * kPitch + kOff + e * 32 + h);
        *(uint4*)&Ks[r * 40 + h] = u;
    }
    for (int idx = tid; idx < 240 * 8; idx += 256) {
        int t = idx >> 3, c4 = (idx & 7) * 4;
        int d = dlo + t;
        float4 vk = make_float4(0, 0, 0, 0), vq = make_float4(0, 0, 0, 0);
        if (d < 383) {
            vk = *(const float4*)(proj + (size_t)d * 256 + 128 + e * 32 + c4);
            vq = *(const float4*)(proj + (size_t)d * 256 + e * 32 + c4);
        }
        *(uint2*)&PKs[t * 40 + c4] = pack4(vk);
        *(uint2*)&PQs[t * 40 + c4] = pack4s(vq, scale);
    }
    __syncthreads();

    int wid = tid >> 5, lane = tid & 31;
    int g = lane >> 2, tg = lane & 3;
    unsigned qBase  = (unsigned)__cvta_generic_to_shared(Qs);
    unsigned kBase  = (unsigned)__cvta_generic_to_shared(Ks);
    unsigned pkBase = (unsigned)__cvta_generic_to_shared(PKs);
    unsigned pqBase = (unsigned)__cvta_generic_to_shared(PQs);
    unsigned vtBase = (unsigned)__cvta_generic_to_shared(Vt);
    unsigned pBase  = (unsigned)__cvta_generic_to_shared(Ssm);

    // ---- Z1 = Q @ PK^T, skew-scattered (init): 3 m-tiles x 13 n16-tiles ----
    #pragma unroll 1
    for (int u = wid; u < 39; u += 8) {
        int mt = u / 13, nt = u % 13;
        int t0m = (DSIGN > 0) ? (32 - 16 * mt) : (16 * mt);
        int tb = t0m + nt * 16;
        unsigned a[2][4], b[2][4];
        #pragma unroll
        for (int ks = 0; ks < 2; ks++) {
            unsigned addrA = qBase + (unsigned)((mt * 16 + (lane & 15)) * 80 + (ks * 2 + (lane >> 4)) * 16);
            ldm4(a[ks][0], a[ks][1], a[ks][2], a[ks][3], addrA);
            int row = tb + (lane & 7) + ((lane >> 4) << 3);
            unsigned addrB = pkBase + (unsigned)(row * 80 + (ks * 2 + ((lane >> 3) & 1)) * 16);
            ldm4(b[ks][0], b[ks][1], b[ks][2], b[ks][3], addrB);
        }
        float acc[2][4];
        #pragma unroll
        for (int h = 0; h < 2; h++) { acc[h][0] = acc[h][1] = acc[h][2] = acc[h][3] = 0.f; }
        mma_bf16(acc[0], a[0], b[0][0], b[0][1]); mma_bf16(acc[0], a[1], b[1][0], b[1][1]);
        mma_bf16(acc[1], a[0], b[0][2], b[0][3]); mma_bf16(acc[1], a[1], b[1][2], b[1][3]);
        #pragma unroll
        for (int h = 0; h < 2; h++) {
            int t = tb + h * 8 + 2 * tg;
            #pragma unroll
            for (int rr = 0; rr < 2; rr++) {
                int il = mt * 16 + g + 8 * rr;
                int j0 = (DSIGN > 0) ? (t + il - 47) : (191 + il - t);
                int j1 = (DSIGN > 0) ? (j0 + 1) : (j0 - 1);
                if ((unsigned)j0 < 192u) Ssm[il * 196 + j0] = acc[h][rr * 2 + 0];
                if ((unsigned)j1 < 192u) Ssm[il * 196 + j1] = acc[h][rr * 2 + 1];
            }
        }
    }
    __syncthreads();

    // ---- Z2 = K @ PQ^T, skew scatter-ADD: 12 j-tiles x 4 n16-tiles ----
    #pragma unroll 1
    for (int u = wid; u < 48; u += 8) {
        int jt = u >> 2, nt = u & 3;
        int t0m = (DSIGN > 0) ? (16 * jt) : (176 - 16 * jt);
        int tb = t0m + nt * 16;
        unsigned a[2][4], b[2][4];
        #pragma unroll
        for (int ks = 0; ks < 2; ks++) {
            unsigned addrA = kBase + (unsigned)((jt * 16 + (lane & 15)) * 80 + (ks * 2 + (lane >> 4)) * 16);
            ldm4(a[ks][0], a[ks][1], a[ks][2], a[ks][3], addrA);
            int row = tb + (lane & 7) + ((lane >> 4) << 3);
            unsigned addrB = pqBase + (unsigned)(row * 80 + (ks * 2 + ((lane >> 3) & 1)) * 16);
            ldm4(b[ks][0], b[ks][1], b[ks][2], b[ks][3], addrB);
        }
        float acc[2][4];
        #pragma unroll
        for (int h = 0; h < 2; h++) { acc[h][0] = acc[h][1] = acc[h][2] = acc[h][3] = 0.f; }
        mma_bf16(acc[0], a[0], b[0][0], b[0][1]); mma_bf16(acc[0], a[1], b[1][0], b[1][1]);
        mma_bf16(acc[1], a[0], b[0][2], b[0][3]); mma_bf16(acc[1], a[1], b[1][2], b[1][3]);
        #pragma unroll
        for (int h = 0; h < 2; h++) {
            int t = tb + h * 8 + 2 * tg;
            #pragma unroll
            for (int rr = 0; rr < 2; rr++) {
                int j = jt * 16 + g + 8 * rr;
                int il0 = (DSIGN > 0) ? (47 + j - t) : (t + j - 191);
                int il1 = (DSIGN > 0) ? (il0 - 1) : (il0 + 1);
                if ((unsigned)il0 < 48u) Ssm[il0 * 196 + j] += acc[h][rr * 2 + 0];
                if ((unsigned)il1 < 48u) Ssm[il1 * 196 + j] += acc[h][rr * 2 + 1];
            }
        }
    }
    __syncthreads();

    // ---- warps 0-5: QK^T + gather + partial max. warps 6-7: load Vt ----
    float acc[12][4];
    int mt = wid >> 1, chalf = wid & 1;
    int ilA = mt * 16 + g, ilB = ilA + 8;
    if (wid < 6) {
        #pragma unroll
        for (int nt = 0; nt < 12; nt++)
            #pragma unroll
            for (int q = 0; q < 4; q++) acc[nt][q] = 0.f;

        unsigned a[2][4];
        #pragma unroll
        for (int ks = 0; ks < 2; ks++) {
            unsigned addrA = qBase + (unsigned)((mt * 16 + (lane & 15)) * 80 + (ks * 2 + (lane >> 4)) * 16);
            ldm4(a[ks][0], a[ks][1], a[ks][2], a[ks][3], addrA);
        }
        #pragma unroll
        for (int nt16 = 0; nt16 < 6; nt16++) {
            unsigned b[2][4];
            #pragma unroll
            for (int ks = 0; ks < 2; ks++) {
                int row = chalf * 96 + nt16 * 16 + (lane & 7) + ((lane >> 4) << 3);
                unsigned addrB = kBase + (unsigned)(row * 80 + (ks * 2 + ((lane >> 3) & 1)) * 16);
                ldm4(b[ks][0], b[ks][1], b[ks][2], b[ks][3], addrB);
            }
            mma_bf16(acc[nt16 * 2],     a[0], b[0][0], b[0][1]);
            mma_bf16(acc[nt16 * 2],     a[1], b[1][0], b[1][1]);
            mma_bf16(acc[nt16 * 2 + 1], a[0], b[0][2], b[0][3]);
            mma_bf16(acc[nt16 * 2 + 1], a[1], b[1][2], b[1][3]);
        }

        #pragma unroll
        for (int nt = 0; nt < 12; nt++) {
            int j = chalf * 96 + nt * 8 + 2 * tg;
            float2 zA = *(const float2*)&Ssm[ilA * 196 + j];
            float2 zB = *(const float2*)&Ssm[ilB * 196 + j];
            acc[nt][0] += zA.x; acc[nt][1] += zA.y;
            acc[nt][2] += zB.x; acc[nt][3] += zB.y;
        }

        float mA = -1e30f, mB = -1e30f;
        #pragma unroll
        for (int nt = 0; nt < 12; nt++) {
            mA = fmaxf(mA, fmaxf(acc[nt][0], acc[nt][1]));
            mB = fmaxf(mB, fmaxf(acc[nt][2], acc[nt][3]));
        }
        mA = fmaxf(mA, __shfl_xor_sync(0xffffffffu, mA, 1));
        mA = fmaxf(mA, __shfl_xor_sync(0xffffffffu, mA, 2));
        mB = fmaxf(mB, __shfl_xor_sync(0xffffffffu, mB, 1));
        mB = fmaxf(mB, __shfl_xor_sync(0xffffffffu, mB, 2));
        if (tg == 0) {
            hmax[chalf * 48 + ilA] = mA;
            hmax[chalf * 48 + ilB] = mB;
        }
    } else {
        // transpose-load V (bf16) into the dead PQs region
        for (int idx = tid - 192; idx < 192 * 4; idx += 64) {
            int j = idx >> 2, c8 = (idx & 3) * 8;
            uint4 u = *(const uint4*)(vPtr + (size_t)(j * nB + n) * vPitch + vOff + e * 32 + c8);
            __nv_bfloat16 tmp[8];
            *(uint4*)tmp = u;
            #pragma unroll
            for (int k = 0; k < 8; k++) Vt[(c8 + k) * 200 + j] = tmp[k];
        }
    }
    __syncthreads();

    // ---- exp + partial sums ----
    if (wid < 6) {
        float mA = fmaxf(hmax[ilA], hmax[48 + ilA]);
        float mB = fmaxf(hmax[ilB], hmax[48 + ilB]);
        float sA = 0.f, sB = 0.f;
        #pragma unroll
        for (int nt = 0; nt < 12; nt++) {
            acc[nt][0] = __expf(acc[nt][0] - mA); sA += acc[nt][0];
            acc[nt][1] = __expf(acc[nt][1] - mA); sA += acc[nt][1];
            acc[nt][2] = __expf(acc[nt][2] - mB); sB += acc[nt][2];
            acc[nt][3] = __expf(acc[nt][3] - mB); sB += acc[nt][3];
        }
        sA += __shfl_xor_sync(0xffffffffu, sA, 1);
        sA += __shfl_xor_sync(0xffffffffu, sA, 2);
        sB += __shfl_xor_sync(0xffffffffu, sB, 1);
        sB += __shfl_xor_sync(0xffffffffu, sB, 2);
        if (tg == 0) {
            hsum[chalf * 48 + ilA] = sA;
            hsum[chalf * 48 + ilB] = sB;
        }
    }
    __syncthreads();

    // ---- normalize, write P (packed bf16 over Ssm) ----
    if (wid < 6) {
        float invA = 1.f / (hsum[ilA] + hsum[48 + ilA]);
        float invB = 1.f / (hsum[ilB] + hsum[48 + ilB]);
        unsigned* Pw = (unsigned*)Ssm;
        #pragma unroll
        for (int nt = 0; nt < 12; nt++) {
            int cw = chalf * 48 + nt * 4 + tg;
            Pw[ilA * 196 + cw] = pack_bf2(acc[nt][0] * invA, acc[nt][1] * invA);
            Pw[ilB * 196 + cw] = pack_bf2(acc[nt][2] * invB, acc[nt][3] * invB);
        }
    }
    __syncthreads();

    // ---- O = P @ V : 6 warps (3 m-tiles x 2 k-halves); combine via Opart ----
    float oacc[4][4];
    if (wid < 6) {
        #pragma unroll
        for (int t = 0; t < 4; t++)
            #pragma unroll
            for (int q = 0; q < 4; q++) oacc[t][q] = 0.f;

        #pragma unroll 1
        for (int s = 0; s < 6; s++) {
            int ks = chalf * 6 + s;
            unsigned a[4];
            unsigned addrA = pBase + (unsigned)((mt * 16 + (lane & 15)) * 784 + (ks * 2 + (lane >> 4)) * 16);
            ldm4(a[0], a[1], a[2], a[3], addrA);
            #pragma unroll
            for (int nb = 0; nb < 2; nb++) {
                int row = nb * 16 + (lane & 7) + ((lane >> 4) << 3);
                unsigned addrB = vtBase + (unsigned)(row * 400 + (ks * 2 + ((lane >> 3) & 1)) * 16);
                unsigned b0, b1, b2, b3;
                ldm4(b0, b1, b2, b3, addrB);
                mma_bf16(oacc[nb * 2],     a, b0, b1);
                mma_bf16(oacc[nb * 2 + 1], a, b2, b3);
            }
        }
        if (chalf == 1) {
            #pragma unroll
            for (int t = 0; t < 4; t++) {
                int c = t * 8 + 2 * tg;
                Opart[ilA * 32 + c]     = oacc[t][0];
                Opart[ilA * 32 + c + 1] = oacc[t][1];
                Opart[ilB * 32 + c]     = oacc[t][2];
                Opart[ilB * 32 + c + 1] = oacc[t][3];
            }
        }
    }
    __syncthreads();

    if (wid < 6 && chalf == 0) {
        int iA = i0 + ilA, iB = i0 + ilB;
        size_t oA = (size_t)(iA * nB + n) * 128 + e * 32;
        size_t oB = (size_t)(iB * nB + n) * 128 + e * 32;
        #pragma unroll
        for (int t = 0; t < 4; t++) {
            int c = t * 8 + 2 * tg;
            *(unsigned*)(vo + oA + c) = pack_bf2(oacc[t][0] + Opart[ilA * 32 + c],
                                                 oacc[t][1] + Opart[ilA * 32 + c + 1]);
            *(unsigned*)(vo + oB + c) = pack_bf2(oacc[t][2] + Opart[ilB * 32 + c],
                                                 oacc[t][3] + Opart[ilB * 32 + c + 1]);
        }
    }
}

// ---------------------------------------------------------------------------
extern "C" void kernel_launch(void* const* d_in, const int* in_sizes, int n_in,
                              void* d_out, int out_size)
{
    (void)in_sizes; (void)n_in; (void)out_size;
    const float* feat_left  = (const float*)d_in[0];
    const float* feat_right = (const float*)d_in[1];
    const float* pos_enc    = (const float*)d_in[2];
    const float* s_iw = (const float*)d_in[3];
    const float* s_ib = (const float*)d_in[4];
    const float* s_ow = (const float*)d_in[5];
    const float* s_ob = (const float*)d_in[6];
    const float* s_g  = (const float*)d_in[7];
    const float* s_b  = (const float*)d_in[8];
    const float* c_iw = (const float*)d_in[9];
    const float* c_ib = (const float*)d_in[10];
    const float* c_ow = (const float*)d_in[11];
    const float* c_ob = (const float*)d_in[12];
    const float* c_g1 = (const float*)d_in[13];
    const float* c_b1 = (const float*)d_in[14];
    const float* c_g2 = (const float*)d_in[15];
    const float* c_b2 = (const float*)d_in[16];

    float* feat = (float*)d_out;

    __nv_bfloat16 *qkvh, *voh;
    float* projb;
    cudaGetSymbolAddress((void**)&qkvh, g_qkvh);
    cudaGetSymbolAddress((void**)&voh, g_voh);
    cudaGetSymbolAddress((void**)&projb, g_proj);
    __nv_bfloat16* qbh  = qkvh;                       // cross q:  (24576, 128) bf16
    __nv_bfloat16* kvbh = qkvh + 192 * 128 * 128;     // cross kv: (24576, 256) bf16

    cudaFuncSetAttribute(attn_tc<1>,  cudaFuncAttributeMaxDynamicSharedMemorySize, ATC_SMEM);
    cudaFuncSetAttribute(attn_tc<-1>, cudaFuncAttributeMaxDynamicSharedMemorySize, ATC_SMEM);
    cudaFuncSetAttribute(hgemm<0>, cudaFuncAttributeMaxDynamicSharedMemorySize, HSMEM);
    cudaFuncSetAttribute(hgemm<1>, cudaFuncAttributeMaxDynamicSharedMemorySize, HSMEM);
    cudaFuncSetAttribute(hgemm<2>, cudaFuncAttributeMaxDynamicSharedMemorySize, HSMEM);

    build_feat<<<dim3(6, 4, 256), dim3(32, 32)>>>(feat_left, feat_right, feat);
    proj_batch<<<dim3(4, 6, 8), 256>>>(pos_enc, s_iw, s_ib, c_iw, c_ib, projb);

    for (int L = 0; L < 4; L++) {
        const float* sow = s_ow + (size_t)L * 128 * 128;
        const float* sob = s_ob + (size_t)L * 128;
        const float* siw = s_iw + (size_t)L * 384 * 128;
        const float* sib = s_ib + (size_t)L * 384;
        const float* ciw = c_iw + (size_t)L * 384 * 128;
        const float* cib = c_ib + (size_t)L * 384;
        const float* cow = c_ow + (size_t)L * 128 * 128;
        const float* cob = c_ob + (size_t)L * 128;
        const float* projS = projb + (size_t)(L * 2) * 383 * 256;
        const float* projC = projb + (size_t)(L * 2 + 1) * 383 * 256;

        // ---------------- self-attention ----------------
        hgemm<1><<<dim3(3, 384), 256, HSMEM>>>(feat, 0, 256, 256,
                                               s_g + L * 128, s_b + L * 128,
                                               siw, sib, nullptr, qkvh,
                                               0, 256, 256, 384, 0, 128);
        attn_tc<1><<<dim3(256, 4, 4), 256, ATC_SMEM>>>(qkvh, 384, 0, qkvh, 384, 128,
                                                       qkvh, 384, 256, projS, voh, 256);
        hgemm<2><<<dim3(1, 384), 256, HSMEM>>>(voh, 0, 256, 256, nullptr, nullptr,
                                               sow, sob, feat, nullptr,
                                               0, 256, 256, 128, 1, 0);

        // ---------------- cross-attention ----------------
        // fr update: q = LN(fr; c_g1), kv = LN(fl; c_g1), flipped table
        hgemm<1><<<dim3(1, 192), 256, HSMEM>>>(feat, 128, 128, 256,
                                               c_g1 + L * 128, c_b1 + L * 128,
                                               ciw, cib, nullptr, qbh,
                                               0, 128, 128, 128, 0, 128);
        hgemm<1><<<dim3(2, 192), 256, HSMEM>>>(feat, 0, 128, 256,
                                               c_g1 + L * 128, c_b1 + L * 128,
                                               ciw + 128 * 128, cib + 128, nullptr, kvbh,
                                               0, 128, 128, 256, 0, 0);
        attn_tc<-1><<<dim3(128, 4, 4), 256, ATC_SMEM>>>(qbh, 128, 0, kvbh, 256, 0,
                                                        kvbh, 256, 128, projC, voh, 128);
        hgemm<2><<<dim3(1, 192), 256, HSMEM>>>(voh, 0, 128, 128, nullptr, nullptr,
                                               cow, cob, feat, nullptr,
                                               128, 128, 256, 128, 1, 0);

        // fl update: q = LN(fl; c_g1), kv = LN(updated fr; c_g2), normal table
        hgemm<1><<<dim3(2, 192), 256, HSMEM>>>(feat, 128, 128, 256,
                                               c_g2 + L * 128, c_b2 + L * 128,
                                               ciw + 128 * 128, cib + 128, nullptr, kvbh,
                                               0, 128, 128, 256, 0, 0);
        hgemm<1><<<dim3(1, 192), 256, HSMEM>>>(feat, 0, 128, 256,
                                               c_g1 + L * 128, c_b1 + L * 128,
                                               ciw, cib, nullptr, qbh,
                                               0, 128, 128, 128, 0, 128);
        attn_tc<1><<<dim3(128, 4, 4), 256, ATC_SMEM>>>(qbh, 128, 0, kvbh, 256, 0,
                                                       kvbh, 256, 128, projC, voh, 128);
        hgemm<2><<<dim3(1, 192), 256, HSMEM>>>(voh, 0, 128, 128, nullptr, nullptr,
                                               cow, cob, feat, nullptr,
                                               0, 128, 256, 128, 1, 0);
    }
}

// round 10
// speedup vs baseline: 1.2285x; 1.0328x over previous
#include <cuda_runtime.h>
#include <cuda_bf16.h>
#include <math.h>

// ---------------------------------------------------------------------------
// STTM: 4-layer transformer, w=192, C=128, NHEAD=4, hd=32
// feat (fp32, d_out): (w, n, C). Self: n in [0,256). fl: n<128, fr: n>=128.
// Activations bf16; LN fused into GEMM A-load; pos_enc projections batched,
// emitted bf16 with q-scale folded; attention scatter has interior fast paths.
// ---------------------------------------------------------------------------

#define W_ 192
#define CC 128

// ------------------------- device scratch ---------------------------------
__device__ __nv_bfloat16 g_qkvh[W_*256*384];   // qkv (self) / qb+kvb (cross)
__device__ __nv_bfloat16 g_voh [W_*256*CC];    // attention output
__device__ __nv_bfloat16 g_proj[8*383*256];    // per (layer, self|cross) proj, bf16

// ------------------------- helpers -----------------------------------------
__device__ __forceinline__ unsigned pack_bf2(float x, float y) {
    __nv_bfloat162 h = __float22bfloat162_rn(make_float2(x, y));
    return *(unsigned*)&h;
}

__device__ __forceinline__ void ldm4(unsigned& r0, unsigned& r1, unsigned& r2, unsigned& r3,
                                     unsigned addr) {
    asm volatile("ldmatrix.sync.aligned.m8n8.x4.shared.b16 {%0,%1,%2,%3},[%4];"
                 : "=r"(r0), "=r"(r1), "=r"(r2), "=r"(r3) : "r"(addr));
}

__device__ __forceinline__ void mma_bf16(float* d, const unsigned* a, unsigned b0, unsigned b1) {
    asm volatile(
        "mma.sync.aligned.m16n8k16.row.col.f32.bf16.bf16.f32 "
        "{%0,%1,%2,%3},{%4,%5,%6,%7},{%8,%9},{%0,%1,%2,%3};"
        : "+f"(d[0]), "+f"(d[1]), "+f"(d[2]), "+f"(d[3])
        : "r"(a[0]), "r"(a[1]), "r"(a[2]), "r"(a[3]), "r"(b0), "r"(b1));
}

// ------------------------- build feat from inputs -------------------------
__global__ void build_feat(const float* __restrict__ L, const float* __restrict__ R,
                           float* __restrict__ feat)
{
    __shared__ float tile[32][33];
    int n = blockIdx.z;
    const float* src = (n < 128) ? L : R;
    int nn = n & 127;
    int h = nn >> 1, b = nn & 1;
    int i = blockIdx.x * 32 + threadIdx.x;
    int c = blockIdx.y * 32 + threadIdx.y;
    tile[threadIdx.y][threadIdx.x] = src[(((size_t)b * 128 + c) * 64 + h) * 192 + i];
    __syncthreads();
    int i2 = blockIdx.x * 32 + threadIdx.y;
    int c2 = blockIdx.y * 32 + threadIdx.x;
    feat[((size_t)i2 * 256 + n) * 128 + c2] = tile[threadIdx.x][threadIdx.y];
}

// ------------------------- batched pos_enc projection ----------------------
// out[z] = bf16( pos_enc @ W[z][:256].T + b[z][:256] ), cols<128 scaled by
// hd^-0.5 (q_r side). z = layer*2 + isCross.
__global__ void proj_batch(const float* __restrict__ pos_enc,
                           const float* __restrict__ s_iw, const float* __restrict__ s_ib,
                           const float* __restrict__ c_iw, const float* __restrict__ c_ib,
                           __nv_bfloat16* __restrict__ out)
{
    int z = blockIdx.z, layer = z >> 1;
    const float* B    = ((z & 1) ? c_iw : s_iw) + (size_t)layer * 384 * 128;
    const float* bias = ((z & 1) ? c_ib : s_ib) + layer * 384;
    __nv_bfloat16* C = out + (size_t)z * 383 * 256;
    const int M = 383, N = 256;
    const float qsc = 0.17677669529663687f;

    __shared__ float As[16][68];
    __shared__ float Bs[16][68];
    int tid = threadIdx.x;
    int tx = tid & 15, ty = tid >> 4;
    int rowBase = blockIdx.y * 64;
    int colBase = blockIdx.x * 64;

    float acc[4][4];
    #pragma unroll
    for (int i = 0; i < 4; i++)
        #pragma unroll
        for (int j = 0; j < 4; j++) acc[i][j] = 0.f;

    int lr = tid >> 2;
    int lc = (tid & 3) * 4;
    int ar = rowBase + lr;
    const float* aRowPtr = (ar < M) ? (pos_enc + (size_t)ar * 128) : nullptr;
    int bc = colBase + lr;
    const float* bRowPtr = (bc < N) ? (B + (size_t)bc * 128) : nullptr;

    for (int kt = 0; kt < 8; kt++) {
        int k0 = kt * 16 + lc;
        float4 av = aRowPtr ? *(const float4*)(aRowPtr + k0) : make_float4(0, 0, 0, 0);
        float4 bv = bRowPtr ? *(const float4*)(bRowPtr + k0) : make_float4(0, 0, 0, 0);
        As[lc + 0][lr] = av.x; As[lc + 1][lr] = av.y; As[lc + 2][lr] = av.z; As[lc + 3][lr] = av.w;
        Bs[lc + 0][lr] = bv.x; Bs[lc + 1][lr] = bv.y; Bs[lc + 2][lr] = bv.z; Bs[lc + 3][lr] = bv.w;
        __syncthreads();
        #pragma unroll
        for (int k = 0; k < 16; k++) {
            float a0 = As[k][ty * 4 + 0], a1 = As[k][ty * 4 + 1];
            float a2 = As[k][ty * 4 + 2], a3 = As[k][ty * 4 + 3];
            float b0 = Bs[k][tx * 4 + 0], b1 = Bs[k][tx * 4 + 1];
            float b2 = Bs[k][tx * 4 + 2], b3 = Bs[k][tx * 4 + 3];
            acc[0][0] = fmaf(a0, b0, acc[0][0]); acc[0][1] = fmaf(a0, b1, acc[0][1]);
            acc[0][2] = fmaf(a0, b2, acc[0][2]); acc[0][3] = fmaf(a0, b3, acc[0][3]);
            acc[1][0] = fmaf(a1, b0, acc[1][0]); acc[1][1] = fmaf(a1, b1, acc[1][1]);
            acc[1][2] = fmaf(a1, b2, acc[1][2]); acc[1][3] = fmaf(a1, b3, acc[1][3]);
            acc[2][0] = fmaf(a2, b0, acc[2][0]); acc[2][1] = fmaf(a2, b1, acc[2][1]);
            acc[2][2] = fmaf(a2, b2, acc[2][2]); acc[2][3] = fmaf(a2, b3, acc[2][3]);
            acc[3][0] = fmaf(a3, b0, acc[3][0]); acc[3][1] = fmaf(a3, b1, acc[3][1]);
            acc[3][2] = fmaf(a3, b2, acc[3][2]); acc[3][3] = fmaf(a3, b3, acc[3][3]);
        }
        __syncthreads();
    }

    #pragma unroll
    for (int mi = 0; mi < 4; mi++) {
        int r = rowBase + ty * 4 + mi;
        if (r >= M) continue;
        __nv_bfloat16* cRow = C + (size_t)r * 256;
        #pragma unroll
        for (int ni = 0; ni < 4; ni++) {
            int col = colBase + tx * 4 + ni;
            float v = acc[mi][ni] + bias[col];
            if (col < 128) v *= qsc;
            cRow[col] = __float2bfloat16(v);
        }
    }
}

// ------------------------- bf16 tensor-core GEMM ---------------------------
// AMODE: 0 = A fp32, 1 = A fp32 + fused LayerNorm(lnG, lnB), 2 = A bf16.
// Output: if Cbf != null -> bf16 store (cols < scaleLim multiplied by hd^-0.5);
// else fp32 store with optional residual add.
#define HSMEM (2 * 128 * 128 * 2)

template<int AMODE>
__global__ void __launch_bounds__(256) hgemm(
    const void* __restrict__ Av, int aN0, int aNW, int aNF,
    const float* __restrict__ lnG, const float* __restrict__ lnB,
    const float* __restrict__ B, const float* __restrict__ bias,
    float* __restrict__ C, __nv_bfloat16* __restrict__ Cbf,
    int cN0, int cNW, int cNF, int cPitch,
    int addRes, int scaleLim)
{
    extern __shared__ __nv_bfloat16 hsm[];
    __nv_bfloat16* As = hsm;
    __nv_bfloat16* Bs = hsm + 128*128;

    int tid = threadIdx.x;
    int rowBase = blockIdx.y * 128;
    int colBase = blockIdx.x * 128;

    int lr = tid >> 1, lkh = tid & 1;
    {
        int ar = rowBase + lr;
        int arow = (ar / aNW) * aNF + aN0 + (ar % aNW);
        const float* bp = B + (size_t)(colBase + lr) * 128 + lkh * 64;
        int sw = lr & 7;

        float mean = 0.f, inv = 1.f;
        if (AMODE == 1) {
            const float* ap = (const float*)Av + (size_t)arow * 128 + lkh * 64;
            float s = 0.f, sq = 0.f;
            #pragma unroll
            for (int j = 0; j < 16; j++) {
                float4 v = *(const float4*)(ap + j * 4);
                s += v.x + v.y + v.z + v.w;
                sq += v.x*v.x + v.y*v.y + v.z*v.z + v.w*v.w;
            }
            s  += __shfl_xor_sync(0xffffffffu, s,  1);
            sq += __shfl_xor_sync(0xffffffffu, sq, 1);
            mean = s * (1.f / 128.f);
            float var = sq * (1.f / 128.f) - mean * mean;
            inv = rsqrtf(var + 1e-5f);
        }

        #pragma unroll
        for (int j = 0; j < 8; j++) {
            int c = lkh * 8 + j;
            int cp = c ^ sw;
            uint4 u;
            if (AMODE == 2) {
                const __nv_bfloat16* ap = (const __nv_bfloat16*)Av + (size_t)arow * 128 + lkh * 64;
                u = *(const uint4*)(ap + j * 8);
            } else {
                const float* ap = (const float*)Av + (size_t)arow * 128 + lkh * 64;
                float4 v0 = *(const float4*)(ap + j * 8);
                float4 v1 = *(const float4*)(ap + j * 8 + 4);
                if (AMODE == 1) {
                    int ch = lkh * 64 + j * 8;
                    float4 g0 = *(const float4*)(lnG + ch), g1 = *(const float4*)(lnG + ch + 4);
                    float4 b0 = *(const float4*)(lnB + ch), b1 = *(const float4*)(lnB + ch + 4);
                    v0.x = (v0.x - mean) * inv * g0.x + b0.x;
                    v0.y = (v0.y - mean) * inv * g0.y + b0.y;
                    v0.z = (v0.z - mean) * inv * g0.z + b0.z;
                    v0.w = (v0.w - mean) * inv * g0.w + b0.w;
                    v1.x = (v1.x - mean) * inv * g1.x + b1.x;
                    v1.y = (v1.y - mean) * inv * g1.y + b1.y;
                    v1.z = (v1.z - mean) * inv * g1.z + b1.z;
                    v1.w = (v1.w - mean) * inv * g1.w + b1.w;
                }
                u.x = pack_bf2(v0.x, v0.y); u.y = pack_bf2(v0.z, v0.w);
                u.z = pack_bf2(v1.x, v1.y); u.w = pack_bf2(v1.z, v1.w);
            }
            *(uint4*)&As[lr * 128 + cp * 8] = u;

            float4 w0 = *(const float4*)(bp + j * 8);
            float4 w1 = *(const float4*)(bp + j * 8 + 4);
            uint4 ub;
            ub.x = pack_bf2(w0.x, w0.y); ub.y = pack_bf2(w0.z, w0.w);
            ub.z = pack_bf2(w1.x, w1.y); ub.w = pack_bf2(w1.z, w1.w);
            *(uint4*)&Bs[lr * 128 + cp * 8] = ub;
        }
    }
    __syncthreads();

    int wid = tid >> 5, lane = tid & 31;
    int wm = (wid & 3) * 32;
    int wn = (wid >> 2) * 64;
    int g = lane >> 2, tg = lane & 3;

    float acc[2][8][4];
    #pragma unroll
    for (int mt = 0; mt < 2; mt++)
        #pragma unroll
        for (int nt = 0; nt < 8; nt++)
            #pragma unroll
            for (int q = 0; q < 4; q++) acc[mt][nt][q] = 0.f;

    unsigned asBase = (unsigned)__cvta_generic_to_shared(As);
    unsigned bsBase = (unsigned)__cvta_generic_to_shared(Bs);

    #pragma unroll
    for (int ks = 0; ks < 8; ks++) {
        int c0 = ks * 2;
        unsigned afr[2][4];
        #pragma unroll
        for (int mt = 0; mt < 2; mt++) {
            int row = wm + mt * 16 + (lane & 15);
            int ch = c0 + (lane >> 4);
            unsigned addr = asBase + (unsigned)((row * 128 + ((ch ^ (row & 7)) << 3)) * 2);
            ldm4(afr[mt][0], afr[mt][1], afr[mt][2], afr[mt][3], addr);
        }
        unsigned bfr[8][2];
        #pragma unroll
        for (int p = 0; p < 4; p++) {
            int row = wn + p * 16 + (lane & 7) + ((lane >> 4) << 3);
            int ch = c0 + ((lane >> 3) & 1);
            unsigned addr = bsBase + (unsigned)((row * 128 + ((ch ^ (row & 7)) << 3)) * 2);
            unsigned r0, r1, r2, r3;
            ldm4(r0, r1, r2, r3, addr);
            bfr[p * 2][0] = r0;     bfr[p * 2][1] = r1;
            bfr[p * 2 + 1][0] = r2; bfr[p * 2 + 1][1] = r3;
        }
        #pragma unroll
        for (int mt = 0; mt < 2; mt++)
            #pragma unroll
            for (int nt = 0; nt < 8; nt++)
                mma_bf16(acc[mt][nt], afr[mt], bfr[nt][0], bfr[nt][1]);
    }

    const float qsc = 0.17677669529663687f;
    #pragma unroll
    for (int mt = 0; mt < 2; mt++) {
        int r0g = rowBase + wm + mt * 16 + g;
        #pragma unroll
        for (int half = 0; half < 2; half++) {
            int r = r0g + half * 8;
            int crow = (r / cNW) * cNF + cN0 + (r % cNW);
            #pragma unroll
            for (int nt = 0; nt < 8; nt++) {
                int col = colBase + wn + nt * 8 + 2 * tg;
                float2 b2 = *(const float2*)(bias + col);
                float vx = acc[mt][nt][half * 2 + 0] + b2.x;
                float vy = acc[mt][nt][half * 2 + 1] + b2.y;
                if (Cbf) {
                    if (col < scaleLim) { vx *= qsc; vy *= qsc; }
                    *(unsigned*)(Cbf + (size_t)crow * cPitch + col) = pack_bf2(vx, vy);
                } else {
                    float* cp = C + (size_t)crow * cPitch + col;
                    if (addRes) {
                        float2 old = *(const float2*)cp;
                        vx += old.x; vy += old.y;
                    }
                    float2 o2; o2.x = vx; o2.y = vy;
                    *(float2*)cp = o2;
                }
            }
        }
    }
}

// ------------------------- bf16 mma attention (48-row blocks) ---------------
// Block = (n, e, q: rows i in [q*48, q*48+48)). 256 threads = 8 warps.
// q/k/v bf16 (q pre-scaled). proj bf16 (PQ cols pre-scaled).
// S[il][j] = QK[il][j] + Ssm[il][j]; Ssm = skew(Q@PK^T) + skew(K@PQ^T).
// Interior scatter tiles (provably in-bounds) skip all predicates.
// smem: Qs@0 (48x40 bf16), Ks@3840 (192x40; Opart overlays), PKs@19200
//   (240x40), PQs@38400 (240x40; Vt overlays), Ssm@57600 (48x196 f32 -> P),
//   stats@95232. Total 96000 B -> 2 blocks/SM.
#define ATC_SMEM 96000

template<int DSIGN>
__global__ void __launch_bounds__(256, 2) attn_tc(
    const __nv_bfloat16* __restrict__ qPtr, int qPitch, int qOff,
    const __nv_bfloat16* __restrict__ kPtr, int kPitch, int kOff,
    const __nv_bfloat16* __restrict__ vPtr, int vPitch, int vOff,
    const __nv_bfloat16* __restrict__ proj, __nv_bfloat16* __restrict__ vo, int nB)
{
    extern __shared__ char smraw[];
    __nv_bfloat16* Qs  = (__nv_bfloat16*)(smraw);
    __nv_bfloat16* Ks  = (__nv_bfloat16*)(smraw + 3840);
    __nv_bfloat16* PKs = (__nv_bfloat16*)(smraw + 19200);
    __nv_bfloat16* PQs = (__nv_bfloat16*)(smraw + 38400);
    __nv_bfloat16* Vt  = PQs;                       // overlay (after Z2 phase)
    float* Opart = (float*)(smraw + 3840);          // overlay Ks (after QK phase)
    float* Ssm  = (float*)(smraw + 57600);
    float* hmax = (float*)(smraw + 95232);          // [2][48]
    float* hsum = hmax + 96;                        // [2][48]

    int n = blockIdx.x, e = blockIdx.y;
    int i0 = blockIdx.z * 48;
    int tid = threadIdx.x;
    const int dlo = (DSIGN > 0) ? (144 - i0) : i0;

    // ---- loads: Q, K, PK, PQ — pure bf16 uint4 copies ----
    for (int idx = tid; idx < 48 * 4; idx += 256) {
        int r = idx >> 2, h = (idx & 3) * 8;
        uint4 u = *(const uint4*)(qPtr + (size_t)((i0 + r) * nB + n) * qPitch + qOff + e * 32 + h);
        *(uint4*)&Qs[r * 40 + h] = u;
    }
    for (int idx = tid; idx < 192 * 4; idx += 256) {
        int r = idx >> 2, h = (idx & 3) * 8;
        uint4 u = *(const uint4*)(kPtr + (size_t)(r * nB + n) * kPitch + kOff + e * 32 + h);
        *(uint4*)&Ks[r * 40 + h] = u;
    }
    for (int idx = tid; idx < 240 * 4; idx += 256) {
        int t = idx >> 2, h = (idx & 3) * 8;
        int d = dlo + t;
        uint4 zk = make_uint4(0, 0, 0, 0), zq = make_uint4(0, 0, 0, 0);
        if (d < 383) {
            zk = *(const uint4*)(proj + (size_t)d * 256 + 128 + e * 32 + h);
            zq = *(const uint4*)(proj + (size_t)d * 256 + e * 32 + h);
        }
        *(uint4*)&PKs[t * 40 + h] = zk;
        *(uint4*)&PQs[t * 40 + h] = zq;
    }
    __syncthreads();

    int wid = tid >> 5, lane = tid & 31;
    int g = lane >> 2, tg = lane & 3;
    unsigned qBase  = (unsigned)__cvta_generic_to_shared(Qs);
    unsigned kBase  = (unsigned)__cvta_generic_to_shared(Ks);
    unsigned pkBase = (unsigned)__cvta_generic_to_shared(PKs);
    unsigned pqBase = (unsigned)__cvta_generic_to_shared(PQs);
    unsigned vtBase = (unsigned)__cvta_generic_to_shared(Vt);
    unsigned pBase  = (unsigned)__cvta_generic_to_shared(Ssm);

    // ---- Z1 = Q @ PK^T, skew-scattered (init): 3 m-tiles x 13 n16-tiles ----
    // Interior nt in [1,11]: j indices provably in [0,192) — no predicates.
    #pragma unroll 1
    for (int u = wid; u < 39; u += 8) {
        int mt = u / 13, nt = u % 13;
        int t0m = (DSIGN > 0) ? (32 - 16 * mt) : (16 * mt);
        int tb = t0m + nt * 16;
        unsigned a[2][4], b[2][4];
        #pragma unroll
        for (int ks = 0; ks < 2; ks++) {
            unsigned addrA = qBase + (unsigned)((mt * 16 + (lane & 15)) * 80 + (ks * 2 + (lane >> 4)) * 16);
            ldm4(a[ks][0], a[ks][1], a[ks][2], a[ks][3], addrA);
            int row = tb + (lane & 7) + ((lane >> 4) << 3);
            unsigned addrB = pkBase + (unsigned)(row * 80 + (ks * 2 + ((lane >> 3) & 1)) * 16);
            ldm4(b[ks][0], b[ks][1], b[ks][2], b[ks][3], addrB);
        }
        float acc[2][4];
        #pragma unroll
        for (int h = 0; h < 2; h++) { acc[h][0] = acc[h][1] = acc[h][2] = acc[h][3] = 0.f; }
        mma_bf16(acc[0], a[0], b[0][0], b[0][1]); mma_bf16(acc[0], a[1], b[1][0], b[1][1]);
        mma_bf16(acc[1], a[0], b[0][2], b[0][3]); mma_bf16(acc[1], a[1], b[1][2], b[1][3]);

        if (nt >= 1 && nt <= 11) {
            #pragma unroll
            for (int h = 0; h < 2; h++) {
                int t = tb + h * 8 + 2 * tg;
                #pragma unroll
                for (int rr = 0; rr < 2; rr++) {
                    int il = mt * 16 + g + 8 * rr;
                    float* row = &Ssm[il * 196];
                    if (DSIGN > 0) {
                        int j0 = t + il - 47;
                        row[j0]     = acc[h][rr * 2 + 0];
                        row[j0 + 1] = acc[h][rr * 2 + 1];
                    } else {
                        int j0 = 191 + il - t;
                        row[j0]     = acc[h][rr * 2 + 0];
                        row[j0 - 1] = acc[h][rr * 2 + 1];
                    }
                }
            }
        } else {
            #pragma unroll
            for (int h = 0; h < 2; h++) {
                int t = tb + h * 8 + 2 * tg;
                #pragma unroll
                for (int rr = 0; rr < 2; rr++) {
                    int il = mt * 16 + g + 8 * rr;
                    int j0 = (DSIGN > 0) ? (t + il - 47) : (191 + il - t);
                    int j1 = (DSIGN > 0) ? (j0 + 1) : (j0 - 1);
                    if ((unsigned)j0 < 192u) Ssm[il * 196 + j0] = acc[h][rr * 2 + 0];
                    if ((unsigned)j1 < 192u) Ssm[il * 196 + j1] = acc[h][rr * 2 + 1];
                }
            }
        }
    }
    __syncthreads();

    // ---- Z2 = K @ PQ^T, skew scatter-ADD: 12 j-tiles x 4 n16-tiles ----
    // Interior nt in {1,2}: il indices provably in [0,48) — no predicates.
    #pragma unroll 1
    for (int u = wid; u < 48; u += 8) {
        int jt = u >> 2, nt = u & 3;
        int t0m = (DSIGN > 0) ? (16 * jt) : (176 - 16 * jt);
        int tb = t0m + nt * 16;
        unsigned a[2][4], b[2][4];
        #pragma unroll
        for (int ks = 0; ks < 2; ks++) {
            unsigned addrA = kBase + (unsigned)((jt * 16 + (lane & 15)) * 80 + (ks * 2 + (lane >> 4)) * 16);
            ldm4(a[ks][0], a[ks][1], a[ks][2], a[ks][3], addrA);
            int row = tb + (lane & 7) + ((lane >> 4) << 3);
            unsigned addrB = pqBase + (unsigned)(row * 80 + (ks * 2 + ((lane >> 3) & 1)) * 16);
            ldm4(b[ks][0], b[ks][1], b[ks][2], b[ks][3], addrB);
        }
        float acc[2][4];
        #pragma unroll
        for (int h = 0; h < 2; h++) { acc[h][0] = acc[h][1] = acc[h][2] = acc[h][3] = 0.f; }
        mma_bf16(acc[0], a[0], b[0][0], b[0][1]); mma_bf16(acc[0], a[1], b[1][0], b[1][1]);
        mma_bf16(acc[1], a[0], b[0][2], b[0][3]); mma_bf16(acc[1], a[1], b[1][2], b[1][3]);

        if (nt == 1 || nt == 2) {
            #pragma unroll
            for (int h = 0; h < 2; h++) {
                int t = tb + h * 8 + 2 * tg;
                #pragma unroll
                for (int rr = 0; rr < 2; rr++) {
                    int j = jt * 16 + g + 8 * rr;
                    int il0 = (DSIGN > 0) ? (47 + j - t) : (t + j - 191);
                    int il1 = (DSIGN > 0) ? (il0 - 1) : (il0 + 1);
                    Ssm[il0 * 196 + j] += acc[h][rr * 2 + 0];
                    Ssm[il1 * 196 + j] += acc[h][rr * 2 + 1];
                }
            }
        } else {
            #pragma unroll
            for (int h = 0; h < 2; h++) {
                int t = tb + h * 8 + 2 * tg;
                #pragma unroll
                for (int rr = 0; rr < 2; rr++) {
                    int j = jt * 16 + g + 8 * rr;
                    int il0 = (DSIGN > 0) ? (47 + j - t) : (t + j - 191);
                    int il1 = (DSIGN > 0) ? (il0 - 1) : (il0 + 1);
                    if ((unsigned)il0 < 48u) Ssm[il0 * 196 + j] += acc[h][rr * 2 + 0];
                    if ((unsigned)il1 < 48u) Ssm[il1 * 196 + j] += acc[h][rr * 2 + 1];
                }
            }
        }
    }
    __syncthreads();

    // ---- warps 0-5: QK^T + gather + partial max. warps 6-7: load Vt ----
    float acc[12][4];
    int mt = wid >> 1, chalf = wid & 1;
    int ilA = mt * 16 + g, ilB = ilA + 8;
    if (wid < 6) {
        #pragma unroll
        for (int nt = 0; nt < 12; nt++)
            #pragma unroll
            for (int q = 0; q < 4; q++) acc[nt][q] = 0.f;

        unsigned a[2][4];
        #pragma unroll
        for (int ks = 0; ks < 2; ks++) {
            unsigned addrA = qBase + (unsigned)((mt * 16 + (lane & 15)) * 80 + (ks * 2 + (lane >> 4)) * 16);
            ldm4(a[ks][0], a[ks][1], a[ks][2], a[ks][3], addrA);
        }
        #pragma unroll
        for (int nt16 = 0; nt16 < 6; nt16++) {
            unsigned b[2][4];
            #pragma unroll
            for (int ks = 0; ks < 2; ks++) {
                int row = chalf * 96 + nt16 * 16 + (lane & 7) + ((lane >> 4) << 3);
                unsigned addrB = kBase + (unsigned)(row * 80 + (ks * 2 + ((lane >> 3) & 1)) * 16);
                ldm4(b[ks][0], b[ks][1], b[ks][2], b[ks][3], addrB);
            }
            mma_bf16(acc[nt16 * 2],     a[0], b[0][0], b[0][1]);
            mma_bf16(acc[nt16 * 2],     a[1], b[1][0], b[1][1]);
            mma_bf16(acc[nt16 * 2 + 1], a[0], b[0][2], b[0][3]);
            mma_bf16(acc[nt16 * 2 + 1], a[1], b[1][2], b[1][3]);
        }

        #pragma unroll
        for (int nt = 0; nt < 12; nt++) {
            int j = chalf * 96 + nt * 8 + 2 * tg;
            float2 zA = *(const float2*)&Ssm[ilA * 196 + j];
            float2 zB = *(const float2*)&Ssm[ilB * 196 + j];
            acc[nt][0] += zA.x; acc[nt][1] += zA.y;
            acc[nt][2] += zB.x; acc[nt][3] += zB.y;
        }

        float mA = -1e30f, mB = -1e30f;
        #pragma unroll
        for (int nt = 0; nt < 12; nt++) {
            mA = fmaxf(mA, fmaxf(acc[nt][0], acc[nt][1]));
            mB = fmaxf(mB, fmaxf(acc[nt][2], acc[nt][3]));
        }
        mA = fmaxf(mA, __shfl_xor_sync(0xffffffffu, mA, 1));
        mA = fmaxf(mA, __shfl_xor_sync(0xffffffffu, mA, 2));
        mB = fmaxf(mB, __shfl_xor_sync(0xffffffffu, mB, 1));
        mB = fmaxf(mB, __shfl_xor_sync(0xffffffffu, mB, 2));
        if (tg == 0) {
            hmax[chalf * 48 + ilA] = mA;
            hmax[chalf * 48 + ilB] = mB;
        }
    } else {
        // transpose-load V (bf16) into the dead PQs region
        for (int idx = tid - 192; idx < 192 * 4; idx += 64) {
            int j = idx >> 2, c8 = (idx & 3) * 8;
            uint4 u = *(const uint4*)(vPtr + (size_t)(j * nB + n) * vPitch + vOff + e * 32 + c8);
            __nv_bfloat16 tmp[8];
            *(uint4*)tmp = u;
            #pragma unroll
            for (int k = 0; k < 8; k++) Vt[(c8 + k) * 200 + j] = tmp[k];
        }
    }
    __syncthreads();

    // ---- exp + partial sums ----
    if (wid < 6) {
        float mA = fmaxf(hmax[ilA], hmax[48 + ilA]);
        float mB = fmaxf(hmax[ilB], hmax[48 + ilB]);
        float sA = 0.f, sB = 0.f;
        #pragma unroll
        for (int nt = 0; nt < 12; nt++) {
            acc[nt][0] = __expf(acc[nt][0] - mA); sA += acc[nt][0];
            acc[nt][1] = __expf(acc[nt][1] - mA); sA += acc[nt][1];
            acc[nt][2] = __expf(acc[nt][2] - mB); sB += acc[nt][2];
            acc[nt][3] = __expf(acc[nt][3] - mB); sB += acc[nt][3];
        }
        sA += __shfl_xor_sync(0xffffffffu, sA, 1);
        sA += __shfl_xor_sync(0xffffffffu, sA, 2);
        sB += __shfl_xor_sync(0xffffffffu, sB, 1);
        sB += __shfl_xor_sync(0xffffffffu, sB, 2);
        if (tg == 0) {
            hsum[chalf * 48 + ilA] = sA;
            hsum[chalf * 48 + ilB] = sB;
        }
    }
    __syncthreads();

    // ---- normalize, write P (packed bf16 over Ssm) ----
    if (wid < 6) {
        float invA = 1.f / (hsum[ilA] + hsum[48 + ilA]);
        float invB = 1.f / (hsum[ilB] + hsum[48 + ilB]);
        unsigned* Pw = (unsigned*)Ssm;
        #pragma unroll
        for (int nt = 0; nt < 12; nt++) {
            int cw = chalf * 48 + nt * 4 + tg;
            Pw[ilA * 196 + cw] = pack_bf2(acc[nt][0] * invA, acc[nt][1] * invA);
            Pw[ilB * 196 + cw] = pack_bf2(acc[nt][2] * invB, acc[nt][3] * invB);
        }
    }
    __syncthreads();

    // ---- O = P @ V : 6 warps (3 m-tiles x 2 k-halves); combine via Opart ----
    float oacc[4][4];
    if (wid < 6) {
        #pragma unroll
        for (int t = 0; t < 4; t++)
            #pragma unroll
            for (int q = 0; q < 4; q++) oacc[t][q] = 0.f;

        #pragma unroll 1
        for (int s = 0; s < 6; s++) {
            int ks = chalf * 6 + s;
            unsigned a[4];
            unsigned addrA = pBase + (unsigned)((mt * 16 + (lane & 15)) * 784 + (ks * 2 + (lane >> 4)) * 16);
            ldm4(a[0], a[1], a[2], a[3], addrA);
            #pragma unroll
            for (int nb = 0; nb < 2; nb++) {
                int row = nb * 16 + (lane & 7) + ((lane >> 4) << 3);
                unsigned addrB = vtBase + (unsigned)(row * 400 + (ks * 2 + ((lane >> 3) & 1)) * 16);
                unsigned b0, b1, b2, b3;
                ldm4(b0, b1, b2, b3, addrB);
                mma_bf16(oacc[nb * 2],     a, b0, b1);
                mma_bf16(oacc[nb * 2 + 1], a, b2, b3);
            }
        }
        if (chalf == 1) {
            #pragma unroll
            for (int t = 0; t < 4; t++) {
                int c = t * 8 + 2 * tg;
                Opart[ilA * 32 + c]     = oacc[t][0];
                Opart[ilA * 32 + c + 1] = oacc[t][1];
                Opart[ilB * 32 + c]     = oacc[t][2];
                Opart[ilB * 32 + c + 1] = oacc[t][3];
            }
        }
    }
    __syncthreads();

    if (wid < 6 && chalf == 0) {
        int iA = i0 + ilA, iB = i0 + ilB;
        size_t oA = (size_t)(iA * nB + n) * 128 + e * 32;
        size_t oB = (size_t)(iB * nB + n) * 128 + e * 32;
        #pragma unroll
        for (int t = 0; t < 4; t++) {
            int c = t * 8 + 2 * tg;
            *(unsigned*)(vo + oA + c) = pack_bf2(oacc[t][0] + Opart[ilA * 32 + c],
                                                 oacc[t][1] + Opart[ilA * 32 + c + 1]);
            *(unsigned*)(vo + oB + c) = pack_bf2(oacc[t][2] + Opart[ilB * 32 + c],
                                                 oacc[t][3] + Opart[ilB * 32 + c + 1]);
        }
    }
}

// ---------------------------------------------------------------------------
extern "C" void kernel_launch(void* const* d_in, const int* in_sizes, int n_in,
                              void* d_out, int out_size)
{
    (void)in_sizes; (void)n_in; (void)out_size;
    const float* feat_left  = (const float*)d_in[0];
    const float* feat_right = (const float*)d_in[1];
    const float* pos_enc    = (const float*)d_in[2];
    const float* s_iw = (const float*)d_in[3];
    const float* s_ib = (const float*)d_in[4];
    const float* s_ow = (const float*)d_in[5];
    const float* s_ob = (const float*)d_in[6];
    const float* s_g  = (const float*)d_in[7];
    const float* s_b  = (const float*)d_in[8];
    const float* c_iw = (const float*)d_in[9];
    const float* c_ib = (const float*)d_in[10];
    const float* c_ow = (const float*)d_in[11];
    const float* c_ob = (const float*)d_in[12];
    const float* c_g1 = (const float*)d_in[13];
    const float* c_b1 = (const float*)d_in[14];
    const float* c_g2 = (const float*)d_in[15];
    const float* c_b2 = (const float*)d_in[16];

    float* feat = (float*)d_out;

    __nv_bfloat16 *qkvh, *voh, *projb;
    cudaGetSymbolAddress((void**)&qkvh, g_qkvh);
    cudaGetSymbolAddress((void**)&voh, g_voh);
    cudaGetSymbolAddress((void**)&projb, g_proj);
    __nv_bfloat16* qbh  = qkvh;                       // cross q:  (24576, 128) bf16
    __nv_bfloat16* kvbh = qkvh + 192 * 128 * 128;     // cross kv: (24576, 256) bf16

    cudaFuncSetAttribute(attn_tc<1>,  cudaFuncAttributeMaxDynamicSharedMemorySize, ATC_SMEM);
    cudaFuncSetAttribute(attn_tc<-1>, cudaFuncAttributeMaxDynamicSharedMemorySize, ATC_SMEM);
    cudaFuncSetAttribute(hgemm<0>, cudaFuncAttributeMaxDynamicSharedMemorySize, HSMEM);
    cudaFuncSetAttribute(hgemm<1>, cudaFuncAttributeMaxDynamicSharedMemorySize, HSMEM);
    cudaFuncSetAttribute(hgemm<2>, cudaFuncAttributeMaxDynamicSharedMemorySize, HSMEM);

    build_feat<<<dim3(6, 4, 256), dim3(32, 32)>>>(feat_left, feat_right, feat);
    proj_batch<<<dim3(4, 6, 8), 256>>>(pos_enc, s_iw, s_ib, c_iw, c_ib, projb);

    for (int L = 0; L < 4; L++) {
        const float* sow = s_ow + (size_t)L * 128 * 128;
        const float* sob = s_ob + (size_t)L * 128;
        const float* siw = s_iw + (size_t)L * 384 * 128;
        const float* sib = s_ib + (size_t)L * 384;
        const float* ciw = c_iw + (size_t)L * 384 * 128;
        const float* cib = c_ib + (size_t)L * 384;
        const float* cow = c_ow + (size_t)L * 128 * 128;
        const float* cob = c_ob + (size_t)L * 128;
        const __nv_bfloat16* projS = projb + (size_t)(L * 2) * 383 * 256;
        const __nv_bfloat16* projC = projb + (size_t)(L * 2 + 1) * 383 * 256;

        // ---------------- self-attention ----------------
        hgemm<1><<<dim3(3, 384), 256, HSMEM>>>(feat, 0, 256, 256,
                                               s_g + L * 128, s_b + L * 128,
                                               siw, sib, nullptr, qkvh,
                                               0, 256, 256, 384, 0, 128);
        attn_tc<1><<<dim3(256, 4, 4), 256, ATC_SMEM>>>(qkvh, 384, 0, qkvh, 384, 128,
                                                       qkvh, 384, 256, projS, voh, 256);
        hgemm<2><<<dim3(1, 384), 256, HSMEM>>>(voh, 0, 256, 256, nullptr, nullptr,
                                               sow, sob, feat, nullptr,
                                               0, 256, 256, 128, 1, 0);

        // ---------------- cross-attention ----------------
        // fr update: q = LN(fr; c_g1), kv = LN(fl; c_g1), flipped table
        hgemm<1><<<dim3(1, 192), 256, HSMEM>>>(feat, 128, 128, 256,
                                               c_g1 + L * 128, c_b1 + L * 128,
                                               ciw, cib, nullptr, qbh,
                                               0, 128, 128, 128, 0, 128);
        hgemm<1><<<dim3(2, 192), 256, HSMEM>>>(feat, 0, 128, 256,
                                               c_g1 + L * 128, c_b1 + L * 128,
                                               ciw + 128 * 128, cib + 128, nullptr, kvbh,
                                               0, 128, 128, 256, 0, 0);
        attn_tc<-1><<<dim3(128, 4, 4), 256, ATC_SMEM>>>(qbh, 128, 0, kvbh, 256, 0,
                                                        kvbh, 256, 128, projC, voh, 128);
        hgemm<2><<<dim3(1, 192), 256, HSMEM>>>(voh, 0, 128, 128, nullptr, nullptr,
                                               cow, cob, feat, nullptr,
                                               128, 128, 256, 128, 1, 0);

        // fl update: q = LN(fl; c_g1), kv = LN(updated fr; c_g2), normal table
        hgemm<1><<<dim3(2, 192), 256, HSMEM>>>(feat, 128, 128, 256,
                                               c_g2 + L * 128, c_b2 + L * 128,
                                               ciw + 128 * 128, cib + 128, nullptr, kvbh,
                                               0, 128, 128, 256, 0, 0);
        hgemm<1><<<dim3(1, 192), 256, HSMEM>>>(feat, 0, 128, 256,
                                               c_g1 + L * 128, c_b1 + L * 128,
                                               ciw, cib, nullptr, qbh,
                                               0, 128, 128, 128, 0, 128);
        attn_tc<1><<<dim3(128, 4, 4), 256, ATC_SMEM>>>(qbh, 128, 0, kvbh, 256, 0,
                                                       kvbh, 256, 128, projC, voh, 128);
        hgemm<2><<<dim3(1, 192), 256, HSMEM>>>(voh, 0, 128, 128, nullptr, nullptr,
                                               cow, cob, feat, nullptr,
                                               0, 128, 256, 128, 1, 0);
    }
}

// round 11
// speedup vs baseline: 1.3258x; 1.0792x over previous
#include <cuda_runtime.h>
#include <cuda_bf16.h>
#include <math.h>

// ---------------------------------------------------------------------------
// STTM: 4-layer transformer, w=192, C=128, NHEAD=4, hd=32
// feat (fp32, d_out): (w, n, C). Self: n in [0,256). fl: n<128, fr: n>=128.
// Activations bf16; LN fused into GEMM A-load; pos_enc projections batched
// (bf16, q-scale folded); attention: no-max softmax (clamped), 4 barriers;
// cross q+kv projections merged into one launch.
// ---------------------------------------------------------------------------

#define W_ 192
#define CC 128

// ------------------------- device scratch ---------------------------------
__device__ __nv_bfloat16 g_qkvh[W_*256*384];   // qkv (self) / qb+kvb (cross)
__device__ __nv_bfloat16 g_voh [W_*256*CC];    // attention output
__device__ __nv_bfloat16 g_proj[8*383*256];    // per (layer, self|cross) proj, bf16

// ------------------------- helpers -----------------------------------------
__device__ __forceinline__ unsigned pack_bf2(float x, float y) {
    __nv_bfloat162 h = __float22bfloat162_rn(make_float2(x, y));
    return *(unsigned*)&h;
}

__device__ __forceinline__ void ldm4(unsigned& r0, unsigned& r1, unsigned& r2, unsigned& r3,
                                     unsigned addr) {
    asm volatile("ldmatrix.sync.aligned.m8n8.x4.shared.b16 {%0,%1,%2,%3},[%4];"
                 : "=r"(r0), "=r"(r1), "=r"(r2), "=r"(r3) : "r"(addr));
}

__device__ __forceinline__ void mma_bf16(float* d, const unsigned* a, unsigned b0, unsigned b1) {
    asm volatile(
        "mma.sync.aligned.m16n8k16.row.col.f32.bf16.bf16.f32 "
        "{%0,%1,%2,%3},{%4,%5,%6,%7},{%8,%9},{%0,%1,%2,%3};"
        : "+f"(d[0]), "+f"(d[1]), "+f"(d[2]), "+f"(d[3])
        : "r"(a[0]), "r"(a[1]), "r"(a[2]), "r"(a[3]), "r"(b0), "r"(b1));
}

// ------------------------- build feat from inputs -------------------------
__global__ void build_feat(const float* __restrict__ L, const float* __restrict__ R,
                           float* __restrict__ feat)
{
    __shared__ float tile[32][33];
    int n = blockIdx.z;
    const float* src = (n < 128) ? L : R;
    int nn = n & 127;
    int h = nn >> 1, b = nn & 1;
    int i = blockIdx.x * 32 + threadIdx.x;
    int c = blockIdx.y * 32 + threadIdx.y;
    tile[threadIdx.y][threadIdx.x] = src[(((size_t)b * 128 + c) * 64 + h) * 192 + i];
    __syncthreads();
    int i2 = blockIdx.x * 32 + threadIdx.y;
    int c2 = blockIdx.y * 32 + threadIdx.x;
    feat[((size_t)i2 * 256 + n) * 128 + c2] = tile[threadIdx.x][threadIdx.y];
}

// ------------------------- batched pos_enc projection ----------------------
__global__ void proj_batch(const float* __restrict__ pos_enc,
                           const float* __restrict__ s_iw, const float* __restrict__ s_ib,
                           const float* __restrict__ c_iw, const float* __restrict__ c_ib,
                           __nv_bfloat16* __restrict__ out)
{
    int z = blockIdx.z, layer = z >> 1;
    const float* B    = ((z & 1) ? c_iw : s_iw) + (size_t)layer * 384 * 128;
    const float* bias = ((z & 1) ? c_ib : s_ib) + layer * 384;
    __nv_bfloat16* C = out + (size_t)z * 383 * 256;
    const int M = 383, N = 256;
    const float qsc = 0.17677669529663687f;

    __shared__ float As[16][68];
    __shared__ float Bs[16][68];
    int tid = threadIdx.x;
    int tx = tid & 15, ty = tid >> 4;
    int rowBase = blockIdx.y * 64;
    int colBase = blockIdx.x * 64;

    float acc[4][4];
    #pragma unroll
    for (int i = 0; i < 4; i++)
        #pragma unroll
        for (int j = 0; j < 4; j++) acc[i][j] = 0.f;

    int lr = tid >> 2;
    int lc = (tid & 3) * 4;
    int ar = rowBase + lr;
    const float* aRowPtr = (ar < M) ? (pos_enc + (size_t)ar * 128) : nullptr;
    int bc = colBase + lr;
    const float* bRowPtr = (bc < N) ? (B + (size_t)bc * 128) : nullptr;

    for (int kt = 0; kt < 8; kt++) {
        int k0 = kt * 16 + lc;
        float4 av = aRowPtr ? *(const float4*)(aRowPtr + k0) : make_float4(0, 0, 0, 0);
        float4 bv = bRowPtr ? *(const float4*)(bRowPtr + k0) : make_float4(0, 0, 0, 0);
        As[lc + 0][lr] = av.x; As[lc + 1][lr] = av.y; As[lc + 2][lr] = av.z; As[lc + 3][lr] = av.w;
        Bs[lc + 0][lr] = bv.x; Bs[lc + 1][lr] = bv.y; Bs[lc + 2][lr] = bv.z; Bs[lc + 3][lr] = bv.w;
        __syncthreads();
        #pragma unroll
        for (int k = 0; k < 16; k++) {
            float a0 = As[k][ty * 4 + 0], a1 = As[k][ty * 4 + 1];
            float a2 = As[k][ty * 4 + 2], a3 = As[k][ty * 4 + 3];
            float b0 = Bs[k][tx * 4 + 0], b1 = Bs[k][tx * 4 + 1];
            float b2 = Bs[k][tx * 4 + 2], b3 = Bs[k][tx * 4 + 3];
            acc[0][0] = fmaf(a0, b0, acc[0][0]); acc[0][1] = fmaf(a0, b1, acc[0][1]);
            acc[0][2] = fmaf(a0, b2, acc[0][2]); acc[0][3] = fmaf(a0, b3, acc[0][3]);
            acc[1][0] = fmaf(a1, b0, acc[1][0]); acc[1][1] = fmaf(a1, b1, acc[1][1]);
            acc[1][2] = fmaf(a1, b2, acc[1][2]); acc[1][3] = fmaf(a1, b3, acc[1][3]);
            acc[2][0] = fmaf(a2, b0, acc[2][0]); acc[2][1] = fmaf(a2, b1, acc[2][1]);
            acc[2][2] = fmaf(a2, b2, acc[2][2]); acc[2][3] = fmaf(a2, b3, acc[2][3]);
            acc[3][0] = fmaf(a3, b0, acc[3][0]); acc[3][1] = fmaf(a3, b1, acc[3][1]);
            acc[3][2] = fmaf(a3, b2, acc[3][2]); acc[3][3] = fmaf(a3, b3, acc[3][3]);
        }
        __syncthreads();
    }

    #pragma unroll
    for (int mi = 0; mi < 4; mi++) {
        int r = rowBase + ty * 4 + mi;
        if (r >= M) continue;
        __nv_bfloat16* cRow = C + (size_t)r * 256;
        #pragma unroll
        for (int ni = 0; ni < 4; ni++) {
            int col = colBase + tx * 4 + ni;
            float v = acc[mi][ni] + bias[col];
            if (col < 128) v *= qsc;
            cRow[col] = __float2bfloat16(v);
        }
    }
}

// ------------------------- bf16 tensor-core GEMM core ----------------------
#define HSMEM (2 * 128 * 128 * 2)

// Shared device body: LN(optional) A-load + mma + epilogue.
template<int AMODE>
__device__ __forceinline__ void hgemm_body(
    const void* __restrict__ Av, int aN0, int aNW, int aNF,
    const float* __restrict__ lnG, const float* __restrict__ lnB,
    const float* __restrict__ B, const float* __restrict__ bias,
    float* __restrict__ C, __nv_bfloat16* __restrict__ Cbf,
    int cN0, int cNW, int cNF, int cPitch,
    int addRes, int scaleLim, int rowBase, int colBase,
    __nv_bfloat16* As, __nv_bfloat16* Bs)
{
    int tid = threadIdx.x;
    int lr = tid >> 1, lkh = tid & 1;
    {
        int ar = rowBase + lr;
        int arow = (ar / aNW) * aNF + aN0 + (ar % aNW);
        const float* bp = B + (size_t)(colBase + lr) * 128 + lkh * 64;
        int sw = lr & 7;

        float mean = 0.f, inv = 1.f;
        if (AMODE == 1) {
            const float* ap = (const float*)Av + (size_t)arow * 128 + lkh * 64;
            float s = 0.f, sq = 0.f;
            #pragma unroll
            for (int j = 0; j < 16; j++) {
                float4 v = *(const float4*)(ap + j * 4);
                s += v.x + v.y + v.z + v.w;
                sq += v.x*v.x + v.y*v.y + v.z*v.z + v.w*v.w;
            }
            s  += __shfl_xor_sync(0xffffffffu, s,  1);
            sq += __shfl_xor_sync(0xffffffffu, sq, 1);
            mean = s * (1.f / 128.f);
            float var = sq * (1.f / 128.f) - mean * mean;
            inv = rsqrtf(var + 1e-5f);
        }

        #pragma unroll
        for (int j = 0; j < 8; j++) {
            int c = lkh * 8 + j;
            int cp = c ^ sw;
            uint4 u;
            if (AMODE == 2) {
                const __nv_bfloat16* ap = (const __nv_bfloat16*)Av + (size_t)arow * 128 + lkh * 64;
                u = *(const uint4*)(ap + j * 8);
            } else {
                const float* ap = (const float*)Av + (size_t)arow * 128 + lkh * 64;
                float4 v0 = *(const float4*)(ap + j * 8);
                float4 v1 = *(const float4*)(ap + j * 8 + 4);
                if (AMODE == 1) {
                    int ch = lkh * 64 + j * 8;
                    float4 g0 = *(const float4*)(lnG + ch), g1 = *(const float4*)(lnG + ch + 4);
                    float4 b0 = *(const float4*)(lnB + ch), b1 = *(const float4*)(lnB + ch + 4);
                    v0.x = (v0.x - mean) * inv * g0.x + b0.x;
                    v0.y = (v0.y - mean) * inv * g0.y + b0.y;
                    v0.z = (v0.z - mean) * inv * g0.z + b0.z;
                    v0.w = (v0.w - mean) * inv * g0.w + b0.w;
                    v1.x = (v1.x - mean) * inv * g1.x + b1.x;
                    v1.y = (v1.y - mean) * inv * g1.y + b1.y;
                    v1.z = (v1.z - mean) * inv * g1.z + b1.z;
                    v1.w = (v1.w - mean) * inv * g1.w + b1.w;
                }
                u.x = pack_bf2(v0.x, v0.y); u.y = pack_bf2(v0.z, v0.w);
                u.z = pack_bf2(v1.x, v1.y); u.w = pack_bf2(v1.z, v1.w);
            }
            *(uint4*)&As[lr * 128 + cp * 8] = u;

            float4 w0 = *(const float4*)(bp + j * 8);
            float4 w1 = *(const float4*)(bp + j * 8 + 4);
            uint4 ub;
            ub.x = pack_bf2(w0.x, w0.y); ub.y = pack_bf2(w0.z, w0.w);
            ub.z = pack_bf2(w1.x, w1.y); ub.w = pack_bf2(w1.z, w1.w);
            *(uint4*)&Bs[lr * 128 + cp * 8] = ub;
        }
    }
    __syncthreads();

    int wid = tid >> 5, lane = tid & 31;
    int wm = (wid & 3) * 32;
    int wn = (wid >> 2) * 64;
    int g = lane >> 2, tg = lane & 3;

    float acc[2][8][4];
    #pragma unroll
    for (int mt = 0; mt < 2; mt++)
        #pragma unroll
        for (int nt = 0; nt < 8; nt++)
            #pragma unroll
            for (int q = 0; q < 4; q++) acc[mt][nt][q] = 0.f;

    unsigned asBase = (unsigned)__cvta_generic_to_shared(As);
    unsigned bsBase = (unsigned)__cvta_generic_to_shared(Bs);

    #pragma unroll
    for (int ks = 0; ks < 8; ks++) {
        int c0 = ks * 2;
        unsigned afr[2][4];
        #pragma unroll
        for (int mt = 0; mt < 2; mt++) {
            int row = wm + mt * 16 + (lane & 15);
            int ch = c0 + (lane >> 4);
            unsigned addr = asBase + (unsigned)((row * 128 + ((ch ^ (row & 7)) << 3)) * 2);
            ldm4(afr[mt][0], afr[mt][1], afr[mt][2], afr[mt][3], addr);
        }
        unsigned bfr[8][2];
        #pragma unroll
        for (int p = 0; p < 4; p++) {
            int row = wn + p * 16 + (lane & 7) + ((lane >> 4) << 3);
            int ch = c0 + ((lane >> 3) & 1);
            unsigned addr = bsBase + (unsigned)((row * 128 + ((ch ^ (row & 7)) << 3)) * 2);
            unsigned r0, r1, r2, r3;
            ldm4(r0, r1, r2, r3, addr);
            bfr[p * 2][0] = r0;     bfr[p * 2][1] = r1;
            bfr[p * 2 + 1][0] = r2; bfr[p * 2 + 1][1] = r3;
        }
        #pragma unroll
        for (int mt = 0; mt < 2; mt++)
            #pragma unroll
            for (int nt = 0; nt < 8; nt++)
                mma_bf16(acc[mt][nt], afr[mt], bfr[nt][0], bfr[nt][1]);
    }

    const float qsc = 0.17677669529663687f;
    #pragma unroll
    for (int mt = 0; mt < 2; mt++) {
        int r0g = rowBase + wm + mt * 16 + g;
        #pragma unroll
        for (int half = 0; half < 2; half++) {
            int r = r0g + half * 8;
            int crow = (r / cNW) * cNF + cN0 + (r % cNW);
            #pragma unroll
            for (int nt = 0; nt < 8; nt++) {
                int col = colBase + wn + nt * 8 + 2 * tg;
                float2 b2 = *(const float2*)(bias + col);
                float vx = acc[mt][nt][half * 2 + 0] + b2.x;
                float vy = acc[mt][nt][half * 2 + 1] + b2.y;
                if (Cbf) {
                    if (col < scaleLim) { vx *= qsc; vy *= qsc; }
                    *(unsigned*)(Cbf + (size_t)crow * cPitch + col) = pack_bf2(vx, vy);
                } else {
                    float* cp = C + (size_t)crow * cPitch + col;
                    if (addRes) {
                        float2 old = *(const float2*)cp;
                        vx += old.x; vy += old.y;
                    }
                    float2 o2; o2.x = vx; o2.y = vy;
                    *(float2*)cp = o2;
                }
            }
        }
    }
}

template<int AMODE>
__global__ void __launch_bounds__(256) hgemm(
    const void* __restrict__ Av, int aN0, int aNW, int aNF,
    const float* __restrict__ lnG, const float* __restrict__ lnB,
    const float* __restrict__ B, const float* __restrict__ bias,
    float* __restrict__ C, __nv_bfloat16* __restrict__ Cbf,
    int cN0, int cNW, int cNF, int cPitch,
    int addRes, int scaleLim)
{
    extern __shared__ __nv_bfloat16 hsm[];
    hgemm_body<AMODE>(Av, aN0, aNW, aNF, lnG, lnB, B, bias, C, Cbf,
                      cN0, cNW, cNF, cPitch, addRes, scaleLim,
                      blockIdx.y * 128, blockIdx.x * 128, hsm, hsm + 128*128);
}

// Merged cross projections: x=0 -> q (A window qN0, LN q params, out qbh),
// x in {1,2} -> kv (A window kN0, LN kv params, out kvbh).
__global__ void __launch_bounds__(256) hgemm_cross(
    const float* __restrict__ feat, int qN0, int kN0,
    const float* __restrict__ lnGq, const float* __restrict__ lnBq,
    const float* __restrict__ lnGk, const float* __restrict__ lnBk,
    const float* __restrict__ ciw, const float* __restrict__ cib,
    __nv_bfloat16* __restrict__ outQ, __nv_bfloat16* __restrict__ outKV)
{
    extern __shared__ __nv_bfloat16 hsm[];
    int x = blockIdx.x;
    if (x == 0) {
        hgemm_body<1>(feat, qN0, 128, 256, lnGq, lnBq, ciw, cib,
                      nullptr, outQ, 0, 128, 128, 128, 0, 128,
                      blockIdx.y * 128, 0, hsm, hsm + 128*128);
    } else {
        hgemm_body<1>(feat, kN0, 128, 256, lnGk, lnBk, ciw + 128 * 128, cib + 128,
                      nullptr, outKV, 0, 128, 128, 256, 0, 0,
                      blockIdx.y * 128, (x - 1) * 128, hsm, hsm + 128*128);
    }
}

// ------------------------- bf16 mma attention (48-row blocks) ---------------
// No-max softmax (scores provably small; exp clamped at 70): 4 barriers.
// smem: Qs@0, Ks@3840 (Opart overlays), PKs@19200, PQs@38400 (Vt overlays),
//   Ssm@57600 (48x196 f32 -> P), hsum@95232 (2x48 f32). 95616 B -> 2 blocks/SM.
#define ATC_SMEM 95616

template<int DSIGN>
__global__ void __launch_bounds__(256, 2) attn_tc(
    const __nv_bfloat16* __restrict__ qPtr, int qPitch, int qOff,
    const __nv_bfloat16* __restrict__ kPtr, int kPitch, int kOff,
    const __nv_bfloat16* __restrict__ vPtr, int vPitch, int vOff,
    const __nv_bfloat16* __restrict__ proj, __nv_bfloat16* __restrict__ vo, int nB)
{
    extern __shared__ char smraw[];
    __nv_bfloat16* Qs  = (__nv_bfloat16*)(smraw);
    __nv_bfloat16* Ks  = (__nv_bfloat16*)(smraw + 3840);
    __nv_bfloat16* PKs = (__nv_bfloat16*)(smraw + 19200);
    __nv_bfloat16* PQs = (__nv_bfloat16*)(smraw + 38400);
    __nv_bfloat16* Vt  = PQs;                       // overlay (after Z2 phase)
    float* Opart = (float*)(smraw + 3840);          // overlay Ks (after QK phase)
    float* Ssm  = (float*)(smraw + 57600);
    float* hsum = (float*)(smraw + 95232);          // [2][48]

    int n = blockIdx.x, e = blockIdx.y;
    int i0 = blockIdx.z * 48;
    int tid = threadIdx.x;
    const int dlo = (DSIGN > 0) ? (144 - i0) : i0;

    // ---- loads: Q, K, PK, PQ — pure bf16 uint4 copies ----
    for (int idx = tid; idx < 48 * 4; idx += 256) {
        int r = idx >> 2, h = (idx & 3) * 8;
        uint4 u = *(const uint4*)(qPtr + (size_t)((i0 + r) * nB + n) * qPitch + qOff + e * 32 + h);
        *(uint4*)&Qs[r * 40 + h] = u;
    }
    for (int idx = tid; idx < 192 * 4; idx += 256) {
        int r = idx >> 2, h = (idx & 3) * 8;
        uint4 u = *(const uint4*)(kPtr + (size_t)(r * nB + n) * kPitch + kOff + e * 32 + h);
        *(uint4*)&Ks[r * 40 + h] = u;
    }
    for (int idx = tid; idx < 240 * 4; idx += 256) {
        int t = idx >> 2, h = (idx & 3) * 8;
        int d = dlo + t;
        uint4 zk = make_uint4(0, 0, 0, 0), zq = make_uint4(0, 0, 0, 0);
        if (d < 383) {
            zk = *(const uint4*)(proj + (size_t)d * 256 + 128 + e * 32 + h);
            zq = *(const uint4*)(proj + (size_t)d * 256 + e * 32 + h);
        }
        *(uint4*)&PKs[t * 40 + h] = zk;
        *(uint4*)&PQs[t * 40 + h] = zq;
    }
    __syncthreads();

    int wid = tid >> 5, lane = tid & 31;
    int g = lane >> 2, tg = lane & 3;
    unsigned qBase  = (unsigned)__cvta_generic_to_shared(Qs);
    unsigned kBase  = (unsigned)__cvta_generic_to_shared(Ks);
    unsigned pkBase = (unsigned)__cvta_generic_to_shared(PKs);
    unsigned pqBase = (unsigned)__cvta_generic_to_shared(PQs);
    unsigned vtBase = (unsigned)__cvta_generic_to_shared(Vt);
    unsigned pBase  = (unsigned)__cvta_generic_to_shared(Ssm);

    // ---- Z1 = Q @ PK^T, skew-scattered (init): 3 m-tiles x 13 n16-tiles ----
    #pragma unroll 1
    for (int u = wid; u < 39; u += 8) {
        int mt = u / 13, nt = u % 13;
        int t0m = (DSIGN > 0) ? (32 - 16 * mt) : (16 * mt);
        int tb = t0m + nt * 16;
        unsigned a[2][4], b[2][4];
        #pragma unroll
        for (int ks = 0; ks < 2; ks++) {
            unsigned addrA = qBase + (unsigned)((mt * 16 + (lane & 15)) * 80 + (ks * 2 + (lane >> 4)) * 16);
            ldm4(a[ks][0], a[ks][1], a[ks][2], a[ks][3], addrA);
            int row = tb + (lane & 7) + ((lane >> 4) << 3);
            unsigned addrB = pkBase + (unsigned)(row * 80 + (ks * 2 + ((lane >> 3) & 1)) * 16);
            ldm4(b[ks][0], b[ks][1], b[ks][2], b[ks][3], addrB);
        }
        float acc[2][4];
        #pragma unroll
        for (int h = 0; h < 2; h++) { acc[h][0] = acc[h][1] = acc[h][2] = acc[h][3] = 0.f; }
        mma_bf16(acc[0], a[0], b[0][0], b[0][1]); mma_bf16(acc[0], a[1], b[1][0], b[1][1]);
        mma_bf16(acc[1], a[0], b[0][2], b[0][3]); mma_bf16(acc[1], a[1], b[1][2], b[1][3]);

        if (nt >= 1 && nt <= 11) {
            #pragma unroll
            for (int h = 0; h < 2; h++) {
                int t = tb + h * 8 + 2 * tg;
                #pragma unroll
                for (int rr = 0; rr < 2; rr++) {
                    int il = mt * 16 + g + 8 * rr;
                    float* row = &Ssm[il * 196];
                    if (DSIGN > 0) {
                        int j0 = t + il - 47;
                        row[j0]     = acc[h][rr * 2 + 0];
                        row[j0 + 1] = acc[h][rr * 2 + 1];
                    } else {
                        int j0 = 191 + il - t;
                        row[j0]     = acc[h][rr * 2 + 0];
                        row[j0 - 1] = acc[h][rr * 2 + 1];
                    }
                }
            }
        } else {
            #pragma unroll
            for (int h = 0; h < 2; h++) {
                int t = tb + h * 8 + 2 * tg;
                #pragma unroll
                for (int rr = 0; rr < 2; rr++) {
                    int il = mt * 16 + g + 8 * rr;
                    int j0 = (DSIGN > 0) ? (t + il - 47) : (191 + il - t);
                    int j1 = (DSIGN > 0) ? (j0 + 1) : (j0 - 1);
                    if ((unsigned)j0 < 192u) Ssm[il * 196 + j0] = acc[h][rr * 2 + 0];
                    if ((unsigned)j1 < 192u) Ssm[il * 196 + j1] = acc[h][rr * 2 + 1];
                }
            }
        }
    }
    __syncthreads();

    // ---- Z2 = K @ PQ^T, skew scatter-ADD: 12 j-tiles x 4 n16-tiles ----
    #pragma unroll 1
    for (int u = wid; u < 48; u += 8) {
        int jt = u >> 2, nt = u & 3;
        int t0m = (DSIGN > 0) ? (16 * jt) : (176 - 16 * jt);
        int tb = t0m + nt * 16;
        unsigned a[2][4], b[2][4];
        #pragma unroll
        for (int ks = 0; ks < 2; ks++) {
            unsigned addrA = kBase + (unsigned)((jt * 16 + (lane & 15)) * 80 + (ks * 2 + (lane >> 4)) * 16);
            ldm4(a[ks][0], a[ks][1], a[ks][2], a[ks][3], addrA);
            int row = tb + (lane & 7) + ((lane >> 4) << 3);
            unsigned addrB = pqBase + (unsigned)(row * 80 + (ks * 2 + ((lane >> 3) & 1)) * 16);
            ldm4(b[ks][0], b[ks][1], b[ks][2], b[ks][3], addrB);
        }
        float acc[2][4];
        #pragma unroll
        for (int h = 0; h < 2; h++) { acc[h][0] = acc[h][1] = acc[h][2] = acc[h][3] = 0.f; }
        mma_bf16(acc[0], a[0], b[0][0], b[0][1]); mma_bf16(acc[0], a[1], b[1][0], b[1][1]);
        mma_bf16(acc[1], a[0], b[0][2], b[0][3]); mma_bf16(acc[1], a[1], b[1][2], b[1][3]);

        if (nt == 1 || nt == 2) {
            #pragma unroll
            for (int h = 0; h < 2; h++) {
                int t = tb + h * 8 + 2 * tg;
                #pragma unroll
                for (int rr = 0; rr < 2; rr++) {
                    int j = jt * 16 + g + 8 * rr;
                    int il0 = (DSIGN > 0) ? (47 + j - t) : (t + j - 191);
                    int il1 = (DSIGN > 0) ? (il0 - 1) : (il0 + 1);
                    Ssm[il0 * 196 + j] += acc[h][rr * 2 + 0];
                    Ssm[il1 * 196 + j] += acc[h][rr * 2 + 1];
                }
            }
        } else {
            #pragma unroll
            for (int h = 0; h < 2; h++) {
                int t = tb + h * 8 + 2 * tg;
                #pragma unroll
                for (int rr = 0; rr < 2; rr++) {
                    int j = jt * 16 + g + 8 * rr;
                    int il0 = (DSIGN > 0) ? (47 + j - t) : (t + j - 191);
                    int il1 = (DSIGN > 0) ? (il0 - 1) : (il0 + 1);
                    if ((unsigned)il0 < 48u) Ssm[il0 * 196 + j] += acc[h][rr * 2 + 0];
                    if ((unsigned)il1 < 48u) Ssm[il1 * 196 + j] += acc[h][rr * 2 + 1];
                }
            }
        }
    }
    __syncthreads();

    // ---- warps 0-5: QK^T + gather + exp + partial sums. warps 6-7: Vt ----
    float acc[12][4];
    int mt = wid >> 1, chalf = wid & 1;
    int ilA = mt * 16 + g, ilB = ilA + 8;
    if (wid < 6) {
        #pragma unroll
        for (int nt = 0; nt < 12; nt++)
            #pragma unroll
            for (int q = 0; q < 4; q++) acc[nt][q] = 0.f;

        unsigned a[2][4];
        #pragma unroll
        for (int ks = 0; ks < 2; ks++) {
            unsigned addrA = qBase + (unsigned)((mt * 16 + (lane & 15)) * 80 + (ks * 2 + (lane >> 4)) * 16);
            ldm4(a[ks][0], a[ks][1], a[ks][2], a[ks][3], addrA);
        }
        #pragma unroll
        for (int nt16 = 0; nt16 < 6; nt16++) {
            unsigned b[2][4];
            #pragma unroll
            for (int ks = 0; ks < 2; ks++) {
                int row = chalf * 96 + nt16 * 16 + (lane & 7) + ((lane >> 4) << 3);
                unsigned addrB = kBase + (unsigned)(row * 80 + (ks * 2 + ((lane >> 3) & 1)) * 16);
                ldm4(b[ks][0], b[ks][1], b[ks][2], b[ks][3], addrB);
            }
            mma_bf16(acc[nt16 * 2],     a[0], b[0][0], b[0][1]);
            mma_bf16(acc[nt16 * 2],     a[1], b[1][0], b[1][1]);
            mma_bf16(acc[nt16 * 2 + 1], a[0], b[0][2], b[0][3]);
            mma_bf16(acc[nt16 * 2 + 1], a[1], b[1][2], b[1][3]);
        }

        // gather prior + exp (no max shift; clamp guards overflow) + sums
        float sA = 0.f, sB = 0.f;
        #pragma unroll
        for (int nt = 0; nt < 12; nt++) {
            int j = chalf * 96 + nt * 8 + 2 * tg;
            float2 zA = *(const float2*)&Ssm[ilA * 196 + j];
            float2 zB = *(const float2*)&Ssm[ilB * 196 + j];
            acc[nt][0] = __expf(fminf(acc[nt][0] + zA.x, 70.f)); sA += acc[nt][0];
            acc[nt][1] = __expf(fminf(acc[nt][1] + zA.y, 70.f)); sA += acc[nt][1];
            acc[nt][2] = __expf(fminf(acc[nt][2] + zB.x, 70.f)); sB += acc[nt][2];
            acc[nt][3] = __expf(fminf(acc[nt][3] + zB.y, 70.f)); sB += acc[nt][3];
        }
        sA += __shfl_xor_sync(0xffffffffu, sA, 1);
        sA += __shfl_xor_sync(0xffffffffu, sA, 2);
        sB += __shfl_xor_sync(0xffffffffu, sB, 1);
        sB += __shfl_xor_sync(0xffffffffu, sB, 2);
        if (tg == 0) {
            hsum[chalf * 48 + ilA] = sA;
            hsum[chalf * 48 + ilB] = sB;
        }
    } else {
        // transpose-load V (bf16) into the dead PQs region
        for (int idx = tid - 192; idx < 192 * 4; idx += 64) {
            int j = idx >> 2, c8 = (idx & 3) * 8;
            uint4 u = *(const uint4*)(vPtr + (size_t)(j * nB + n) * vPitch + vOff + e * 32 + c8);
            __nv_bfloat16 tmp[8];
            *(uint4*)tmp = u;
            #pragma unroll
            for (int k = 0; k < 8; k++) Vt[(c8 + k) * 200 + j] = tmp[k];
        }
    }
    __syncthreads();

    // ---- normalize, write P (packed bf16 over Ssm) ----
    if (wid < 6) {
        float invA = 1.f / (hsum[ilA] + hsum[48 + ilA]);
        float invB = 1.f / (hsum[ilB] + hsum[48 + ilB]);
        unsigned* Pw = (unsigned*)Ssm;
        #pragma unroll
        for (int nt = 0; nt < 12; nt++) {
            int cw = chalf * 48 + nt * 4 + tg;
            Pw[ilA * 196 + cw] = pack_bf2(acc[nt][0] * invA, acc[nt][1] * invA);
            Pw[ilB * 196 + cw] = pack_bf2(acc[nt][2] * invB, acc[nt][3] * invB);
        }
    }
    __syncthreads();

    // ---- O = P @ V : 6 warps (3 m-tiles x 2 k-halves); combine via Opart ----
    float oacc[4][4];
    if (wid < 6) {
        #pragma unroll
        for (int t = 0; t < 4; t++)
            #pragma unroll
            for (int q = 0; q < 4; q++) oacc[t][q] = 0.f;

        #pragma unroll 1
        for (int s = 0; s < 6; s++) {
            int ks = chalf * 6 + s;
            unsigned a[4];
            unsigned addrA = pBase + (unsigned)((mt * 16 + (lane & 15)) * 784 + (ks * 2 + (lane >> 4)) * 16);
            ldm4(a[0], a[1], a[2], a[3], addrA);
            #pragma unroll
            for (int nb = 0; nb < 2; nb++) {
                int row = nb * 16 + (lane & 7) + ((lane >> 4) << 3);
                unsigned addrB = vtBase + (unsigned)(row * 400 + (ks * 2 + ((lane >> 3) & 1)) * 16);
                unsigned b0, b1, b2, b3;
                ldm4(b0, b1, b2, b3, addrB);
                mma_bf16(oacc[nb * 2],     a, b0, b1);
                mma_bf16(oacc[nb * 2 + 1], a, b2, b3);
            }
        }
        if (chalf == 1) {
            #pragma unroll
            for (int t = 0; t < 4; t++) {
                int c = t * 8 + 2 * tg;
                Opart[ilA * 32 + c]     = oacc[t][0];
                Opart[ilA * 32 + c + 1] = oacc[t][1];
                Opart[ilB * 32 + c]     = oacc[t][2];
                Opart[ilB * 32 + c + 1] = oacc[t][3];
            }
        }
    }
    __syncthreads();

    if (wid < 6 && chalf == 0) {
        int iA = i0 + ilA, iB = i0 + ilB;
        size_t oA = (size_t)(iA * nB + n) * 128 + e * 32;
        size_t oB = (size_t)(iB * nB + n) * 128 + e * 32;
        #pragma unroll
        for (int t = 0; t < 4; t++) {
            int c = t * 8 + 2 * tg;
            *(unsigned*)(vo + oA + c) = pack_bf2(oacc[t][0] + Opart[ilA * 32 + c],
                                                 oacc[t][1] + Opart[ilA * 32 + c + 1]);
            *(unsigned*)(vo + oB + c) = pack_bf2(oacc[t][2] + Opart[ilB * 32 + c],
                                                 oacc[t][3] + Opart[ilB * 32 + c + 1]);
        }
    }
}

// ---------------------------------------------------------------------------
extern "C" void kernel_launch(void* const* d_in, const int* in_sizes, int n_in,
                              void* d_out, int out_size)
{
    (void)in_sizes; (void)n_in; (void)out_size;
    const float* feat_left  = (const float*)d_in[0];
    const float* feat_right = (const float*)d_in[1];
    const float* pos_enc    = (const float*)d_in[2];
    const float* s_iw = (const float*)d_in[3];
    const float* s_ib = (const float*)d_in[4];
    const float* s_ow = (const float*)d_in[5];
    const float* s_ob = (const float*)d_in[6];
    const float* s_g  = (const float*)d_in[7];
    const float* s_b  = (const float*)d_in[8];
    const float* c_iw = (const float*)d_in[9];
    const float* c_ib = (const float*)d_in[10];
    const float* c_ow = (const float*)d_in[11];
    const float* c_ob = (const float*)d_in[12];
    const float* c_g1 = (const float*)d_in[13];
    const float* c_b1 = (const float*)d_in[14];
    const float* c_g2 = (const float*)d_in[15];
    const float* c_b2 = (const float*)d_in[16];

    float* feat = (float*)d_out;

    __nv_bfloat16 *qkvh, *voh, *projb;
    cudaGetSymbolAddress((void**)&qkvh, g_qkvh);
    cudaGetSymbolAddress((void**)&voh, g_voh);
    cudaGetSymbolAddress((void**)&projb, g_proj);
    __nv_bfloat16* qbh  = qkvh;
    __nv_bfloat16* kvbh = qkvh + 192 * 128 * 128;

    cudaFuncSetAttribute(attn_tc<1>,  cudaFuncAttributeMaxDynamicSharedMemorySize, ATC_SMEM);
    cudaFuncSetAttribute(attn_tc<-1>, cudaFuncAttributeMaxDynamicSharedMemorySize, ATC_SMEM);
    cudaFuncSetAttribute(hgemm<1>, cudaFuncAttributeMaxDynamicSharedMemorySize, HSMEM);
    cudaFuncSetAttribute(hgemm<2>, cudaFuncAttributeMaxDynamicSharedMemorySize, HSMEM);
    cudaFuncSetAttribute(hgemm_cross, cudaFuncAttributeMaxDynamicSharedMemorySize, HSMEM);

    build_feat<<<dim3(6, 4, 256), dim3(32, 32)>>>(feat_left, feat_right, feat);
    proj_batch<<<dim3(4, 6, 8), 256>>>(pos_enc, s_iw, s_ib, c_iw, c_ib, projb);

    for (int L = 0; L < 4; L++) {
        const float* sow = s_ow + (size_t)L * 128 * 128;
        const float* sob = s_ob + (size_t)L * 128;
        const float* siw = s_iw + (size_t)L * 384 * 128;
        const float* sib = s_ib + (size_t)L * 384;
        const float* ciw = c_iw + (size_t)L * 384 * 128;
        const float* cib = c_ib + (size_t)L * 384;
        const float* cow = c_ow + (size_t)L * 128 * 128;
        const float* cob = c_ob + (size_t)L * 128;
        const __nv_bfloat16* projS = projb + (size_t)(L * 2) * 383 * 256;
        const __nv_bfloat16* projC = projb + (size_t)(L * 2 + 1) * 383 * 256;

        // ---------------- self-attention ----------------
        hgemm<1><<<dim3(3, 384), 256, HSMEM>>>(feat, 0, 256, 256,
                                               s_g + L * 128, s_b + L * 128,
                                               siw, sib, nullptr, qkvh,
                                               0, 256, 256, 384, 0, 128);
        attn_tc<1><<<dim3(256, 4, 4), 256, ATC_SMEM>>>(qkvh, 384, 0, qkvh, 384, 128,
                                                       qkvh, 384, 256, projS, voh, 256);
        hgemm<2><<<dim3(1, 384), 256, HSMEM>>>(voh, 0, 256, 256, nullptr, nullptr,
                                               sow, sob, feat, nullptr,
                                               0, 256, 256, 128, 1, 0);

        // ---------------- cross-attention ----------------
        // fr update: q = LN(fr; c_g1), kv = LN(fl; c_g1), flipped table
        hgemm_cross<<<dim3(3, 192), 256, HSMEM>>>(feat, 128, 0,
                                                  c_g1 + L * 128, c_b1 + L * 128,
                                                  c_g1 + L * 128, c_b1 + L * 128,
                                                  ciw, cib, qbh, kvbh);
        attn_tc<-1><<<dim3(128, 4, 4), 256, ATC_SMEM>>>(qbh, 128, 0, kvbh, 256, 0,
                                                        kvbh, 256, 128, projC, voh, 128);
        hgemm<2><<<dim3(1, 192), 256, HSMEM>>>(voh, 0, 128, 128, nullptr, nullptr,
                                               cow, cob, feat, nullptr,
                                               128, 128, 256, 128, 1, 0);

        // fl update: q = LN(fl; c_g1), kv = LN(updated fr; c_g2), normal table
        hgemm_cross<<<dim3(3, 192), 256, HSMEM>>>(feat, 0, 128,
                                                  c_g1 + L * 128, c_b1 + L * 128,
                                                  c_g2 + L * 128, c_b2 + L * 128,
                                                  ciw, cib, qbh, kvbh);
        attn_tc<1><<<dim3(128, 4, 4), 256, ATC_SMEM>>>(qbh, 128, 0, kvbh, 256, 0,
                                                       kvbh, 256, 128, projC, voh, 128);
        hgemm<2><<<dim3(1, 192), 256, HSMEM>>>(voh, 0, 128, 128, nullptr, nullptr,
                                               cow, cob, feat, nullptr,
                                               0, 128, 256, 128, 1, 0);
    }
}

// round 12
// speedup vs baseline: 1.3918x; 1.0498x over previous
#include <cuda_runtime.h>
#include <cuda_bf16.h>
#include <math.h>

// ---------------------------------------------------------------------------
// STTM: 4-layer transformer, w=192, C=128, NHEAD=4, hd=32
// feat (fp32, d_out): (w, n, C). Self: n in [0,256). fl: n<128, fr: n>=128.
// Activations bf16; LN fused into GEMM A-load; weights pre-converted to bf16;
// pos_enc projections batched (bf16, q-scale folded); attention: no-max
// softmax, interior-fast scatter, swizzled Vt transpose.
// ---------------------------------------------------------------------------

#define W_ 192
#define CC 128

// ------------------------- device scratch ---------------------------------
__device__ __nv_bfloat16 g_qkvh[W_*256*384];   // qkv (self) / qb+kvb (cross)
__device__ __nv_bfloat16 g_voh [W_*256*CC];    // attention output
__device__ __nv_bfloat16 g_proj[8*383*256];    // per (layer, self|cross) proj, bf16
__device__ __nv_bfloat16 g_wbh [4*1024*128];   // bf16 weights: siw|sow|ciw|cow

#define WOFF_SIW 0
#define WOFF_SOW (4*384*128)
#define WOFF_CIW (WOFF_SOW + 4*128*128)
#define WOFF_COW (WOFF_CIW + 4*384*128)

// ------------------------- helpers -----------------------------------------
__device__ __forceinline__ unsigned pack_bf2(float x, float y) {
    __nv_bfloat162 h = __float22bfloat162_rn(make_float2(x, y));
    return *(unsigned*)&h;
}

__device__ __forceinline__ void ldm4(unsigned& r0, unsigned& r1, unsigned& r2, unsigned& r3,
                                     unsigned addr) {
    asm volatile("ldmatrix.sync.aligned.m8n8.x4.shared.b16 {%0,%1,%2,%3},[%4];"
                 : "=r"(r0), "=r"(r1), "=r"(r2), "=r"(r3) : "r"(addr));
}

__device__ __forceinline__ void mma_bf16(float* d, const unsigned* a, unsigned b0, unsigned b1) {
    asm volatile(
        "mma.sync.aligned.m16n8k16.row.col.f32.bf16.bf16.f32 "
        "{%0,%1,%2,%3},{%4,%5,%6,%7},{%8,%9},{%0,%1,%2,%3};"
        : "+f"(d[0]), "+f"(d[1]), "+f"(d[2]), "+f"(d[3])
        : "r"(a[0]), "r"(a[1]), "r"(a[2]), "r"(a[3]), "r"(b0), "r"(b1));
}

// ------------------------- fp32 -> bf16 weight conversion ------------------
__global__ void cvt_bf16(const float* __restrict__ src, __nv_bfloat16* __restrict__ dst, int n4)
{
    int i = blockIdx.x * 256 + threadIdx.x;
    if (i >= n4) return;
    float4 v = *(const float4*)(src + i * 4);
    uint2 u; u.x = pack_bf2(v.x, v.y); u.y = pack_bf2(v.z, v.w);
    *(uint2*)(dst + i * 4) = u;
}

// ------------------------- build feat from inputs -------------------------
__global__ void build_feat(const float* __restrict__ L, const float* __restrict__ R,
                           float* __restrict__ feat)
{
    __shared__ float tile[32][33];
    int n = blockIdx.z;
    const float* src = (n < 128) ? L : R;
    int nn = n & 127;
    int h = nn >> 1, b = nn & 1;
    int i = blockIdx.x * 32 + threadIdx.x;
    int c = blockIdx.y * 32 + threadIdx.y;
    tile[threadIdx.y][threadIdx.x] = src[(((size_t)b * 128 + c) * 64 + h) * 192 + i];
    __syncthreads();
    int i2 = blockIdx.x * 32 + threadIdx.y;
    int c2 = blockIdx.y * 32 + threadIdx.x;
    feat[((size_t)i2 * 256 + n) * 128 + c2] = tile[threadIdx.x][threadIdx.y];
}

// ------------------------- batched pos_enc projection ----------------------
__global__ void proj_batch(const float* __restrict__ pos_enc,
                           const float* __restrict__ s_iw, const float* __restrict__ s_ib,
                           const float* __restrict__ c_iw, const float* __restrict__ c_ib,
                           __nv_bfloat16* __restrict__ out)
{
    int z = blockIdx.z, layer = z >> 1;
    const float* B    = ((z & 1) ? c_iw : s_iw) + (size_t)layer * 384 * 128;
    const float* bias = ((z & 1) ? c_ib : s_ib) + layer * 384;
    __nv_bfloat16* C = out + (size_t)z * 383 * 256;
    const int M = 383, N = 256;
    const float qsc = 0.17677669529663687f;

    __shared__ float As[16][68];
    __shared__ float Bs[16][68];
    int tid = threadIdx.x;
    int tx = tid & 15, ty = tid >> 4;
    int rowBase = blockIdx.y * 64;
    int colBase = blockIdx.x * 64;

    float acc[4][4];
    #pragma unroll
    for (int i = 0; i < 4; i++)
        #pragma unroll
        for (int j = 0; j < 4; j++) acc[i][j] = 0.f;

    int lr = tid >> 2;
    int lc = (tid & 3) * 4;
    int ar = rowBase + lr;
    const float* aRowPtr = (ar < M) ? (pos_enc + (size_t)ar * 128) : nullptr;
    int bc = colBase + lr;
    const float* bRowPtr = (bc < N) ? (B + (size_t)bc * 128) : nullptr;

    for (int kt = 0; kt < 8; kt++) {
        int k0 = kt * 16 + lc;
        float4 av = aRowPtr ? *(const float4*)(aRowPtr + k0) : make_float4(0, 0, 0, 0);
        float4 bv = bRowPtr ? *(const float4*)(bRowPtr + k0) : make_float4(0, 0, 0, 0);
        As[lc + 0][lr] = av.x; As[lc + 1][lr] = av.y; As[lc + 2][lr] = av.z; As[lc + 3][lr] = av.w;
        Bs[lc + 0][lr] = bv.x; Bs[lc + 1][lr] = bv.y; Bs[lc + 2][lr] = bv.z; Bs[lc + 3][lr] = bv.w;
        __syncthreads();
        #pragma unroll
        for (int k = 0; k < 16; k++) {
            float a0 = As[k][ty * 4 + 0], a1 = As[k][ty * 4 + 1];
            float a2 = As[k][ty * 4 + 2], a3 = As[k][ty * 4 + 3];
            float b0 = Bs[k][tx * 4 + 0], b1 = Bs[k][tx * 4 + 1];
            float b2 = Bs[k][tx * 4 + 2], b3 = Bs[k][tx * 4 + 3];
            acc[0][0] = fmaf(a0, b0, acc[0][0]); acc[0][1] = fmaf(a0, b1, acc[0][1]);
            acc[0][2] = fmaf(a0, b2, acc[0][2]); acc[0][3] = fmaf(a0, b3, acc[0][3]);
            acc[1][0] = fmaf(a1, b0, acc[1][0]); acc[1][1] = fmaf(a1, b1, acc[1][1]);
            acc[1][2] = fmaf(a1, b2, acc[1][2]); acc[1][3] = fmaf(a1, b3, acc[1][3]);
            acc[2][0] = fmaf(a2, b0, acc[2][0]); acc[2][1] = fmaf(a2, b1, acc[2][1]);
            acc[2][2] = fmaf(a2, b2, acc[2][2]); acc[2][3] = fmaf(a2, b3, acc[2][3]);
            acc[3][0] = fmaf(a3, b0, acc[3][0]); acc[3][1] = fmaf(a3, b1, acc[3][1]);
            acc[3][2] = fmaf(a3, b2, acc[3][2]); acc[3][3] = fmaf(a3, b3, acc[3][3]);
        }
        __syncthreads();
    }

    #pragma unroll
    for (int mi = 0; mi < 4; mi++) {
        int r = rowBase + ty * 4 + mi;
        if (r >= M) continue;
        __nv_bfloat16* cRow = C + (size_t)r * 256;
        #pragma unroll
        for (int ni = 0; ni < 4; ni++) {
            int col = colBase + tx * 4 + ni;
            float v = acc[mi][ni] + bias[col];
            if (col < 128) v *= qsc;
            cRow[col] = __float2bfloat16(v);
        }
    }
}

// ------------------------- bf16 tensor-core GEMM core ----------------------
#define HSMEM (2 * 128 * 128 * 2)

// AMODE: 1 = A fp32 + fused LayerNorm, 2 = A bf16. B is bf16 (pre-converted).
template<int AMODE>
__device__ __forceinline__ void hgemm_body(
    const void* __restrict__ Av, int aN0, int aNW, int aNF,
    const float* __restrict__ lnG, const float* __restrict__ lnB,
    const __nv_bfloat16* __restrict__ B, const float* __restrict__ bias,
    float* __restrict__ C, __nv_bfloat16* __restrict__ Cbf,
    int cN0, int cNW, int cNF, int cPitch,
    int addRes, int scaleLim, int rowBase, int colBase,
    __nv_bfloat16* As, __nv_bfloat16* Bs)
{
    int tid = threadIdx.x;
    int lr = tid >> 1, lkh = tid & 1;
    {
        int ar = rowBase + lr;
        int arow = (ar / aNW) * aNF + aN0 + (ar % aNW);
        const __nv_bfloat16* bp = B + (size_t)(colBase + lr) * 128 + lkh * 64;
        int sw = lr & 7;

        float mean = 0.f, inv = 1.f;
        if (AMODE == 1) {
            const float* ap = (const float*)Av + (size_t)arow * 128 + lkh * 64;
            float s = 0.f, sq = 0.f;
            #pragma unroll
            for (int j = 0; j < 16; j++) {
                float4 v = *(const float4*)(ap + j * 4);
                s += v.x + v.y + v.z + v.w;
                sq += v.x*v.x + v.y*v.y + v.z*v.z + v.w*v.w;
            }
            s  += __shfl_xor_sync(0xffffffffu, s,  1);
            sq += __shfl_xor_sync(0xffffffffu, sq, 1);
            mean = s * (1.f / 128.f);
            float var = sq * (1.f / 128.f) - mean * mean;
            inv = rsqrtf(var + 1e-5f);
        }

        #pragma unroll
        for (int j = 0; j < 8; j++) {
            int c = lkh * 8 + j;
            int cp = c ^ sw;
            uint4 u;
            if (AMODE == 2) {
                const __nv_bfloat16* ap = (const __nv_bfloat16*)Av + (size_t)arow * 128 + lkh * 64;
                u = *(const uint4*)(ap + j * 8);
            } else {
                const float* ap = (const float*)Av + (size_t)arow * 128 + lkh * 64;
                float4 v0 = *(const float4*)(ap + j * 8);
                float4 v1 = *(const float4*)(ap + j * 8 + 4);
                int ch = lkh * 64 + j * 8;
                float4 g0 = *(const float4*)(lnG + ch), g1 = *(const float4*)(lnG + ch + 4);
                float4 b0 = *(const float4*)(lnB + ch), b1 = *(const float4*)(lnB + ch + 4);
                v0.x = (v0.x - mean) * inv * g0.x + b0.x;
                v0.y = (v0.y - mean) * inv * g0.y + b0.y;
                v0.z = (v0.z - mean) * inv * g0.z + b0.z;
                v0.w = (v0.w - mean) * inv * g0.w + b0.w;
                v1.x = (v1.x - mean) * inv * g1.x + b1.x;
                v1.y = (v1.y - mean) * inv * g1.y + b1.y;
                v1.z = (v1.z - mean) * inv * g1.z + b1.z;
                v1.w = (v1.w - mean) * inv * g1.w + b1.w;
                u.x = pack_bf2(v0.x, v0.y); u.y = pack_bf2(v0.z, v0.w);
                u.z = pack_bf2(v1.x, v1.y); u.w = pack_bf2(v1.z, v1.w);
            }
            *(uint4*)&As[lr * 128 + cp * 8] = u;
            *(uint4*)&Bs[lr * 128 + cp * 8] = *(const uint4*)(bp + j * 8);
        }
    }
    __syncthreads();

    int wid = tid >> 5, lane = tid & 31;
    int wm = (wid & 3) * 32;
    int wn = (wid >> 2) * 64;
    int g = lane >> 2, tg = lane & 3;

    float acc[2][8][4];
    #pragma unroll
    for (int mt = 0; mt < 2; mt++)
        #pragma unroll
        for (int nt = 0; nt < 8; nt++)
            #pragma unroll
            for (int q = 0; q < 4; q++) acc[mt][nt][q] = 0.f;

    unsigned asBase = (unsigned)__cvta_generic_to_shared(As);
    unsigned bsBase = (unsigned)__cvta_generic_to_shared(Bs);

    #pragma unroll
    for (int ks = 0; ks < 8; ks++) {
        int c0 = ks * 2;
        unsigned afr[2][4];
        #pragma unroll
        for (int mt = 0; mt < 2; mt++) {
            int row = wm + mt * 16 + (lane & 15);
            int ch = c0 + (lane >> 4);
            unsigned addr = asBase + (unsigned)((row * 128 + ((ch ^ (row & 7)) << 3)) * 2);
            ldm4(afr[mt][0], afr[mt][1], afr[mt][2], afr[mt][3], addr);
        }
        unsigned bfr[8][2];
        #pragma unroll
        for (int p = 0; p < 4; p++) {
            int row = wn + p * 16 + (lane & 7) + ((lane >> 4) << 3);
            int ch = c0 + ((lane >> 3) & 1);
            unsigned addr = bsBase + (unsigned)((row * 128 + ((ch ^ (row & 7)) << 3)) * 2);
            unsigned r0, r1, r2, r3;
            ldm4(r0, r1, r2, r3, addr);
            bfr[p * 2][0] = r0;     bfr[p * 2][1] = r1;
            bfr[p * 2 + 1][0] = r2; bfr[p * 2 + 1][1] = r3;
        }
        #pragma unroll
        for (int mt = 0; mt < 2; mt++)
            #pragma unroll
            for (int nt = 0; nt < 8; nt++)
                mma_bf16(acc[mt][nt], afr[mt], bfr[nt][0], bfr[nt][1]);
    }

    const float qsc = 0.17677669529663687f;
    #pragma unroll
    for (int mt = 0; mt < 2; mt++) {
        int r0g = rowBase + wm + mt * 16 + g;
        #pragma unroll
        for (int half = 0; half < 2; half++) {
            int r = r0g + half * 8;
            int crow = (r / cNW) * cNF + cN0 + (r % cNW);
            #pragma unroll
            for (int nt = 0; nt < 8; nt++) {
                int col = colBase + wn + nt * 8 + 2 * tg;
                float2 b2 = *(const float2*)(bias + col);
                float vx = acc[mt][nt][half * 2 + 0] + b2.x;
                float vy = acc[mt][nt][half * 2 + 1] + b2.y;
                if (Cbf) {
                    if (col < scaleLim) { vx *= qsc; vy *= qsc; }
                    *(unsigned*)(Cbf + (size_t)crow * cPitch + col) = pack_bf2(vx, vy);
                } else {
                    float* cp = C + (size_t)crow * cPitch + col;
                    if (addRes) {
                        float2 old = *(const float2*)cp;
                        vx += old.x; vy += old.y;
                    }
                    float2 o2; o2.x = vx; o2.y = vy;
                    *(float2*)cp = o2;
                }
            }
        }
    }
}

template<int AMODE>
__global__ void __launch_bounds__(256) hgemm(
    const void* __restrict__ Av, int aN0, int aNW, int aNF,
    const float* __restrict__ lnG, const float* __restrict__ lnB,
    const __nv_bfloat16* __restrict__ B, const float* __restrict__ bias,
    float* __restrict__ C, __nv_bfloat16* __restrict__ Cbf,
    int cN0, int cNW, int cNF, int cPitch,
    int addRes, int scaleLim)
{
    extern __shared__ __nv_bfloat16 hsm[];
    hgemm_body<AMODE>(Av, aN0, aNW, aNF, lnG, lnB, B, bias, C, Cbf,
                      cN0, cNW, cNF, cPitch, addRes, scaleLim,
                      blockIdx.y * 128, blockIdx.x * 128, hsm, hsm + 128*128);
}

// Merged cross projections.
__global__ void __launch_bounds__(256) hgemm_cross(
    const float* __restrict__ feat, int qN0, int kN0,
    const float* __restrict__ lnGq, const float* __restrict__ lnBq,
    const float* __restrict__ lnGk, const float* __restrict__ lnBk,
    const __nv_bfloat16* __restrict__ ciw, const float* __restrict__ cib,
    __nv_bfloat16* __restrict__ outQ, __nv_bfloat16* __restrict__ outKV)
{
    extern __shared__ __nv_bfloat16 hsm[];
    int x = blockIdx.x;
    if (x == 0) {
        hgemm_body<1>(feat, qN0, 128, 256, lnGq, lnBq, ciw, cib,
                      nullptr, outQ, 0, 128, 128, 128, 0, 128,
                      blockIdx.y * 128, 0, hsm, hsm + 128*128);
    } else {
        hgemm_body<1>(feat, kN0, 128, 256, lnGk, lnBk, ciw + 128 * 128, cib + 128,
                      nullptr, outKV, 0, 128, 128, 256, 0, 0,
                      blockIdx.y * 128, (x - 1) * 128, hsm, hsm + 128*128);
    }
}

// ------------------------- bf16 mma attention (48-row blocks) ---------------
#define ATC_SMEM 95616

template<int DSIGN>
__global__ void __launch_bounds__(256, 2) attn_tc(
    const __nv_bfloat16* __restrict__ qPtr, int qPitch, int qOff,
    const __nv_bfloat16* __restrict__ kPtr, int kPitch, int kOff,
    const __nv_bfloat16* __restrict__ vPtr, int vPitch, int vOff,
    const __nv_bfloat16* __restrict__ proj, __nv_bfloat16* __restrict__ vo, int nB)
{
    extern __shared__ char smraw[];
    __nv_bfloat16* Qs  = (__nv_bfloat16*)(smraw);
    __nv_bfloat16* Ks  = (__nv_bfloat16*)(smraw + 3840);
    __nv_bfloat16* PKs = (__nv_bfloat16*)(smraw + 19200);
    __nv_bfloat16* PQs = (__nv_bfloat16*)(smraw + 38400);
    __nv_bfloat16* Vt  = PQs;                       // overlay (after Z2 phase)
    float* Opart = (float*)(smraw + 3840);          // overlay Ks (after QK phase)
    float* Ssm  = (float*)(smraw + 57600);
    float* hsum = (float*)(smraw + 95232);          // [2][48]

    int n = blockIdx.x, e = blockIdx.y;
    int i0 = blockIdx.z * 48;
    int tid = threadIdx.x;
    const int dlo = (DSIGN > 0) ? (144 - i0) : i0;

    // ---- loads: Q, K, PK, PQ — pure bf16 uint4 copies ----
    for (int idx = tid; idx < 48 * 4; idx += 256) {
        int r = idx >> 2, h = (idx & 3) * 8;
        uint4 u = *(const uint4*)(qPtr + (size_t)((i0 + r) * nB + n) * qPitch + qOff + e * 32 + h);
        *(uint4*)&Qs[r * 40 + h] = u;
    }
    for (int idx = tid; idx < 192 * 4; idx += 256) {
        int r = idx >> 2, h = (idx & 3) * 8;
        uint4 u = *(const uint4*)(kPtr + (size_t)(r * nB + n) * kPitch + kOff + e * 32 + h);
        *(uint4*)&Ks[r * 40 + h] = u;
    }
    for (int idx = tid; idx < 240 * 4; idx += 256) {
        int t = idx >> 2, h = (idx & 3) * 8;
        int d = dlo + t;
        uint4 zk = make_uint4(0, 0, 0, 0), zq = make_uint4(0, 0, 0, 0);
        if (d < 383) {
            zk = *(const uint4*)(proj + (size_t)d * 256 + 128 + e * 32 + h);
            zq = *(const uint4*)(proj + (size_t)d * 256 + e * 32 + h);
        }
        *(uint4*)&PKs[t * 40 + h] = zk;
        *(uint4*)&PQs[t * 40 + h] = zq;
    }
    __syncthreads();

    int wid = tid >> 5, lane = tid & 31;
    int g = lane >> 2, tg = lane & 3;
    unsigned qBase  = (unsigned)__cvta_generic_to_shared(Qs);
    unsigned kBase  = (unsigned)__cvta_generic_to_shared(Ks);
    unsigned pkBase = (unsigned)__cvta_generic_to_shared(PKs);
    unsigned pqBase = (unsigned)__cvta_generic_to_shared(PQs);
    unsigned vtBase = (unsigned)__cvta_generic_to_shared(Vt);
    unsigned pBase  = (unsigned)__cvta_generic_to_shared(Ssm);

    // ---- Z1 = Q @ PK^T, skew-scattered (init): 3 m-tiles x 13 n16-tiles ----
    #pragma unroll 1
    for (int u = wid; u < 39; u += 8) {
        int mt = u / 13, nt = u % 13;
        int t0m = (DSIGN > 0) ? (32 - 16 * mt) : (16 * mt);
        int tb = t0m + nt * 16;
        unsigned a[2][4], b[2][4];
        #pragma unroll
        for (int ks = 0; ks < 2; ks++) {
            unsigned addrA = qBase + (unsigned)((mt * 16 + (lane & 15)) * 80 + (ks * 2 + (lane >> 4)) * 16);
            ldm4(a[ks][0], a[ks][1], a[ks][2], a[ks][3], addrA);
            int row = tb + (lane & 7) + ((lane >> 4) << 3);
            unsigned addrB = pkBase + (unsigned)(row * 80 + (ks * 2 + ((lane >> 3) & 1)) * 16);
            ldm4(b[ks][0], b[ks][1], b[ks][2], b[ks][3], addrB);
        }
        float acc[2][4];
        #pragma unroll
        for (int h = 0; h < 2; h++) { acc[h][0] = acc[h][1] = acc[h][2] = acc[h][3] = 0.f; }
        mma_bf16(acc[0], a[0], b[0][0], b[0][1]); mma_bf16(acc[0], a[1], b[1][0], b[1][1]);
        mma_bf16(acc[1], a[0], b[0][2], b[0][3]); mma_bf16(acc[1], a[1], b[1][2], b[1][3]);

        if (nt >= 1 && nt <= 11) {
            #pragma unroll
            for (int h = 0; h < 2; h++) {
                int t = tb + h * 8 + 2 * tg;
                #pragma unroll
                for (int rr = 0; rr < 2; rr++) {
                    int il = mt * 16 + g + 8 * rr;
                    float* row = &Ssm[il * 196];
                    if (DSIGN > 0) {
                        int j0 = t + il - 47;
                        row[j0]     = acc[h][rr * 2 + 0];
                        row[j0 + 1] = acc[h][rr * 2 + 1];
                    } else {
                        int j0 = 191 + il - t;
                        row[j0]     = acc[h][rr * 2 + 0];
                        row[j0 - 1] = acc[h][rr * 2 + 1];
                    }
                }
            }
        } else {
            #pragma unroll
            for (int h = 0; h < 2; h++) {
                int t = tb + h * 8 + 2 * tg;
                #pragma unroll
                for (int rr = 0; rr < 2; rr++) {
                    int il = mt * 16 + g + 8 * rr;
                    int j0 = (DSIGN > 0) ? (t + il - 47) : (191 + il - t);
                    int j1 = (DSIGN > 0) ? (j0 + 1) : (j0 - 1);
                    if ((unsigned)j0 < 192u) Ssm[il * 196 + j0] = acc[h][rr * 2 + 0];
                    if ((unsigned)j1 < 192u) Ssm[il * 196 + j1] = acc[h][rr * 2 + 1];
                }
            }
        }
    }
    __syncthreads();

    // ---- Z2 = K @ PQ^T, skew scatter-ADD: 12 j-tiles x 4 n16-tiles ----
    #pragma unroll 1
    for (int u = wid; u < 48; u += 8) {
        int jt = u >> 2, nt = u & 3;
        int t0m = (DSIGN > 0) ? (16 * jt) : (176 - 16 * jt);
        int tb = t0m + nt * 16;
        unsigned a[2][4], b[2][4];
        #pragma unroll
        for (int ks = 0; ks < 2; ks++) {
            unsigned addrA = kBase + (unsigned)((jt * 16 + (lane & 15)) * 80 + (ks * 2 + (lane >> 4)) * 16);
            ldm4(a[ks][0], a[ks][1], a[ks][2], a[ks][3], addrA);
            int row = tb + (lane & 7) + ((lane >> 4) << 3);
            unsigned addrB = pqBase + (unsigned)(row * 80 + (ks * 2 + ((lane >> 3) & 1)) * 16);
            ldm4(b[ks][0], b[ks][1], b[ks][2], b[ks][3], addrB);
        }
        float acc[2][4];
        #pragma unroll
        for (int h = 0; h < 2; h++) { acc[h][0] = acc[h][1] = acc[h][2] = acc[h][3] = 0.f; }
        mma_bf16(acc[0], a[0], b[0][0], b[0][1]); mma_bf16(acc[0], a[1], b[1][0], b[1][1]);
        mma_bf16(acc[1], a[0], b[0][2], b[0][3]); mma_bf16(acc[1], a[1], b[1][2], b[1][3]);

        if (nt == 1 || nt == 2) {
            #pragma unroll
            for (int h = 0; h < 2; h++) {
                int t = tb + h * 8 + 2 * tg;
                #pragma unroll
                for (int rr = 0; rr < 2; rr++) {
                    int j = jt * 16 + g + 8 * rr;
                    int il0 = (DSIGN > 0) ? (47 + j - t) : (t + j - 191);
                    int il1 = (DSIGN > 0) ? (il0 - 1) : (il0 + 1);
                    Ssm[il0 * 196 + j] += acc[h][rr * 2 + 0];
                    Ssm[il1 * 196 + j] += acc[h][rr * 2 + 1];
                }
            }
        } else {
            #pragma unroll
            for (int h = 0; h < 2; h++) {
                int t = tb + h * 8 + 2 * tg;
                #pragma unroll
                for (int rr = 0; rr < 2; rr++) {
                    int j = jt * 16 + g + 8 * rr;
                    int il0 = (DSIGN > 0) ? (47 + j - t) : (t + j - 191);
                    int il1 = (DSIGN > 0) ? (il0 - 1) : (il0 + 1);
                    if ((unsigned)il0 < 48u) Ssm[il0 * 196 + j] += acc[h][rr * 2 + 0];
                    if ((unsigned)il1 < 48u) Ssm[il1 * 196 + j] += acc[h][rr * 2 + 1];
                }
            }
        }
    }
    __syncthreads();

    // ---- warps 0-5: QK^T + gather + exp + partial sums. warps 6-7: Vt ----
    float acc[12][4];
    int mt = wid >> 1, chalf = wid & 1;
    int ilA = mt * 16 + g, ilB = ilA + 8;
    if (wid < 6) {
        #pragma unroll
        for (int nt = 0; nt < 12; nt++)
            #pragma unroll
            for (int q = 0; q < 4; q++) acc[nt][q] = 0.f;

        unsigned a[2][4];
        #pragma unroll
        for (int ks = 0; ks < 2; ks++) {
            unsigned addrA = qBase + (unsigned)((mt * 16 + (lane & 15)) * 80 + (ks * 2 + (lane >> 4)) * 16);
            ldm4(a[ks][0], a[ks][1], a[ks][2], a[ks][3], addrA);
        }
        #pragma unroll
        for (int nt16 = 0; nt16 < 6; nt16++) {
            unsigned b[2][4];
            #pragma unroll
            for (int ks = 0; ks < 2; ks++) {
                int row = chalf * 96 + nt16 * 16 + (lane & 7) + ((lane >> 4) << 3);
                unsigned addrB = kBase + (unsigned)(row * 80 + (ks * 2 + ((lane >> 3) & 1)) * 16);
                ldm4(b[ks][0], b[ks][1], b[ks][2], b[ks][3], addrB);
            }
            mma_bf16(acc[nt16 * 2],     a[0], b[0][0], b[0][1]);
            mma_bf16(acc[nt16 * 2],     a[1], b[1][0], b[1][1]);
            mma_bf16(acc[nt16 * 2 + 1], a[0], b[0][2], b[0][3]);
            mma_bf16(acc[nt16 * 2 + 1], a[1], b[1][2], b[1][3]);
        }

        float sA = 0.f, sB = 0.f;
        #pragma unroll
        for (int nt = 0; nt < 12; nt++) {
            int j = chalf * 96 + nt * 8 + 2 * tg;
            float2 zA = *(const float2*)&Ssm[ilA * 196 + j];
            float2 zB = *(const float2*)&Ssm[ilB * 196 + j];
            acc[nt][0] = __expf(fminf(acc[nt][0] + zA.x, 70.f)); sA += acc[nt][0];
            acc[nt][1] = __expf(fminf(acc[nt][1] + zA.y, 70.f)); sA += acc[nt][1];
            acc[nt][2] = __expf(fminf(acc[nt][2] + zB.x, 70.f)); sB += acc[nt][2];
            acc[nt][3] = __expf(fminf(acc[nt][3] + zB.y, 70.f)); sB += acc[nt][3];
        }
        sA += __shfl_xor_sync(0xffffffffu, sA, 1);
        sA += __shfl_xor_sync(0xffffffffu, sA, 2);
        sB += __shfl_xor_sync(0xffffffffu, sB, 1);
        sB += __shfl_xor_sync(0xffffffffu, sB, 2);
        if (tg == 0) {
            hsum[chalf * 48 + ilA] = sA;
            hsum[chalf * 48 + ilB] = sB;
        }
    } else {
        // transpose-load V into dead PQs region; XOR-swizzled j-chunks
        for (int idx = tid - 192; idx < 192 * 4; idx += 64) {
            int j = idx >> 2, c8 = (idx & 3) * 8;
            uint4 u = *(const uint4*)(vPtr + (size_t)(j * nB + n) * vPitch + vOff + e * 32 + c8);
            __nv_bfloat16 tmp[8];
            *(uint4*)tmp = u;
            int chunk = j >> 3, jo = j & 7;
            #pragma unroll
            for (int k = 0; k < 8; k++) {
                int row = c8 + k;
                int cs = chunk ^ ((row >> 3) & 3);
                Vt[row * 200 + cs * 8 + jo] = tmp[k];
            }
        }
    }
    __syncthreads();

    // ---- normalize, write P (packed bf16 over Ssm) ----
    if (wid < 6) {
        float invA = 1.f / (hsum[ilA] + hsum[48 + ilA]);
        float invB = 1.f / (hsum[ilB] + hsum[48 + ilB]);
        unsigned* Pw = (unsigned*)Ssm;
        #pragma unroll
        for (int nt = 0; nt < 12; nt++) {
            int cw = chalf * 48 + nt * 4 + tg;
            Pw[ilA * 196 + cw] = pack_bf2(acc[nt][0] * invA, acc[nt][1] * invA);
            Pw[ilB * 196 + cw] = pack_bf2(acc[nt][2] * invB, acc[nt][3] * invB);
        }
    }
    __syncthreads();

    // ---- O = P @ V : 6 warps (3 m-tiles x 2 k-halves); combine via Opart ----
    float oacc[4][4];
    if (wid < 6) {
        #pragma unroll
        for (int t = 0; t < 4; t++)
            #pragma unroll
            for (int q = 0; q < 4; q++) oacc[t][q] = 0.f;

        #pragma unroll 1
        for (int s = 0; s < 6; s++) {
            int ks = chalf * 6 + s;
            unsigned a[4];
            unsigned addrA = pBase + (unsigned)((mt * 16 + (lane & 15)) * 784 + (ks * 2 + (lane >> 4)) * 16);
            ldm4(a[0], a[1], a[2], a[3], addrA);
            #pragma unroll
            for (int nb = 0; nb < 2; nb++) {
                int row = nb * 16 + (lane & 7) + ((lane >> 4) << 3);
                int chunk = ks * 2 + ((lane >> 3) & 1);
                int cs = chunk ^ ((row >> 3) & 3);
                unsigned addrB = vtBase + (unsigned)(row * 400 + cs * 16);
                unsigned b0, b1, b2, b3;
                ldm4(b0, b1, b2, b3, addrB);
                mma_bf16(oacc[nb * 2],     a, b0, b1);
                mma_bf16(oacc[nb * 2 + 1], a, b2, b3);
            }
        }
        if (chalf == 1) {
            #pragma unroll
            for (int t = 0; t < 4; t++) {
                int c = t * 8 + 2 * tg;
                Opart[ilA * 32 + c]     = oacc[t][0];
                Opart[ilA * 32 + c + 1] = oacc[t][1];
                Opart[ilB * 32 + c]     = oacc[t][2];
                Opart[ilB * 32 + c + 1] = oacc[t][3];
            }
        }
    }
    __syncthreads();

    if (wid < 6 && chalf == 0) {
        int iA = i0 + ilA, iB = i0 + ilB;
        size_t oA = (size_t)(iA * nB + n) * 128 + e * 32;
        size_t oB = (size_t)(iB * nB + n) * 128 + e * 32;
        #pragma unroll
        for (int t = 0; t < 4; t++) {
            int c = t * 8 + 2 * tg;
            *(unsigned*)(vo + oA + c) = pack_bf2(oacc[t][0] + Opart[ilA * 32 + c],
                                                 oacc[t][1] + Opart[ilA * 32 + c + 1]);
            *(unsigned*)(vo + oB + c) = pack_bf2(oacc[t][2] + Opart[ilB * 32 + c],
                                                 oacc[t][3] + Opart[ilB * 32 + c + 1]);
        }
    }
}

// ---------------------------------------------------------------------------
extern "C" void kernel_launch(void* const* d_in, const int* in_sizes, int n_in,
                              void* d_out, int out_size)
{
    (void)in_sizes; (void)n_in; (void)out_size;
    const float* feat_left  = (const float*)d_in[0];
    const float* feat_right = (const float*)d_in[1];
    const float* pos_enc    = (const float*)d_in[2];
    const float* s_iw = (const float*)d_in[3];
    const float* s_ib = (const float*)d_in[4];
    const float* s_ow = (const float*)d_in[5];
    const float* s_ob = (const float*)d_in[6];
    const float* s_g  = (const float*)d_in[7];
    const float* s_b  = (const float*)d_in[8];
    const float* c_iw = (const float*)d_in[9];
    const float* c_ib = (const float*)d_in[10];
    const float* c_ow = (const float*)d_in[11];
    const float* c_ob = (const float*)d_in[12];
    const float* c_g1 = (const float*)d_in[13];
    const float* c_b1 = (const float*)d_in[14];
    const float* c_g2 = (const float*)d_in[15];
    const float* c_b2 = (const float*)d_in[16];

    float* feat = (float*)d_out;

    __nv_bfloat16 *qkvh, *voh, *projb, *wbh;
    cudaGetSymbolAddress((void**)&qkvh, g_qkvh);
    cudaGetSymbolAddress((void**)&voh, g_voh);
    cudaGetSymbolAddress((void**)&projb, g_proj);
    cudaGetSymbolAddress((void**)&wbh, g_wbh);
    __nv_bfloat16* qbh  = qkvh;
    __nv_bfloat16* kvbh = qkvh + 192 * 128 * 128;

    cudaFuncSetAttribute(attn_tc<1>,  cudaFuncAttributeMaxDynamicSharedMemorySize, ATC_SMEM);
    cudaFuncSetAttribute(attn_tc<-1>, cudaFuncAttributeMaxDynamicSharedMemorySize, ATC_SMEM);
    cudaFuncSetAttribute(hgemm<1>, cudaFuncAttributeMaxDynamicSharedMemorySize, HSMEM);
    cudaFuncSetAttribute(hgemm<2>, cudaFuncAttributeMaxDynamicSharedMemorySize, HSMEM);
    cudaFuncSetAttribute(hgemm_cross, cudaFuncAttributeMaxDynamicSharedMemorySize, HSMEM);

    build_feat<<<dim3(6, 4, 256), dim3(32, 32)>>>(feat_left, feat_right, feat);
    proj_batch<<<dim3(4, 6, 8), 256>>>(pos_enc, s_iw, s_ib, c_iw, c_ib, projb);
    cvt_bf16<<<192, 256>>>(s_iw, wbh + WOFF_SIW, 49152);
    cvt_bf16<<<64, 256>>>(s_ow, wbh + WOFF_SOW, 16384);
    cvt_bf16<<<192, 256>>>(c_iw, wbh + WOFF_CIW, 49152);
    cvt_bf16<<<64, 256>>>(c_ow, wbh + WOFF_COW, 16384);

    for (int L = 0; L < 4; L++) {
        const __nv_bfloat16* siwH = wbh + WOFF_SIW + (size_t)L * 384 * 128;
        const __nv_bfloat16* sowH = wbh + WOFF_SOW + (size_t)L * 128 * 128;
        const __nv_bfloat16* ciwH = wbh + WOFF_CIW + (size_t)L * 384 * 128;
        const __nv_bfloat16* cowH = wbh + WOFF_COW + (size_t)L * 128 * 128;
        const float* sib = s_ib + (size_t)L * 384;
        const float* sob = s_ob + (size_t)L * 128;
        const float* cib = c_ib + (size_t)L * 384;
        const float* cob = c_ob + (size_t)L * 128;
        const __nv_bfloat16* projS = projb + (size_t)(L * 2) * 383 * 256;
        const __nv_bfloat16* projC = projb + (size_t)(L * 2 + 1) * 383 * 256;

        // ---------------- self-attention ----------------
        hgemm<1><<<dim3(3, 384), 256, HSMEM>>>(feat, 0, 256, 256,
                                               s_g + L * 128, s_b + L * 128,
                                               siwH, sib, nullptr, qkvh,
                                               0, 256, 256, 384, 0, 128);
        attn_tc<1><<<dim3(256, 4, 4), 256, ATC_SMEM>>>(qkvh, 384, 0, qkvh, 384, 128,
                                                       qkvh, 384, 256, projS, voh, 256);
        hgemm<2><<<dim3(1, 384), 256, HSMEM>>>(voh, 0, 256, 256, nullptr, nullptr,
                                               sowH, sob, feat, nullptr,
                                               0, 256, 256, 128, 1, 0);

        // ---------------- cross-attention ----------------
        hgemm_cross<<<dim3(3, 192), 256, HSMEM>>>(feat, 128, 0,
                                                  c_g1 + L * 128, c_b1 + L * 128,
                                                  c_g1 + L * 128, c_b1 + L * 128,
                                                  ciwH, cib, qbh, kvbh);
        attn_tc<-1><<<dim3(128, 4, 4), 256, ATC_SMEM>>>(qbh, 128, 0, kvbh, 256, 0,
                                                        kvbh, 256, 128, projC, voh, 128);
        hgemm<2><<<dim3(1, 192), 256, HSMEM>>>(voh, 0, 128, 128, nullptr, nullptr,
                                               cowH, cob, feat, nullptr,
                                               128, 128, 256, 128, 1, 0);

        hgemm_cross<<<dim3(3, 192), 256, HSMEM>>>(feat, 0, 128,
                                                  c_g1 + L * 128, c_b1 + L * 128,
                                                  c_g2 + L * 128, c_b2 + L * 128,
                                                  ciwH, cib, qbh, kvbh);
        attn_tc<1><<<dim3(128, 4, 4), 256, ATC_SMEM>>>(qbh, 128, 0, kvbh, 256, 0,
                                                       kvbh, 256, 128, projC, voh, 128);
        hgemm<2><<<dim3(1, 192), 256, HSMEM>>>(voh, 0, 128, 128, nullptr, nullptr,
                                               cowH, cob, feat, nullptr,
                                               0, 128, 256, 128, 1, 0);
    }
}

// round 13
// speedup vs baseline: 1.3990x; 1.0052x over previous
#include <cuda_runtime.h>
#include <cuda_bf16.h>
#include <math.h>

// ---------------------------------------------------------------------------
// STTM: 4-layer transformer, w=192, C=128, NHEAD=4, hd=32
// feat (fp32, d_out): (w, n, C). Self: n in [0,256). fl: n<128, fr: n>=128.
// Activations bf16; LN fused into GEMM A-load; weights pre-converted to bf16;
// pos_enc projections batched (bf16, q-scale folded); attention: no-max
// softmax, interior-fast scatter, swizzled Vt, 2x-unrolled phase loops,
// pair-scoped barrier between P-write and PV.
// ---------------------------------------------------------------------------

#define W_ 192
#define CC 128

// ------------------------- device scratch ---------------------------------
__device__ __nv_bfloat16 g_qkvh[W_*256*384];
__device__ __nv_bfloat16 g_voh [W_*256*CC];
__device__ __nv_bfloat16 g_proj[8*383*256];
__device__ __nv_bfloat16 g_wbh [4*1024*128];

#define WOFF_SIW 0
#define WOFF_SOW (4*384*128)
#define WOFF_CIW (WOFF_SOW + 4*128*128)
#define WOFF_COW (WOFF_CIW + 4*384*128)

// ------------------------- helpers -----------------------------------------
__device__ __forceinline__ unsigned pack_bf2(float x, float y) {
    __nv_bfloat162 h = __float22bfloat162_rn(make_float2(x, y));
    return *(unsigned*)&h;
}

__device__ __forceinline__ void ldm4(unsigned& r0, unsigned& r1, unsigned& r2, unsigned& r3,
                                     unsigned addr) {
    asm volatile("ldmatrix.sync.aligned.m8n8.x4.shared.b16 {%0,%1,%2,%3},[%4];"
                 : "=r"(r0), "=r"(r1), "=r"(r2), "=r"(r3) : "r"(addr));
}

__device__ __forceinline__ void mma_bf16(float* d, const unsigned* a, unsigned b0, unsigned b1) {
    asm volatile(
        "mma.sync.aligned.m16n8k16.row.col.f32.bf16.bf16.f32 "
        "{%0,%1,%2,%3},{%4,%5,%6,%7},{%8,%9},{%0,%1,%2,%3};"
        : "+f"(d[0]), "+f"(d[1]), "+f"(d[2]), "+f"(d[3])
        : "r"(a[0]), "r"(a[1]), "r"(a[2]), "r"(a[3]), "r"(b0), "r"(b1));
}

// ------------------------- fp32 -> bf16 weight conversion ------------------
__global__ void cvt_bf16(const float* __restrict__ src, __nv_bfloat16* __restrict__ dst, int n4)
{
    int i = blockIdx.x * 256 + threadIdx.x;
    if (i >= n4) return;
    float4 v = *(const float4*)(src + i * 4);
    uint2 u; u.x = pack_bf2(v.x, v.y); u.y = pack_bf2(v.z, v.w);
    *(uint2*)(dst + i * 4) = u;
}

// ------------------------- build feat from inputs -------------------------
__global__ void build_feat(const float* __restrict__ L, const float* __restrict__ R,
                           float* __restrict__ feat)
{
    __shared__ float tile[32][33];
    int n = blockIdx.z;
    const float* src = (n < 128) ? L : R;
    int nn = n & 127;
    int h = nn >> 1, b = nn & 1;
    int i = blockIdx.x * 32 + threadIdx.x;
    int c = blockIdx.y * 32 + threadIdx.y;
    tile[threadIdx.y][threadIdx.x] = src[(((size_t)b * 128 + c) * 64 + h) * 192 + i];
    __syncthreads();
    int i2 = blockIdx.x * 32 + threadIdx.y;
    int c2 = blockIdx.y * 32 + threadIdx.x;
    feat[((size_t)i2 * 256 + n) * 128 + c2] = tile[threadIdx.x][threadIdx.y];
}

// ------------------------- batched pos_enc projection ----------------------
__global__ void proj_batch(const float* __restrict__ pos_enc,
                           const float* __restrict__ s_iw, const float* __restrict__ s_ib,
                           const float* __restrict__ c_iw, const float* __restrict__ c_ib,
                           __nv_bfloat16* __restrict__ out)
{
    int z = blockIdx.z, layer = z >> 1;
    const float* B    = ((z & 1) ? c_iw : s_iw) + (size_t)layer * 384 * 128;
    const float* bias = ((z & 1) ? c_ib : s_ib) + layer * 384;
    __nv_bfloat16* C = out + (size_t)z * 383 * 256;
    const int M = 383, N = 256;
    const float qsc = 0.17677669529663687f;

    __shared__ float As[16][68];
    __shared__ float Bs[16][68];
    int tid = threadIdx.x;
    int tx = tid & 15, ty = tid >> 4;
    int rowBase = blockIdx.y * 64;
    int colBase = blockIdx.x * 64;

    float acc[4][4];
    #pragma unroll
    for (int i = 0; i < 4; i++)
        #pragma unroll
        for (int j = 0; j < 4; j++) acc[i][j] = 0.f;

    int lr = tid >> 2;
    int lc = (tid & 3) * 4;
    int ar = rowBase + lr;
    const float* aRowPtr = (ar < M) ? (pos_enc + (size_t)ar * 128) : nullptr;
    int bc = colBase + lr;
    const float* bRowPtr = (bc < N) ? (B + (size_t)bc * 128) : nullptr;

    for (int kt = 0; kt < 8; kt++) {
        int k0 = kt * 16 + lc;
        float4 av = aRowPtr ? *(const float4*)(aRowPtr + k0) : make_float4(0, 0, 0, 0);
        float4 bv = bRowPtr ? *(const float4*)(bRowPtr + k0) : make_float4(0, 0, 0, 0);
        As[lc + 0][lr] = av.x; As[lc + 1][lr] = av.y; As[lc + 2][lr] = av.z; As[lc + 3][lr] = av.w;
        Bs[lc + 0][lr] = bv.x; Bs[lc + 1][lr] = bv.y; Bs[lc + 2][lr] = bv.z; Bs[lc + 3][lr] = bv.w;
        __syncthreads();
        #pragma unroll
        for (int k = 0; k < 16; k++) {
            float a0 = As[k][ty * 4 + 0], a1 = As[k][ty * 4 + 1];
            float a2 = As[k][ty * 4 + 2], a3 = As[k][ty * 4 + 3];
            float b0 = Bs[k][tx * 4 + 0], b1 = Bs[k][tx * 4 + 1];
            float b2 = Bs[k][tx * 4 + 2], b3 = Bs[k][tx * 4 + 3];
            acc[0][0] = fmaf(a0, b0, acc[0][0]); acc[0][1] = fmaf(a0, b1, acc[0][1]);
            acc[0][2] = fmaf(a0, b2, acc[0][2]); acc[0][3] = fmaf(a0, b3, acc[0][3]);
            acc[1][0] = fmaf(a1, b0, acc[1][0]); acc[1][1] = fmaf(a1, b1, acc[1][1]);
            acc[1][2] = fmaf(a1, b2, acc[1][2]); acc[1][3] = fmaf(a1, b3, acc[1][3]);
            acc[2][0] = fmaf(a2, b0, acc[2][0]); acc[2][1] = fmaf(a2, b1, acc[2][1]);
            acc[2][2] = fmaf(a2, b2, acc[2][2]); acc[2][3] = fmaf(a2, b3, acc[2][3]);
            acc[3][0] = fmaf(a3, b0, acc[3][0]); acc[3][1] = fmaf(a3, b1, acc[3][1]);
            acc[3][2] = fmaf(a3, b2, acc[3][2]); acc[3][3] = fmaf(a3, b3, acc[3][3]);
        }
        __syncthreads();
    }

    #pragma unroll
    for (int mi = 0; mi < 4; mi++) {
        int r = rowBase + ty * 4 + mi;
        if (r >= M) continue;
        __nv_bfloat16* cRow = C + (size_t)r * 256;
        #pragma unroll
        for (int ni = 0; ni < 4; ni++) {
            int col = colBase + tx * 4 + ni;
            float v = acc[mi][ni] + bias[col];
            if (col < 128) v *= qsc;
            cRow[col] = __float2bfloat16(v);
        }
    }
}

// ------------------------- bf16 tensor-core GEMM core ----------------------
#define HSMEM (2 * 128 * 128 * 2)

template<int AMODE>
__device__ __forceinline__ void hgemm_body(
    const void* __restrict__ Av, int aN0, int aNW, int aNF,
    const float* __restrict__ lnG, const float* __restrict__ lnB,
    const __nv_bfloat16* __restrict__ B, const float* __restrict__ bias,
    float* __restrict__ C, __nv_bfloat16* __restrict__ Cbf,
    int cN0, int cNW, int cNF, int cPitch,
    int addRes, int scaleLim, int rowBase, int colBase,
    __nv_bfloat16* As, __nv_bfloat16* Bs)
{
    int tid = threadIdx.x;
    int lr = tid >> 1, lkh = tid & 1;
    {
        int ar = rowBase + lr;
        int arow = (ar / aNW) * aNF + aN0 + (ar % aNW);
        const __nv_bfloat16* bp = B + (size_t)(colBase + lr) * 128 + lkh * 64;
        int sw = lr & 7;

        float mean = 0.f, inv = 1.f;
        if (AMODE == 1) {
            const float* ap = (const float*)Av + (size_t)arow * 128 + lkh * 64;
            float s = 0.f, sq = 0.f;
            #pragma unroll
            for (int j = 0; j < 16; j++) {
                float4 v = *(const float4*)(ap + j * 4);
                s += v.x + v.y + v.z + v.w;
                sq += v.x*v.x + v.y*v.y + v.z*v.z + v.w*v.w;
            }
            s  += __shfl_xor_sync(0xffffffffu, s,  1);
            sq += __shfl_xor_sync(0xffffffffu, sq, 1);
            mean = s * (1.f / 128.f);
            float var = sq * (1.f / 128.f) - mean * mean;
            inv = rsqrtf(var + 1e-5f);
        }

        #pragma unroll
        for (int j = 0; j < 8; j++) {
            int c = lkh * 8 + j;
            int cp = c ^ sw;
            uint4 u;
            if (AMODE == 2) {
                const __nv_bfloat16* ap = (const __nv_bfloat16*)Av + (size_t)arow * 128 + lkh * 64;
                u = *(const uint4*)(ap + j * 8);
            } else {
                const float* ap = (const float*)Av + (size_t)arow * 128 + lkh * 64;
                float4 v0 = *(const float4*)(ap + j * 8);
                float4 v1 = *(const float4*)(ap + j * 8 + 4);
                int ch = lkh * 64 + j * 8;
                float4 g0 = *(const float4*)(lnG + ch), g1 = *(const float4*)(lnG + ch + 4);
                float4 b0 = *(const float4*)(lnB + ch), b1 = *(const float4*)(lnB + ch + 4);
                v0.x = (v0.x - mean) * inv * g0.x + b0.x;
                v0.y = (v0.y - mean) * inv * g0.y + b0.y;
                v0.z = (v0.z - mean) * inv * g0.z + b0.z;
                v0.w = (v0.w - mean) * inv * g0.w + b0.w;
                v1.x = (v1.x - mean) * inv * g1.x + b1.x;
                v1.y = (v1.y - mean) * inv * g1.y + b1.y;
                v1.z = (v1.z - mean) * inv * g1.z + b1.z;
                v1.w = (v1.w - mean) * inv * g1.w + b1.w;
                u.x = pack_bf2(v0.x, v0.y); u.y = pack_bf2(v0.z, v0.w);
                u.z = pack_bf2(v1.x, v1.y); u.w = pack_bf2(v1.z, v1.w);
            }
            *(uint4*)&As[lr * 128 + cp * 8] = u;
            *(uint4*)&Bs[lr * 128 + cp * 8] = *(const uint4*)(bp + j * 8);
        }
    }
    __syncthreads();

    int wid = tid >> 5, lane = tid & 31;
    int wm = (wid & 3) * 32;
    int wn = (wid >> 2) * 64;
    int g = lane >> 2, tg = lane & 3;

    float acc[2][8][4];
    #pragma unroll
    for (int mt = 0; mt < 2; mt++)
        #pragma unroll
        for (int nt = 0; nt < 8; nt++)
            #pragma unroll
            for (int q = 0; q < 4; q++) acc[mt][nt][q] = 0.f;

    unsigned asBase = (unsigned)__cvta_generic_to_shared(As);
    unsigned bsBase = (unsigned)__cvta_generic_to_shared(Bs);

    #pragma unroll
    for (int ks = 0; ks < 8; ks++) {
        int c0 = ks * 2;
        unsigned afr[2][4];
        #pragma unroll
        for (int mt = 0; mt < 2; mt++) {
            int row = wm + mt * 16 + (lane & 15);
            int ch = c0 + (lane >> 4);
            unsigned addr = asBase + (unsigned)((row * 128 + ((ch ^ (row & 7)) << 3)) * 2);
            ldm4(afr[mt][0], afr[mt][1], afr[mt][2], afr[mt][3], addr);
        }
        unsigned bfr[8][2];
        #pragma unroll
        for (int p = 0; p < 4; p++) {
            int row = wn + p * 16 + (lane & 7) + ((lane >> 4) << 3);
            int ch = c0 + ((lane >> 3) & 1);
            unsigned addr = bsBase + (unsigned)((row * 128 + ((ch ^ (row & 7)) << 3)) * 2);
            unsigned r0, r1, r2, r3;
            ldm4(r0, r1, r2, r3, addr);
            bfr[p * 2][0] = r0;     bfr[p * 2][1] = r1;
            bfr[p * 2 + 1][0] = r2; bfr[p * 2 + 1][1] = r3;
        }
        #pragma unroll
        for (int mt = 0; mt < 2; mt++)
            #pragma unroll
            for (int nt = 0; nt < 8; nt++)
                mma_bf16(acc[mt][nt], afr[mt], bfr[nt][0], bfr[nt][1]);
    }

    const float qsc = 0.17677669529663687f;
    #pragma unroll
    for (int mt = 0; mt < 2; mt++) {
        int r0g = rowBase + wm + mt * 16 + g;
        #pragma unroll
        for (int half = 0; half < 2; half++) {
            int r = r0g + half * 8;
            int crow = (r / cNW) * cNF + cN0 + (r % cNW);
            #pragma unroll
            for (int nt = 0; nt < 8; nt++) {
                int col = colBase + wn + nt * 8 + 2 * tg;
                float2 b2 = *(const float2*)(bias + col);
                float vx = acc[mt][nt][half * 2 + 0] + b2.x;
                float vy = acc[mt][nt][half * 2 + 1] + b2.y;
                if (Cbf) {
                    if (col < scaleLim) { vx *= qsc; vy *= qsc; }
                    *(unsigned*)(Cbf + (size_t)crow * cPitch + col) = pack_bf2(vx, vy);
                } else {
                    float* cp = C + (size_t)crow * cPitch + col;
                    if (addRes) {
                        float2 old = *(const float2*)cp;
                        vx += old.x; vy += old.y;
                    }
                    float2 o2; o2.x = vx; o2.y = vy;
                    *(float2*)cp = o2;
                }
            }
        }
    }
}

template<int AMODE>
__global__ void __launch_bounds__(256) hgemm(
    const void* __restrict__ Av, int aN0, int aNW, int aNF,
    const float* __restrict__ lnG, const float* __restrict__ lnB,
    const __nv_bfloat16* __restrict__ B, const float* __restrict__ bias,
    float* __restrict__ C, __nv_bfloat16* __restrict__ Cbf,
    int cN0, int cNW, int cNF, int cPitch,
    int addRes, int scaleLim)
{
    extern __shared__ __nv_bfloat16 hsm[];
    hgemm_body<AMODE>(Av, aN0, aNW, aNF, lnG, lnB, B, bias, C, Cbf,
                      cN0, cNW, cNF, cPitch, addRes, scaleLim,
                      blockIdx.y * 128, blockIdx.x * 128, hsm, hsm + 128*128);
}

__global__ void __launch_bounds__(256) hgemm_cross(
    const float* __restrict__ feat, int qN0, int kN0,
    const float* __restrict__ lnGq, const float* __restrict__ lnBq,
    const float* __restrict__ lnGk, const float* __restrict__ lnBk,
    const __nv_bfloat16* __restrict__ ciw, const float* __restrict__ cib,
    __nv_bfloat16* __restrict__ outQ, __nv_bfloat16* __restrict__ outKV)
{
    extern __shared__ __nv_bfloat16 hsm[];
    int x = blockIdx.x;
    if (x == 0) {
        hgemm_body<1>(feat, qN0, 128, 256, lnGq, lnBq, ciw, cib,
                      nullptr, outQ, 0, 128, 128, 128, 0, 128,
                      blockIdx.y * 128, 0, hsm, hsm + 128*128);
    } else {
        hgemm_body<1>(feat, kN0, 128, 256, lnGk, lnBk, ciw + 128 * 128, cib + 128,
                      nullptr, outKV, 0, 128, 128, 256, 0, 0,
                      blockIdx.y * 128, (x - 1) * 128, hsm, hsm + 128*128);
    }
}

// ------------------------- bf16 mma attention (48-row blocks) ---------------
#define ATC_SMEM 95616

template<int DSIGN>
__global__ void __launch_bounds__(256, 2) attn_tc(
    const __nv_bfloat16* __restrict__ qPtr, int qPitch, int qOff,
    const __nv_bfloat16* __restrict__ kPtr, int kPitch, int kOff,
    const __nv_bfloat16* __restrict__ vPtr, int vPitch, int vOff,
    const __nv_bfloat16* __restrict__ proj, __nv_bfloat16* __restrict__ vo, int nB)
{
    extern __shared__ char smraw[];
    __nv_bfloat16* Qs  = (__nv_bfloat16*)(smraw);
    __nv_bfloat16* Ks  = (__nv_bfloat16*)(smraw + 3840);
    __nv_bfloat16* PKs = (__nv_bfloat16*)(smraw + 19200);
    __nv_bfloat16* PQs = (__nv_bfloat16*)(smraw + 38400);
    __nv_bfloat16* Vt  = PQs;                       // overlay (after Z2 phase)
    float* Opart = (float*)(smraw + 3840);          // overlay Ks (after QK phase)
    float* Ssm  = (float*)(smraw + 57600);
    float* hsum = (float*)(smraw + 95232);          // [2][48]

    int n = blockIdx.x, e = blockIdx.y;
    int i0 = blockIdx.z * 48;
    int tid = threadIdx.x;
    const int dlo = (DSIGN > 0) ? (144 - i0) : i0;

    // ---- loads: Q, K, PK, PQ — pure bf16 uint4 copies ----
    for (int idx = tid; idx < 48 * 4; idx += 256) {
        int r = idx >> 2, h = (idx & 3) * 8;
        uint4 u = *(const uint4*)(qPtr + (size_t)((i0 + r) * nB + n) * qPitch + qOff + e * 32 + h);
        *(uint4*)&Qs[r * 40 + h] = u;
    }
    for (int idx = tid; idx < 192 * 4; idx += 256) {
        int r = idx >> 2, h = (idx & 3) * 8;
        uint4 u = *(const uint4*)(kPtr + (size_t)(r * nB + n) * kPitch + kOff + e * 32 + h);
        *(uint4*)&Ks[r * 40 + h] = u;
    }
    for (int idx = tid; idx < 240 * 4; idx += 256) {
        int t = idx >> 2, h = (idx & 3) * 8;
        int d = dlo + t;
        uint4 zk = make_uint4(0, 0, 0, 0), zq = make_uint4(0, 0, 0, 0);
        if (d < 383) {
            zk = *(const uint4*)(proj + (size_t)d * 256 + 128 + e * 32 + h);
            zq = *(const uint4*)(proj + (size_t)d * 256 + e * 32 + h);
        }
        *(uint4*)&PKs[t * 40 + h] = zk;
        *(uint4*)&PQs[t * 40 + h] = zq;
    }
    __syncthreads();

    int wid = tid >> 5, lane = tid & 31;
    int g = lane >> 2, tg = lane & 3;
    unsigned qBase  = (unsigned)__cvta_generic_to_shared(Qs);
    unsigned kBase  = (unsigned)__cvta_generic_to_shared(Ks);
    unsigned pkBase = (unsigned)__cvta_generic_to_shared(PKs);
    unsigned pqBase = (unsigned)__cvta_generic_to_shared(PQs);
    unsigned vtBase = (unsigned)__cvta_generic_to_shared(Vt);
    unsigned pBase  = (unsigned)__cvta_generic_to_shared(Ssm);

    // ---- Z1 = Q @ PK^T, skew-scattered (init): 3 m-tiles x 13 n16-tiles ----
    #pragma unroll 2
    for (int u = wid; u < 39; u += 8) {
        int mt = u / 13, nt = u % 13;
        int t0m = (DSIGN > 0) ? (32 - 16 * mt) : (16 * mt);
        int tb = t0m + nt * 16;
        unsigned a[2][4], b[2][4];
        #pragma unroll
        for (int ks = 0; ks < 2; ks++) {
            unsigned addrA = qBase + (unsigned)((mt * 16 + (lane & 15)) * 80 + (ks * 2 + (lane >> 4)) * 16);
            ldm4(a[ks][0], a[ks][1], a[ks][2], a[ks][3], addrA);
            int row = tb + (lane & 7) + ((lane >> 4) << 3);
            unsigned addrB = pkBase + (unsigned)(row * 80 + (ks * 2 + ((lane >> 3) & 1)) * 16);
            ldm4(b[ks][0], b[ks][1], b[ks][2], b[ks][3], addrB);
        }
        float acc[2][4];
        #pragma unroll
        for (int h = 0; h < 2; h++) { acc[h][0] = acc[h][1] = acc[h][2] = acc[h][3] = 0.f; }
        mma_bf16(acc[0], a[0], b[0][0], b[0][1]); mma_bf16(acc[0], a[1], b[1][0], b[1][1]);
        mma_bf16(acc[1], a[0], b[0][2], b[0][3]); mma_bf16(acc[1], a[1], b[1][2], b[1][3]);

        if (nt >= 1 && nt <= 11) {
            #pragma unroll
            for (int h = 0; h < 2; h++) {
                int t = tb + h * 8 + 2 * tg;
                #pragma unroll
                for (int rr = 0; rr < 2; rr++) {
                    int il = mt * 16 + g + 8 * rr;
                    float* row = &Ssm[il * 196];
                    if (DSIGN > 0) {
                        int j0 = t + il - 47;
                        row[j0]     = acc[h][rr * 2 + 0];
                        row[j0 + 1] = acc[h][rr * 2 + 1];
                    } else {
                        int j0 = 191 + il - t;
                        row[j0]     = acc[h][rr * 2 + 0];
                        row[j0 - 1] = acc[h][rr * 2 + 1];
                    }
                }
            }
        } else {
            #pragma unroll
            for (int h = 0; h < 2; h++) {
                int t = tb + h * 8 + 2 * tg;
                #pragma unroll
                for (int rr = 0; rr < 2; rr++) {
                    int il = mt * 16 + g + 8 * rr;
                    int j0 = (DSIGN > 0) ? (t + il - 47) : (191 + il - t);
                    int j1 = (DSIGN > 0) ? (j0 + 1) : (j0 - 1);
                    if ((unsigned)j0 < 192u) Ssm[il * 196 + j0] = acc[h][rr * 2 + 0];
                    if ((unsigned)j1 < 192u) Ssm[il * 196 + j1] = acc[h][rr * 2 + 1];
                }
            }
        }
    }
    __syncthreads();

    // ---- Z2 = K @ PQ^T, skew scatter-ADD: 12 j-tiles x 4 n16-tiles ----
    #pragma unroll 2
    for (int u = wid; u < 48; u += 8) {
        int jt = u >> 2, nt = u & 3;
        int t0m = (DSIGN > 0) ? (16 * jt) : (176 - 16 * jt);
        int tb = t0m + nt * 16;
        unsigned a[2][4], b[2][4];
        #pragma unroll
        for (int ks = 0; ks < 2; ks++) {
            unsigned addrA = kBase + (unsigned)((jt * 16 + (lane & 15)) * 80 + (ks * 2 + (lane >> 4)) * 16);
            ldm4(a[ks][0], a[ks][1], a[ks][2], a[ks][3], addrA);
            int row = tb + (lane & 7) + ((lane >> 4) << 3);
            unsigned addrB = pqBase + (unsigned)(row * 80 + (ks * 2 + ((lane >> 3) & 1)) * 16);
            ldm4(b[ks][0], b[ks][1], b[ks][2], b[ks][3], addrB);
        }
        float acc[2][4];
        #pragma unroll
        for (int h = 0; h < 2; h++) { acc[h][0] = acc[h][1] = acc[h][2] = acc[h][3] = 0.f; }
        mma_bf16(acc[0], a[0], b[0][0], b[0][1]); mma_bf16(acc[0], a[1], b[1][0], b[1][1]);
        mma_bf16(acc[1], a[0], b[0][2], b[0][3]); mma_bf16(acc[1], a[1], b[1][2], b[1][3]);

        if (nt == 1 || nt == 2) {
            #pragma unroll
            for (int h = 0; h < 2; h++) {
                int t = tb + h * 8 + 2 * tg;
                #pragma unroll
                for (int rr = 0; rr < 2; rr++) {
                    int j = jt * 16 + g + 8 * rr;
                    int il0 = (DSIGN > 0) ? (47 + j - t) : (t + j - 191);
                    int il1 = (DSIGN > 0) ? (il0 - 1) : (il0 + 1);
                    Ssm[il0 * 196 + j] += acc[h][rr * 2 + 0];
                    Ssm[il1 * 196 + j] += acc[h][rr * 2 + 1];
                }
            }
        } else {
            #pragma unroll
            for (int h = 0; h < 2; h++) {
                int t = tb + h * 8 + 2 * tg;
                #pragma unroll
                for (int rr = 0; rr < 2; rr++) {
                    int j = jt * 16 + g + 8 * rr;
                    int il0 = (DSIGN > 0) ? (47 + j - t) : (t + j - 191);
                    int il1 = (DSIGN > 0) ? (il0 - 1) : (il0 + 1);
                    if ((unsigned)il0 < 48u) Ssm[il0 * 196 + j] += acc[h][rr * 2 + 0];
                    if ((unsigned)il1 < 48u) Ssm[il1 * 196 + j] += acc[h][rr * 2 + 1];
                }
            }
        }
    }
    __syncthreads();

    // ---- warps 0-5: QK^T + gather + exp + partial sums. warps 6-7: Vt ----
    float acc[12][4];
    int mt = wid >> 1, chalf = wid & 1;
    int ilA = mt * 16 + g, ilB = ilA + 8;
    if (wid < 6) {
        #pragma unroll
        for (int nt = 0; nt < 12; nt++)
            #pragma unroll
            for (int q = 0; q < 4; q++) acc[nt][q] = 0.f;

        unsigned a[2][4];
        #pragma unroll
        for (int ks = 0; ks < 2; ks++) {
            unsigned addrA = qBase + (unsigned)((mt * 16 + (lane & 15)) * 80 + (ks * 2 + (lane >> 4)) * 16);
            ldm4(a[ks][0], a[ks][1], a[ks][2], a[ks][3], addrA);
        }
        #pragma unroll
        for (int nt16 = 0; nt16 < 6; nt16++) {
            unsigned b[2][4];
            #pragma unroll
            for (int ks = 0; ks < 2; ks++) {
                int row = chalf * 96 + nt16 * 16 + (lane & 7) + ((lane >> 4) << 3);
                unsigned addrB = kBase + (unsigned)(row * 80 + (ks * 2 + ((lane >> 3) & 1)) * 16);
                ldm4(b[ks][0], b[ks][1], b[ks][2], b[ks][3], addrB);
            }
            mma_bf16(acc[nt16 * 2],     a[0], b[0][0], b[0][1]);
            mma_bf16(acc[nt16 * 2],     a[1], b[1][0], b[1][1]);
            mma_bf16(acc[nt16 * 2 + 1], a[0], b[0][2], b[0][3]);
            mma_bf16(acc[nt16 * 2 + 1], a[1], b[1][2], b[1][3]);
        }

        float sA = 0.f, sB = 0.f;
        #pragma unroll
        for (int nt = 0; nt < 12; nt++) {
            int j = chalf * 96 + nt * 8 + 2 * tg;
            float2 zA = *(const float2*)&Ssm[ilA * 196 + j];
            float2 zB = *(const float2*)&Ssm[ilB * 196 + j];
            acc[nt][0] = __expf(fminf(acc[nt][0] + zA.x, 70.f)); sA += acc[nt][0];
            acc[nt][1] = __expf(fminf(acc[nt][1] + zA.y, 70.f)); sA += acc[nt][1];
            acc[nt][2] = __expf(fminf(acc[nt][2] + zB.x, 70.f)); sB += acc[nt][2];
            acc[nt][3] = __expf(fminf(acc[nt][3] + zB.y, 70.f)); sB += acc[nt][3];
        }
        sA += __shfl_xor_sync(0xffffffffu, sA, 1);
        sA += __shfl_xor_sync(0xffffffffu, sA, 2);
        sB += __shfl_xor_sync(0xffffffffu, sB, 1);
        sB += __shfl_xor_sync(0xffffffffu, sB, 2);
        if (tg == 0) {
            hsum[chalf * 48 + ilA] = sA;
            hsum[chalf * 48 + ilB] = sB;
        }
    } else {
        // transpose-load V into dead PQs region; XOR-swizzled j-chunks
        for (int idx = tid - 192; idx < 192 * 4; idx += 64) {
            int j = idx >> 2, c8 = (idx & 3) * 8;
            uint4 u = *(const uint4*)(vPtr + (size_t)(j * nB + n) * vPitch + vOff + e * 32 + c8);
            __nv_bfloat16 tmp[8];
            *(uint4*)tmp = u;
            int chunk = j >> 3, jo = j & 7;
            #pragma unroll
            for (int k = 0; k < 8; k++) {
                int row = c8 + k;
                int cs = chunk ^ ((row >> 3) & 3);
                Vt[row * 200 + cs * 8 + jo] = tmp[k];
            }
        }
    }
    __syncthreads();

    // ---- normalize, write P (packed bf16 over Ssm); pair-scoped barrier ----
    if (wid < 6) {
        float invA = 1.f / (hsum[ilA] + hsum[48 + ilA]);
        float invB = 1.f / (hsum[ilB] + hsum[48 + ilB]);
        unsigned* Pw = (unsigned*)Ssm;
        #pragma unroll
        for (int nt = 0; nt < 12; nt++) {
            int cw = chalf * 48 + nt * 4 + tg;
            Pw[ilA * 196 + cw] = pack_bf2(acc[nt][0] * invA, acc[nt][1] * invA);
            Pw[ilB * 196 + cw] = pack_bf2(acc[nt][2] * invB, acc[nt][3] * invB);
        }
        // sync only the 2 warps (2mt, 2mt+1) that produced/consume P tile mt
        asm volatile("bar.sync %0, 64;" :: "r"(mt + 1) : "memory");
    }

    // ---- O = P @ V : 6 warps (3 m-tiles x 2 k-halves); combine via Opart ----
    float oacc[4][4];
    if (wid < 6) {
        #pragma unroll
        for (int t = 0; t < 4; t++)
            #pragma unroll
            for (int q = 0; q < 4; q++) oacc[t][q] = 0.f;

        #pragma unroll 2
        for (int s = 0; s < 6; s++) {
            int ks = chalf * 6 + s;
            unsigned a[4];
            unsigned addrA = pBase + (unsigned)((mt * 16 + (lane & 15)) * 784 + (ks * 2 + (lane >> 4)) * 16);
            ldm4(a[0], a[1], a[2], a[3], addrA);
            #pragma unroll
            for (int nb = 0; nb < 2; nb++) {
                int row = nb * 16 + (lane & 7) + ((lane >> 4) << 3);
                int chunk = ks * 2 + ((lane >> 3) & 1);
                int cs = chunk ^ ((row >> 3) & 3);
                unsigned addrB = vtBase + (unsigned)(row * 400 + cs * 16);
                unsigned b0, b1, b2, b3;
                ldm4(b0, b1, b2, b3, addrB);
                mma_bf16(oacc[nb * 2],     a, b0, b1);
                mma_bf16(oacc[nb * 2 + 1], a, b2, b3);
            }
        }
        if (chalf == 1) {
            #pragma unroll
            for (int t = 0; t < 4; t++) {
                int c = t * 8 + 2 * tg;
                Opart[ilA * 32 + c]     = oacc[t][0];
                Opart[ilA * 32 + c + 1] = oacc[t][1];
                Opart[ilB * 32 + c]     = oacc[t][2];
                Opart[ilB * 32 + c + 1] = oacc[t][3];
            }
        }
    }
    __syncthreads();

    if (wid < 6 && chalf == 0) {
        int iA = i0 + ilA, iB = i0 + ilB;
        size_t oA = (size_t)(iA * nB + n) * 128 + e * 32;
        size_t oB = (size_t)(iB * nB + n) * 128 + e * 32;
        #pragma unroll
        for (int t = 0; t < 4; t++) {
            int c = t * 8 + 2 * tg;
            *(unsigned*)(vo + oA + c) = pack_bf2(oacc[t][0] + Opart[ilA * 32 + c],
                                                 oacc[t][1] + Opart[ilA * 32 + c + 1]);
            *(unsigned*)(vo + oB + c) = pack_bf2(oacc[t][2] + Opart[ilB * 32 + c],
                                                 oacc[t][3] + Opart[ilB * 32 + c + 1]);
        }
    }
}

// ---------------------------------------------------------------------------
extern "C" void kernel_launch(void* const* d_in, const int* in_sizes, int n_in,
                              void* d_out, int out_size)
{
    (void)in_sizes; (void)n_in; (void)out_size;
    const float* feat_left  = (const float*)d_in[0];
    const float* feat_right = (const float*)d_in[1];
    const float* pos_enc    = (const float*)d_in[2];
    const float* s_iw = (const float*)d_in[3];
    const float* s_ib = (const float*)d_in[4];
    const float* s_ow = (const float*)d_in[5];
    const float* s_ob = (const float*)d_in[6];
    const float* s_g  = (const float*)d_in[7];
    const float* s_b  = (const float*)d_in[8];
    const float* c_iw = (const float*)d_in[9];
    const float* c_ib = (const float*)d_in[10];
    const float* c_ow = (const float*)d_in[11];
    const float* c_ob = (const float*)d_in[12];
    const float* c_g1 = (const float*)d_in[13];
    const float* c_b1 = (const float*)d_in[14];
    const float* c_g2 = (const float*)d_in[15];
    const float* c_b2 = (const float*)d_in[16];

    float* feat = (float*)d_out;

    __nv_bfloat16 *qkvh, *voh, *projb, *wbh;
    cudaGetSymbolAddress((void**)&qkvh, g_qkvh);
    cudaGetSymbolAddress((void**)&voh, g_voh);
    cudaGetSymbolAddress((void**)&projb, g_proj);
    cudaGetSymbolAddress((void**)&wbh, g_wbh);
    __nv_bfloat16* qbh  = qkvh;
    __nv_bfloat16* kvbh = qkvh + 192 * 128 * 128;

    cudaFuncSetAttribute(attn_tc<1>,  cudaFuncAttributeMaxDynamicSharedMemorySize, ATC_SMEM);
    cudaFuncSetAttribute(attn_tc<-1>, cudaFuncAttributeMaxDynamicSharedMemorySize, ATC_SMEM);
    cudaFuncSetAttribute(hgemm<1>, cudaFuncAttributeMaxDynamicSharedMemorySize, HSMEM);
    cudaFuncSetAttribute(hgemm<2>, cudaFuncAttributeMaxDynamicSharedMemorySize, HSMEM);
    cudaFuncSetAttribute(hgemm_cross, cudaFuncAttributeMaxDynamicSharedMemorySize, HSMEM);

    build_feat<<<dim3(6, 4, 256), dim3(32, 32)>>>(feat_left, feat_right, feat);
    proj_batch<<<dim3(4, 6, 8), 256>>>(pos_enc, s_iw, s_ib, c_iw, c_ib, projb);
    cvt_bf16<<<192, 256>>>(s_iw, wbh + WOFF_SIW, 49152);
    cvt_bf16<<<64, 256>>>(s_ow, wbh + WOFF_SOW, 16384);
    cvt_bf16<<<192, 256>>>(c_iw, wbh + WOFF_CIW, 49152);
    cvt_bf16<<<64, 256>>>(c_ow, wbh + WOFF_COW, 16384);

    for (int L = 0; L < 4; L++) {
        const __nv_bfloat16* siwH = wbh + WOFF_SIW + (size_t)L * 384 * 128;
        const __nv_bfloat16* sowH = wbh + WOFF_SOW + (size_t)L * 128 * 128;
        const __nv_bfloat16* ciwH = wbh + WOFF_CIW + (size_t)L * 384 * 128;
        const __nv_bfloat16* cowH = wbh + WOFF_COW + (size_t)L * 128 * 128;
        const float* sib = s_ib + (size_t)L * 384;
        const float* sob = s_ob + (size_t)L * 128;
        const float* cib = c_ib + (size_t)L * 384;
        const float* cob = c_ob + (size_t)L * 128;
        const __nv_bfloat16* projS = projb + (size_t)(L * 2) * 383 * 256;
        const __nv_bfloat16* projC = projb + (size_t)(L * 2 + 1) * 383 * 256;

        // ---------------- self-attention ----------------
        hgemm<1><<<dim3(3, 384), 256, HSMEM>>>(feat, 0, 256, 256,
                                               s_g + L * 128, s_b + L * 128,
                                               siwH, sib, nullptr, qkvh,
                                               0, 256, 256, 384, 0, 128);
        attn_tc<1><<<dim3(256, 4, 4), 256, ATC_SMEM>>>(qkvh, 384, 0, qkvh, 384, 128,
                                                       qkvh, 384, 256, projS, voh, 256);
        hgemm<2><<<dim3(1, 384), 256, HSMEM>>>(voh, 0, 256, 256, nullptr, nullptr,
                                               sowH, sob, feat, nullptr,
                                               0, 256, 256, 128, 1, 0);

        // ---------------- cross-attention ----------------
        hgemm_cross<<<dim3(3, 192), 256, HSMEM>>>(feat, 128, 0,
                                                  c_g1 + L * 128, c_b1 + L * 128,
                                                  c_g1 + L * 128, c_b1 + L * 128,
                                                  ciwH, cib, qbh, kvbh);
        attn_tc<-1><<<dim3(128, 4, 4), 256, ATC_SMEM>>>(qbh, 128, 0, kvbh, 256, 0,
                                                        kvbh, 256, 128, projC, voh, 128);
        hgemm<2><<<dim3(1, 192), 256, HSMEM>>>(voh, 0, 128, 128, nullptr, nullptr,
                                               cowH, cob, feat, nullptr,
                                               128, 128, 256, 128, 1, 0);

        hgemm_cross<<<dim3(3, 192), 256, HSMEM>>>(feat, 0, 128,
                                                  c_g1 + L * 128, c_b1 + L * 128,
                                                  c_g2 + L * 128, c_b2 + L * 128,
                                                  ciwH, cib, qbh, kvbh);
        attn_tc<1><<<dim3(128, 4, 4), 256, ATC_SMEM>>>(qbh, 128, 0, kvbh, 256, 0,
                                                       kvbh, 256, 128, projC, voh, 128);
        hgemm<2><<<dim3(1, 192), 256, HSMEM>>>(voh, 0, 128, 128, nullptr, nullptr,
                                               cowH, cob, feat, nullptr,
                                               0, 128, 256, 128, 1, 0);
    }
}